// round 2
// baseline (speedup 1.0000x reference)
#include <cuda_runtime.h>
#include <cuda_bf16.h>
#include <math.h>

// ---------------- problem constants ----------------
#define T_NEW 16
#define HIDDEN 2560
#define INTER 9728
#define NH 32
#define NKV 8
#define HD 128
#define TC 4080
#define TFULL 4096   // TC + T_NEW
#define RMS_EPS 1e-6f

// ---------------- scratch (device globals, no allocs) ----------------
__device__ float g_y[T_NEW * HIDDEN];
__device__ float g_q[T_NEW * NH * HD];
__device__ float g_k[T_NEW * NKV * HD];
__device__ float g_v[T_NEW * NKV * HD];
__device__ float g_fullk[NKV * TFULL * HD];
__device__ float g_fullv[NKV * TFULL * HD];
__device__ float g_scores[NH * T_NEW * TFULL];
__device__ float g_attnout[T_NEW * NH * HD];
__device__ float g_oacc[T_NEW * HIDDEN];
__device__ float g_h[T_NEW * HIDDEN];
__device__ float g_y2[T_NEW * HIDDEN];
__device__ float g_gate[T_NEW * INTER];
__device__ float g_up[T_NEW * INTER];
__device__ float g_mid[T_NEW * INTER];
__device__ float g_dacc[T_NEW * HIDDEN];

// ---------------- zero the atomic-accumulation targets ----------------
__global__ void zero_scratch() {
    int i = blockIdx.x * 256 + threadIdx.x;
    int stride = gridDim.x * 256;
    for (; i < T_NEW * INTER; i += stride) {
        g_gate[i] = 0.f; g_up[i] = 0.f;
        if (i < T_NEW * NH * HD) { g_q[i] = 0.f; g_attnout[i] = 0.f; }
        if (i < T_NEW * NKV * HD) { g_k[i] = 0.f; g_v[i] = 0.f; }
        if (i < T_NEW * HIDDEN)  { g_oacc[i] = 0.f; g_dacc[i] = 0.f; }
    }
}

// ---------------- rmsnorm over last dim D (per token) ----------------
__global__ void rmsnorm16(const float* __restrict__ x, const float* __restrict__ w,
                          float* __restrict__ y, int D) {
    int t = blockIdx.x;
    const float* row = x + (size_t)t * D;
    float s = 0.f;
    for (int i = threadIdx.x; i < D; i += 256) { float v = row[i]; s += v * v; }
    // block reduce
    __shared__ float red[8];
    for (int o = 16; o > 0; o >>= 1) s += __shfl_xor_sync(0xffffffffu, s, o);
    if ((threadIdx.x & 31) == 0) red[threadIdx.x >> 5] = s;
    __syncthreads();
    float tot = 0.f;
#pragma unroll
    for (int i = 0; i < 8; i++) tot += red[i];
    float r = rsqrtf(tot / (float)D + RMS_EPS);
    for (int i = threadIdx.x; i < D; i += 256)
        y[(size_t)t * D + i] = row[i] * r * w[i];
}

// ---------------- generic M=16 GEMM, out[t][n] = sum_k A[t][k] * W[n or k][...] ----
// WT==0: W is [N][K] row-major (classic x @ W^T)
// WT==1: W is [K][ldwn] row-major, tile columns nbase..nbase+127 (for attn@V)
// grid: x = n-tiles of 128, y = batch, z = k-split
template <int WT, int ATOMIC>
__global__ void __launch_bounds__(128)
gemm16(const float* __restrict__ A, int lda, size_t sA,
       const float* __restrict__ W, size_t sW, int wdiv, int ldwn,
       int K, int klen,
       float* __restrict__ O, int ldo, size_t sO,
       float scale, const float* __restrict__ maskAdd, int maskld) {
    __shared__ __align__(16) float ws[32][132];
    __shared__ __align__(16) float as[32][16];

    const int tid = threadIdx.x;
    const int lane = tid & 31;
    const int wid = tid >> 5;
    const int nbase = blockIdx.x * 128;
    const int b = blockIdx.y;

    const float* Ab = A + (size_t)b * sA;
    const float* Wb = W + (size_t)(b / wdiv) * sW;
    float* Ob = O + (size_t)b * sO;

    int kbeg = blockIdx.z * klen;
    int kend = kbeg + klen; if (kend > K) kend = K;

    float acc[4][4];
#pragma unroll
    for (int i = 0; i < 4; i++)
#pragma unroll
        for (int j = 0; j < 4; j++) acc[i][j] = 0.f;

    for (int k0 = kbeg; k0 < kend; k0 += 32) {
        // load W tile -> ws[k][n] (transposed to [k][n] on the fly for WT==0)
        if (WT == 0) {
#pragma unroll
            for (int i = 0; i < 8; i++) {
                int li = tid + i * 128;
                int r = li >> 3;          // n within tile 0..127
                int c = (li & 7) * 4;     // k within tile
                float4 wv = *(const float4*)(Wb + (size_t)(nbase + r) * K + k0 + c);
                ws[c + 0][r] = wv.x; ws[c + 1][r] = wv.y;
                ws[c + 2][r] = wv.z; ws[c + 3][r] = wv.w;
            }
        } else {
#pragma unroll
            for (int i = 0; i < 8; i++) {
                int li = tid + i * 128;
                int kk = li >> 5;         // k within tile 0..31
                int c = (li & 31) * 4;    // n within tile
                float4 wv = *(const float4*)(Wb + (size_t)(k0 + kk) * ldwn + nbase + c);
                *(float4*)&ws[kk][c] = wv;
            }
        }
        // load A tile -> as[k][t]
        {
            int r = tid >> 3;             // token 0..15
            int c = (tid & 7) * 4;        // k within tile
            float4 av = *(const float4*)(Ab + (size_t)r * lda + k0 + c);
            as[c + 0][r] = av.x; as[c + 1][r] = av.y;
            as[c + 2][r] = av.z; as[c + 3][r] = av.w;
        }
        __syncthreads();
#pragma unroll
        for (int kk = 0; kk < 32; kk++) {
            float4 a = *(const float4*)&as[kk][wid * 4];
            float4 w4 = *(const float4*)&ws[kk][lane * 4];
            acc[0][0] += a.x * w4.x; acc[0][1] += a.x * w4.y; acc[0][2] += a.x * w4.z; acc[0][3] += a.x * w4.w;
            acc[1][0] += a.y * w4.x; acc[1][1] += a.y * w4.y; acc[1][2] += a.y * w4.z; acc[1][3] += a.y * w4.w;
            acc[2][0] += a.z * w4.x; acc[2][1] += a.z * w4.y; acc[2][2] += a.z * w4.z; acc[2][3] += a.z * w4.w;
            acc[3][0] += a.w * w4.x; acc[3][1] += a.w * w4.y; acc[3][2] += a.w * w4.z; acc[3][3] += a.w * w4.w;
        }
        __syncthreads();
    }

#pragma unroll
    for (int i = 0; i < 4; i++) {
        int t = wid * 4 + i;
#pragma unroll
        for (int j = 0; j < 4; j++) {
            int n = nbase + lane * 4 + j;
            float v = acc[i][j] * scale;
            if (maskAdd) v += maskAdd[(size_t)t * maskld + n];
            float* dst = Ob + (size_t)t * ldo + n;
            if (ATOMIC) atomicAdd(dst, v);
            else *dst = v;
        }
    }
}

// ---------------- per-head rmsnorm + RoPE for q/k, and new_v copy ----------------
// grid: (T_NEW, 48): y<32 -> q head, y in [32,40) -> k head, y in [40,48) -> v copy
__global__ void qk_norm_rope(float* __restrict__ q, float* __restrict__ k,
                             const float* __restrict__ v,
                             const float* __restrict__ qw, const float* __restrict__ kw,
                             const float* __restrict__ cosr, const float* __restrict__ sinr,
                             float* __restrict__ outk, float* __restrict__ outv) {
    int t = blockIdx.x;
    int hh = blockIdx.y;
    int d = threadIdx.x; // 128 threads

    if (hh >= 40) { // v copy (uniform per block -> safe early return)
        int h = hh - 40;
        outv[(size_t)(h * T_NEW + t) * HD + d] = v[(size_t)t * (NKV * HD) + h * HD + d];
        return;
    }

    __shared__ float sv[HD];
    __shared__ float red[4];
    float* row; const float* w;
    if (hh < 32) { row = q + (size_t)t * (NH * HD) + hh * HD; w = qw; }
    else         { row = k + (size_t)t * (NKV * HD) + (hh - 32) * HD; w = kw; }

    float val = row[d];
    float s = val * val;
    for (int o = 16; o > 0; o >>= 1) s += __shfl_xor_sync(0xffffffffu, s, o);
    if ((d & 31) == 0) red[d >> 5] = s;
    __syncthreads();
    float tot = red[0] + red[1] + red[2] + red[3];
    float r = rsqrtf(tot / 128.f + RMS_EPS);
    float xn = val * r * w[d];
    sv[d] = xn;
    __syncthreads();
    float rot = (d < 64) ? -sv[d + 64] : sv[d - 64];
    float o = xn * cosr[t * HD + d] + rot * sinr[t * HD + d];
    row[d] = o;
    if (hh >= 32) {
        int h = hh - 32;
        outk[(size_t)(h * T_NEW + t) * HD + d] = o;
    }
}

// ---------------- append the 16 new K/V rows into fullK/fullV ----------------
__global__ void appendkv() {
    int t = blockIdx.x, h = blockIdx.y, d = threadIdx.x;
    g_fullk[((size_t)h * TFULL + TC + t) * HD + d] = g_k[(size_t)t * (NKV * HD) + h * HD + d];
    g_fullv[((size_t)h * TFULL + TC + t) * HD + d] = g_v[(size_t)t * (NKV * HD) + h * HD + d];
}

// ---------------- row softmax over TFULL ----------------
__global__ void softmax_rows(float* __restrict__ s) {
    int row = blockIdx.x;
    float* p = s + (size_t)row * TFULL;
    __shared__ float red[8];
    int tid = threadIdx.x;
    float m = -3.4e38f;
    for (int i = tid; i < TFULL; i += 256) m = fmaxf(m, p[i]);
    for (int o = 16; o > 0; o >>= 1) m = fmaxf(m, __shfl_xor_sync(0xffffffffu, m, o));
    if ((tid & 31) == 0) red[tid >> 5] = m;
    __syncthreads();
    float mm = red[0];
#pragma unroll
    for (int i = 1; i < 8; i++) mm = fmaxf(mm, red[i]);
    __syncthreads();
    float sum = 0.f;
    for (int i = tid; i < TFULL; i += 256) {
        float e = expf(p[i] - mm);
        p[i] = e;
        sum += e;
    }
    for (int o = 16; o > 0; o >>= 1) sum += __shfl_xor_sync(0xffffffffu, sum, o);
    if ((tid & 31) == 0) red[tid >> 5] = sum;
    __syncthreads();
    float tot = 0.f;
#pragma unroll
    for (int i = 0; i < 8; i++) tot += red[i];
    float inv = 1.f / tot;
    for (int i = tid; i < TFULL; i += 256) p[i] *= inv;
}

// ---------------- elementwise helpers ----------------
__global__ void add_k(const float* __restrict__ a, const float* __restrict__ b,
                      float* __restrict__ o, int n) {
    int i = blockIdx.x * 256 + threadIdx.x;
    if (i < n) o[i] = a[i] + b[i];
}
__global__ void silu_mul_k(const float* __restrict__ g, const float* __restrict__ u,
                           float* __restrict__ o, int n) {
    int i = blockIdx.x * 256 + threadIdx.x;
    if (i < n) {
        float x = g[i];
        o[i] = (x / (1.f + expf(-x))) * u[i];
    }
}

// ---------------- host-side symbol pointer helpers ----------------
static float* sym(const void* s) {
    void* p = nullptr;
    cudaGetSymbolAddress(&p, s);
    return (float*)p;
}

extern "C" void kernel_launch(void* const* d_in, const int* in_sizes, int n_in,
                              void* d_out, int out_size) {
    const float* x       = (const float*)d_in[0];
    const float* cos_q   = (const float*)d_in[1];
    const float* sin_q   = (const float*)d_in[2];
    // d_in[3]/d_in[4] (cos_k_new/sin_k_new) are identical to cos_q/sin_q; use q's.
    const float* cache_k = (const float*)d_in[5];
    const float* cache_v = (const float*)d_in[6];
    const float* cmask   = (const float*)d_in[7];
    const float* ln1w    = (const float*)d_in[8];
    const float* ln2w    = (const float*)d_in[9];
    const float* qnw     = (const float*)d_in[10];
    const float* knw     = (const float*)d_in[11];
    const float* qw      = (const float*)d_in[12];
    const float* kw      = (const float*)d_in[13];
    const float* vw      = (const float*)d_in[14];
    const float* ow      = (const float*)d_in[15];
    const float* gw      = (const float*)d_in[16];
    const float* uw      = (const float*)d_in[17];
    const float* dw      = (const float*)d_in[18];
    float* out = (float*)d_out;
    float* out_k = out + T_NEW * HIDDEN;               // 40960
    float* out_v = out_k + NKV * T_NEW * HD;           // +16384

    static float *p_y = nullptr, *p_q, *p_k, *p_v, *p_fullk, *p_fullv, *p_scores,
                 *p_attnout, *p_oacc, *p_h, *p_y2, *p_gate, *p_up, *p_mid, *p_dacc;
    if (!p_y) {
        p_y = sym(g_y); p_q = sym(g_q); p_k = sym(g_k); p_v = sym(g_v);
        p_fullk = sym(g_fullk); p_fullv = sym(g_fullv); p_scores = sym(g_scores);
        p_attnout = sym(g_attnout); p_oacc = sym(g_oacc); p_h = sym(g_h);
        p_y2 = sym(g_y2); p_gate = sym(g_gate); p_up = sym(g_up);
        p_mid = sym(g_mid); p_dacc = sym(g_dacc);
    }

    const float scale = 0.08838834764831845f; // 1/sqrt(128)

    // 0) zero atomic targets
    zero_scratch<<<608, 256>>>();

    // copy caches into fullK/fullV (rows 0..4079 per head), append rows later
    cudaMemcpy2DAsync(p_fullk, (size_t)TFULL * HD * 4,
                      cache_k, (size_t)TC * HD * 4,
                      (size_t)TC * HD * 4, NKV, cudaMemcpyDeviceToDevice, 0);
    cudaMemcpy2DAsync(p_fullv, (size_t)TFULL * HD * 4,
                      cache_v, (size_t)TC * HD * 4,
                      (size_t)TC * HD * 4, NKV, cudaMemcpyDeviceToDevice, 0);

    // 1) y = rmsnorm(x) * ln1
    rmsnorm16<<<T_NEW, 256>>>(x, ln1w, p_y, HIDDEN);

    // 2) q/k/v projections (split-K=4, atomic)
    gemm16<0, 1><<<dim3(NH * HD / 128, 1, 4), 128>>>(p_y, HIDDEN, 0, qw, 0, 1, 0,
        HIDDEN, 640, p_q, NH * HD, 0, 1.f, nullptr, 0);
    gemm16<0, 1><<<dim3(NKV * HD / 128, 1, 4), 128>>>(p_y, HIDDEN, 0, kw, 0, 1, 0,
        HIDDEN, 640, p_k, NKV * HD, 0, 1.f, nullptr, 0);
    gemm16<0, 1><<<dim3(NKV * HD / 128, 1, 4), 128>>>(p_y, HIDDEN, 0, vw, 0, 1, 0,
        HIDDEN, 640, p_v, NKV * HD, 0, 1.f, nullptr, 0);

    // 3) per-head q/k rmsnorm + RoPE (in-place) + write new_k/new_v to d_out
    qk_norm_rope<<<dim3(T_NEW, 48), 128>>>(p_q, p_k, p_v, qnw, knw, cos_q, sin_q,
                                           out_k, out_v);

    // 4) append new rows to fullK/fullV
    appendkv<<<dim3(T_NEW, NKV), 128>>>();

    // 5) scores[h] = (q_h @ fullK_h^T)*scale + mask   (batched over 32 heads)
    gemm16<0, 0><<<dim3(TFULL / 128, NH, 1), 128>>>(
        p_q, NH * HD, HD,                   // A = q, per-head offset 128
        p_fullk, (size_t)TFULL * HD, 4, 0,  // W per-kv-head, wdiv=4
        HD, HD,
        p_scores, TFULL, (size_t)T_NEW * TFULL,
        scale, cmask, TFULL);

    // 6) softmax
    softmax_rows<<<NH * T_NEW, 256>>>(p_scores);

    // 7) attn_out[h] = P_h @ fullV_h   (W in [K][N] layout, split-K=16, atomic)
    gemm16<1, 1><<<dim3(1, NH, 16), 128>>>(
        p_scores, TFULL, (size_t)T_NEW * TFULL,
        p_fullv, (size_t)TFULL * HD, 4, HD,
        TFULL, 256,
        p_attnout, NH * HD, HD,
        1.f, nullptr, 0);

    // 8) o projection (split-K=8, atomic) then residual add
    gemm16<0, 1><<<dim3(HIDDEN / 128, 1, 8), 128>>>(p_attnout, NH * HD, 0, ow, 0, 1, 0,
        NH * HD, 512, p_oacc, HIDDEN, 0, 1.f, nullptr, 0);
    add_k<<<(T_NEW * HIDDEN + 255) / 256, 256>>>(x, p_oacc, p_h, T_NEW * HIDDEN);

    // 9) y2 = rmsnorm(h) * ln2
    rmsnorm16<<<T_NEW, 256>>>(p_h, ln2w, p_y2, HIDDEN);

    // 10) gate / up (split-K=2, atomic)
    gemm16<0, 1><<<dim3(INTER / 128, 1, 2), 128>>>(p_y2, HIDDEN, 0, gw, 0, 1, 0,
        HIDDEN, 1280, p_gate, INTER, 0, 1.f, nullptr, 0);
    gemm16<0, 1><<<dim3(INTER / 128, 1, 2), 128>>>(p_y2, HIDDEN, 0, uw, 0, 1, 0,
        HIDDEN, 1280, p_up, INTER, 0, 1.f, nullptr, 0);

    // 11) mid = silu(gate) * up
    silu_mul_k<<<(T_NEW * INTER + 255) / 256, 256>>>(p_gate, p_up, p_mid, T_NEW * INTER);

    // 12) down projection (split-K=8, atomic), then final = h + down
    gemm16<0, 1><<<dim3(HIDDEN / 128, 1, 8), 128>>>(p_mid, INTER, 0, dw, 0, 1, 0,
        INTER, 1216, p_dacc, HIDDEN, 0, 1.f, nullptr, 0);
    add_k<<<(T_NEW * HIDDEN + 255) / 256, 256>>>(p_h, p_dacc, out, T_NEW * HIDDEN);
}

// round 3
// speedup vs baseline: 1.5884x; 1.5884x over previous
#include <cuda_runtime.h>
#include <cuda_bf16.h>
#include <math.h>

// ---------------- problem constants ----------------
#define T_NEW 16
#define HIDDEN 2560
#define INTER 9728
#define NH 32
#define NKV 8
#define HD 128
#define TC 4080
#define TFULL 4096
#define RMS_EPS 1e-6f
#define KT 16

typedef unsigned long long ull;

// ---------------- scratch (device globals, no allocs) ----------------
__device__ float g_y[T_NEW * HIDDEN];
__device__ float g_q[T_NEW * NH * HD];
__device__ float g_k[T_NEW * NKV * HD];
__device__ float g_v[T_NEW * NKV * HD];
__device__ float g_scores[NH * T_NEW * TFULL];
__device__ float g_attnout[T_NEW * NH * HD];
__device__ float g_oacc[T_NEW * HIDDEN];
__device__ float g_h[T_NEW * HIDDEN];
__device__ float g_y2[T_NEW * HIDDEN];
__device__ float g_gate[T_NEW * INTER];
__device__ float g_up[T_NEW * INTER];
__device__ float g_mid[T_NEW * INTER];
__device__ float g_dacc[T_NEW * HIDDEN];

// ---------------- packed f32x2 helpers ----------------
__device__ __forceinline__ void fma2(ull& d, ull a, ull b) {
    asm("fma.rn.f32x2 %0, %1, %2, %0;" : "+l"(d) : "l"(a), "l"(b));
}
__device__ __forceinline__ float2 up2(ull v) {
    float2 f;
    asm("mov.b64 {%0, %1}, %2;" : "=f"(f.x), "=f"(f.y) : "l"(v));
    return f;
}

// ---------------- zero atomic-accumulation targets ----------------
__global__ void zero_scratch() {
    int i = blockIdx.x * 256 + threadIdx.x;
    int stride = gridDim.x * 256;
    for (; i < T_NEW * INTER; i += stride) {
        g_gate[i] = 0.f; g_up[i] = 0.f;
        if (i < T_NEW * NH * HD) { g_q[i] = 0.f; g_attnout[i] = 0.f; }
        if (i < T_NEW * NKV * HD) { g_k[i] = 0.f; g_v[i] = 0.f; }
        if (i < T_NEW * HIDDEN)  { g_oacc[i] = 0.f; g_dacc[i] = 0.f; }
    }
}

// ---------------- rmsnorm per token ----------------
__global__ void rmsnorm16(const float* __restrict__ x, const float* __restrict__ w,
                          float* __restrict__ y, int D) {
    int t = blockIdx.x;
    const float* row = x + (size_t)t * D;
    float s = 0.f;
    for (int i = threadIdx.x; i < D; i += 256) { float v = row[i]; s += v * v; }
    __shared__ float red[8];
    for (int o = 16; o > 0; o >>= 1) s += __shfl_xor_sync(0xffffffffu, s, o);
    if ((threadIdx.x & 31) == 0) red[threadIdx.x >> 5] = s;
    __syncthreads();
    float tot = 0.f;
#pragma unroll
    for (int i = 0; i < 8; i++) tot += red[i];
    float r = rsqrtf(tot / (float)D + RMS_EPS);
    for (int i = threadIdx.x; i < D; i += 256)
        y[(size_t)t * D + i] = row[i] * r * w[i];
}

// =============================================================
// gemmA: out[t][n] = sum_k A[t][k] * Wrow(n)[k]
// W is [N][K] row-major; rows >= rowSw come from Wn (if Wn != null).
// tile: 16 tokens x 256 n, KT=16 per stage, reg double-buffered.
// 128 threads; thread tile 8t x 4n, f32x2 math.
// =============================================================
__global__ void __launch_bounds__(128)
gemmA(const float* __restrict__ A, int lda, long sA,
      const float* __restrict__ Wc, long sWc, int wdiv, int ldw,
      const float* __restrict__ Wn, long sWn, int rowSw,
      int K, int klen,
      float* __restrict__ O, int ldo, long sO,
      float scale, const float* __restrict__ maskAdd, int maskld, int atomic) {
    __shared__ __align__(16) float ws[2][KT][260];
    __shared__ __align__(16) float2 asp[2][KT][16];

    const int tid = threadIdx.x;
    const int b = blockIdx.y;
    const int nbase = blockIdx.x * 256;
    const int kbeg = blockIdx.z * klen;
    int kend = kbeg + klen; if (kend > K) kend = K;
    if (kbeg >= kend) return;

    const float* Ab = A + (long)b * sA;
    const int r0 = nbase + tid, r1 = r0 + 128;
    const float* wp0 = (Wn && r0 >= rowSw)
        ? Wn + (long)(b / wdiv) * sWn + (long)(r0 - rowSw) * ldw
        : Wc + (long)(b / wdiv) * sWc + (long)r0 * ldw;
    const float* wp1 = (Wn && r1 >= rowSw)
        ? Wn + (long)(b / wdiv) * sWn + (long)(r1 - rowSw) * ldw
        : Wc + (long)(b / wdiv) * sWc + (long)r1 * ldw;

    const int at = tid >> 3;
    const int ac = (tid & 7) * 2;
    const float* ap = Ab + (long)at * lda + ac;

    const int tt = tid >> 6;   // 0..1 -> 8 tokens each
    const int nn = tid & 63;   // n = nbase + nn*4

    ull acc[8][2];
#pragma unroll
    for (int i = 0; i < 8; i++) { acc[i][0] = 0ULL; acc[i][1] = 0ULL; }

    float4 wr0[4], wr1[4];
    float2 ar;

    const int nb = (kend - kbeg) >> 4;

    // prologue
#pragma unroll
    for (int j = 0; j < 4; j++) {
        wr0[j] = *(const float4*)(wp0 + kbeg + j * 4);
        wr1[j] = *(const float4*)(wp1 + kbeg + j * 4);
    }
    ar = *(const float2*)(ap + kbeg);
#pragma unroll
    for (int j = 0; j < 4; j++) {
        ws[0][j * 4 + 0][tid] = wr0[j].x; ws[0][j * 4 + 1][tid] = wr0[j].y;
        ws[0][j * 4 + 2][tid] = wr0[j].z; ws[0][j * 4 + 3][tid] = wr0[j].w;
        ws[0][j * 4 + 0][tid + 128] = wr1[j].x; ws[0][j * 4 + 1][tid + 128] = wr1[j].y;
        ws[0][j * 4 + 2][tid + 128] = wr1[j].z; ws[0][j * 4 + 3][tid + 128] = wr1[j].w;
    }
    asp[0][ac + 0][at] = make_float2(ar.x, ar.x);
    asp[0][ac + 1][at] = make_float2(ar.y, ar.y);
    __syncthreads();

    for (int it = 0; it < nb; ++it) {
        const int cur = it & 1;
        if (it + 1 < nb) {
            int k0 = kbeg + (it + 1) * KT;
#pragma unroll
            for (int j = 0; j < 4; j++) {
                wr0[j] = *(const float4*)(wp0 + k0 + j * 4);
                wr1[j] = *(const float4*)(wp1 + k0 + j * 4);
            }
            ar = *(const float2*)(ap + k0);
        }
#pragma unroll
        for (int k = 0; k < KT; k++) {
            ulonglong2 w2 = *(const ulonglong2*)&ws[cur][k][nn * 4];
            const ulonglong2* av = (const ulonglong2*)&asp[cur][k][tt * 8];
            ulonglong2 a01 = av[0], a23 = av[1], a45 = av[2], a67 = av[3];
            fma2(acc[0][0], a01.x, w2.x); fma2(acc[0][1], a01.x, w2.y);
            fma2(acc[1][0], a01.y, w2.x); fma2(acc[1][1], a01.y, w2.y);
            fma2(acc[2][0], a23.x, w2.x); fma2(acc[2][1], a23.x, w2.y);
            fma2(acc[3][0], a23.y, w2.x); fma2(acc[3][1], a23.y, w2.y);
            fma2(acc[4][0], a45.x, w2.x); fma2(acc[4][1], a45.x, w2.y);
            fma2(acc[5][0], a45.y, w2.x); fma2(acc[5][1], a45.y, w2.y);
            fma2(acc[6][0], a67.x, w2.x); fma2(acc[6][1], a67.x, w2.y);
            fma2(acc[7][0], a67.y, w2.x); fma2(acc[7][1], a67.y, w2.y);
        }
        if (it + 1 < nb) {
            const int nxt = cur ^ 1;
#pragma unroll
            for (int j = 0; j < 4; j++) {
                ws[nxt][j * 4 + 0][tid] = wr0[j].x; ws[nxt][j * 4 + 1][tid] = wr0[j].y;
                ws[nxt][j * 4 + 2][tid] = wr0[j].z; ws[nxt][j * 4 + 3][tid] = wr0[j].w;
                ws[nxt][j * 4 + 0][tid + 128] = wr1[j].x; ws[nxt][j * 4 + 1][tid + 128] = wr1[j].y;
                ws[nxt][j * 4 + 2][tid + 128] = wr1[j].z; ws[nxt][j * 4 + 3][tid + 128] = wr1[j].w;
            }
            asp[nxt][ac + 0][at] = make_float2(ar.x, ar.x);
            asp[nxt][ac + 1][at] = make_float2(ar.y, ar.y);
        }
        __syncthreads();
    }

    float* Ob = O + (long)b * sO;
#pragma unroll
    for (int i = 0; i < 8; i++) {
        int t = tt * 8 + i;
        int n = nbase + nn * 4;
        float2 v0 = up2(acc[i][0]);
        float2 v1 = up2(acc[i][1]);
        float4 v = make_float4(v0.x * scale, v0.y * scale, v1.x * scale, v1.y * scale);
        if (maskAdd) {
            const float* m = maskAdd + (long)t * maskld + n;
            v.x += m[0]; v.y += m[1]; v.z += m[2]; v.w += m[3];
        }
        float* dst = Ob + (long)t * ldo + n;
        if (atomic) {
            atomicAdd(dst + 0, v.x); atomicAdd(dst + 1, v.y);
            atomicAdd(dst + 2, v.z); atomicAdd(dst + 3, v.w);
        } else {
            *(float4*)dst = v;
        }
    }
}

// =============================================================
// gemmB: out[t][n] = sum_k A[t][k] * W[k][n]   (W rows indexed by k, N=128)
// rows k >= rowSw come from Wn. For attn @ V.
// 128 threads; thread tile 8t x 2n, f32x2 math, KT=16 double-buffered.
// =============================================================
__global__ void __launch_bounds__(128)
gemmB(const float* __restrict__ A, int lda, long sA,
      const float* __restrict__ Wc, long sWc, int wdiv, int ldw,
      const float* __restrict__ Wn, long sWn, int rowSw,
      int K, int klen,
      float* __restrict__ O, int ldo, long sO) {
    __shared__ __align__(16) float ws[2][KT][132];
    __shared__ __align__(16) float2 asp[2][KT][16];

    const int tid = threadIdx.x;
    const int b = blockIdx.y;
    const int kbeg = blockIdx.z * klen;
    int kend = kbeg + klen; if (kend > K) kend = K;
    if (kbeg >= kend) return;

    const float* Ab = A + (long)b * sA;
    const long wco = (long)(b / wdiv) * sWc;
    const long wno = (long)(b / wdiv) * sWn;

    const int kk = tid >> 3;          // 0..15 k-row within tile
    const int cc = (tid & 7) * 4;     // col start

    const int at = tid >> 3;
    const int ac = (tid & 7) * 2;
    const float* ap = Ab + (long)at * lda + ac;

    const int tt = tid >> 6;
    const int nn = tid & 63;          // n = nn*2

    ull acc[8];
#pragma unroll
    for (int i = 0; i < 8; i++) acc[i] = 0ULL;

    float4 wr[4];
    float2 ar;
    const int nb = (kend - kbeg) >> 4;

    // prologue
    {
        int r = kbeg + kk;
        const float* wp = (Wn && r >= rowSw) ? Wn + wno + (long)(r - rowSw) * ldw
                                             : Wc + wco + (long)r * ldw;
#pragma unroll
        for (int j = 0; j < 4; j++) wr[j] = *(const float4*)(wp + cc + j * 32);
        ar = *(const float2*)(ap + kbeg);
#pragma unroll
        for (int j = 0; j < 4; j++) *(float4*)&ws[0][kk][cc + j * 32] = wr[j];
        asp[0][ac + 0][at] = make_float2(ar.x, ar.x);
        asp[0][ac + 1][at] = make_float2(ar.y, ar.y);
    }
    __syncthreads();

    for (int it = 0; it < nb; ++it) {
        const int cur = it & 1;
        if (it + 1 < nb) {
            int k0 = kbeg + (it + 1) * KT;
            int r = k0 + kk;
            const float* wp = (Wn && r >= rowSw) ? Wn + wno + (long)(r - rowSw) * ldw
                                                 : Wc + wco + (long)r * ldw;
#pragma unroll
            for (int j = 0; j < 4; j++) wr[j] = *(const float4*)(wp + cc + j * 32);
            ar = *(const float2*)(ap + k0);
        }
#pragma unroll
        for (int k = 0; k < KT; k++) {
            ull wv = *(const ull*)&ws[cur][k][nn * 2];
            const ulonglong2* av = (const ulonglong2*)&asp[cur][k][tt * 8];
            ulonglong2 a01 = av[0], a23 = av[1], a45 = av[2], a67 = av[3];
            fma2(acc[0], a01.x, wv); fma2(acc[1], a01.y, wv);
            fma2(acc[2], a23.x, wv); fma2(acc[3], a23.y, wv);
            fma2(acc[4], a45.x, wv); fma2(acc[5], a45.y, wv);
            fma2(acc[6], a67.x, wv); fma2(acc[7], a67.y, wv);
        }
        if (it + 1 < nb) {
            const int nxt = cur ^ 1;
#pragma unroll
            for (int j = 0; j < 4; j++) *(float4*)&ws[nxt][kk][cc + j * 32] = wr[j];
            asp[nxt][ac + 0][at] = make_float2(ar.x, ar.x);
            asp[nxt][ac + 1][at] = make_float2(ar.y, ar.y);
        }
        __syncthreads();
    }

    float* Ob = O + (long)b * sO;
#pragma unroll
    for (int i = 0; i < 8; i++) {
        int t = tt * 8 + i;
        int n = nn * 2;
        float2 v = up2(acc[i]);
        float* dst = Ob + (long)t * ldo + n;
        atomicAdd(dst + 0, v.x);
        atomicAdd(dst + 1, v.y);
    }
}

// ---------------- per-head rmsnorm + RoPE for q/k, and new_v copy ----------------
__global__ void qk_norm_rope(float* __restrict__ q, float* __restrict__ k,
                             const float* __restrict__ v,
                             const float* __restrict__ qw, const float* __restrict__ kw,
                             const float* __restrict__ cosr, const float* __restrict__ sinr,
                             float* __restrict__ outk, float* __restrict__ outv) {
    int t = blockIdx.x;
    int hh = blockIdx.y;
    int d = threadIdx.x;

    if (hh >= 40) {
        int h = hh - 40;
        outv[(size_t)(h * T_NEW + t) * HD + d] = v[(size_t)t * (NKV * HD) + h * HD + d];
        return;
    }

    __shared__ float sv[HD];
    __shared__ float red[4];
    float* row; const float* w;
    if (hh < 32) { row = q + (size_t)t * (NH * HD) + hh * HD; w = qw; }
    else         { row = k + (size_t)t * (NKV * HD) + (hh - 32) * HD; w = kw; }

    float val = row[d];
    float s = val * val;
    for (int o = 16; o > 0; o >>= 1) s += __shfl_xor_sync(0xffffffffu, s, o);
    if ((d & 31) == 0) red[d >> 5] = s;
    __syncthreads();
    float tot = red[0] + red[1] + red[2] + red[3];
    float r = rsqrtf(tot / 128.f + RMS_EPS);
    float xn = val * r * w[d];
    sv[d] = xn;
    __syncthreads();
    float rot = (d < 64) ? -sv[d + 64] : sv[d - 64];
    float o = xn * cosr[t * HD + d] + rot * sinr[t * HD + d];
    row[d] = o;
    if (hh >= 32) {
        int h = hh - 32;
        outk[(size_t)(h * T_NEW + t) * HD + d] = o;
    }
}

// ---------------- row softmax over TFULL ----------------
__global__ void softmax_rows(float* __restrict__ s) {
    int row = blockIdx.x;
    float* p = s + (size_t)row * TFULL;
    __shared__ float red[8];
    int tid = threadIdx.x;
    float m = -3.4e38f;
    for (int i = tid; i < TFULL; i += 256) m = fmaxf(m, p[i]);
    for (int o = 16; o > 0; o >>= 1) m = fmaxf(m, __shfl_xor_sync(0xffffffffu, m, o));
    if ((tid & 31) == 0) red[tid >> 5] = m;
    __syncthreads();
    float mm = red[0];
#pragma unroll
    for (int i = 1; i < 8; i++) mm = fmaxf(mm, red[i]);
    __syncthreads();
    float sum = 0.f;
    for (int i = tid; i < TFULL; i += 256) {
        float e = expf(p[i] - mm);
        p[i] = e;
        sum += e;
    }
    for (int o = 16; o > 0; o >>= 1) sum += __shfl_xor_sync(0xffffffffu, sum, o);
    if ((tid & 31) == 0) red[tid >> 5] = sum;
    __syncthreads();
    float tot = 0.f;
#pragma unroll
    for (int i = 0; i < 8; i++) tot += red[i];
    float inv = 1.f / tot;
    for (int i = tid; i < TFULL; i += 256) p[i] *= inv;
}

// ---------------- elementwise helpers ----------------
__global__ void add_k(const float* __restrict__ a, const float* __restrict__ b,
                      float* __restrict__ o, int n) {
    int i = blockIdx.x * 256 + threadIdx.x;
    if (i < n) o[i] = a[i] + b[i];
}
__global__ void silu_mul_k(const float* __restrict__ g, const float* __restrict__ u,
                           float* __restrict__ o, int n) {
    int i = blockIdx.x * 256 + threadIdx.x;
    if (i < n) {
        float x = g[i];
        o[i] = (x / (1.f + expf(-x))) * u[i];
    }
}

static float* sym(const void* s) {
    void* p = nullptr;
    cudaGetSymbolAddress(&p, s);
    return (float*)p;
}

extern "C" void kernel_launch(void* const* d_in, const int* in_sizes, int n_in,
                              void* d_out, int out_size) {
    const float* x       = (const float*)d_in[0];
    const float* cos_q   = (const float*)d_in[1];
    const float* sin_q   = (const float*)d_in[2];
    const float* cache_k = (const float*)d_in[5];
    const float* cache_v = (const float*)d_in[6];
    const float* cmask   = (const float*)d_in[7];
    const float* ln1w    = (const float*)d_in[8];
    const float* ln2w    = (const float*)d_in[9];
    const float* qnw     = (const float*)d_in[10];
    const float* knw     = (const float*)d_in[11];
    const float* qw      = (const float*)d_in[12];
    const float* kw      = (const float*)d_in[13];
    const float* vw      = (const float*)d_in[14];
    const float* ow      = (const float*)d_in[15];
    const float* gw      = (const float*)d_in[16];
    const float* uw      = (const float*)d_in[17];
    const float* dw      = (const float*)d_in[18];
    float* out = (float*)d_out;
    float* out_k = out + T_NEW * HIDDEN;
    float* out_v = out_k + NKV * T_NEW * HD;

    static float *p_y = nullptr, *p_q, *p_k, *p_v, *p_scores, *p_attnout,
                 *p_oacc, *p_h, *p_y2, *p_gate, *p_up, *p_mid, *p_dacc;
    if (!p_y) {
        p_y = sym(g_y); p_q = sym(g_q); p_k = sym(g_k); p_v = sym(g_v);
        p_scores = sym(g_scores); p_attnout = sym(g_attnout); p_oacc = sym(g_oacc);
        p_h = sym(g_h); p_y2 = sym(g_y2); p_gate = sym(g_gate); p_up = sym(g_up);
        p_mid = sym(g_mid); p_dacc = sym(g_dacc);
    }

    const float scale = 0.08838834764831845f; // 1/sqrt(128)

    zero_scratch<<<608, 256>>>();

    // 1) y = rmsnorm(x) * ln1
    rmsnorm16<<<T_NEW, 256>>>(x, ln1w, p_y, HIDDEN);

    // 2) q/k/v projections (atomic split-K)
    gemmA<<<dim3(16, 1, 16), 128>>>(p_y, HIDDEN, 0, qw, 0, 1, HIDDEN,
        nullptr, 0, 0, HIDDEN, 160, p_q, NH * HD, 0, 1.f, nullptr, 0, 1);
    gemmA<<<dim3(4, 1, 16), 128>>>(p_y, HIDDEN, 0, kw, 0, 1, HIDDEN,
        nullptr, 0, 0, HIDDEN, 160, p_k, NKV * HD, 0, 1.f, nullptr, 0, 1);
    gemmA<<<dim3(4, 1, 16), 128>>>(p_y, HIDDEN, 0, vw, 0, 1, HIDDEN,
        nullptr, 0, 0, HIDDEN, 160, p_v, NKV * HD, 0, 1.f, nullptr, 0, 1);

    // 3) per-head q/k rmsnorm + RoPE; writes new_k/new_v into d_out
    qk_norm_rope<<<dim3(T_NEW, 48), 128>>>(p_q, p_k, p_v, qnw, knw, cos_q, sin_q,
                                           out_k, out_v);

    // 4) scores = (q @ K^T)*scale + mask; K rows come from cache / new split
    gemmA<<<dim3(16, NH, 1), 128>>>(
        p_q, NH * HD, HD,
        cache_k, (long)TC * HD, 4, HD,
        out_k, (long)T_NEW * HD, TC,
        HD, HD,
        p_scores, TFULL, (long)T_NEW * TFULL,
        scale, cmask, TFULL, 0);

    // 5) softmax
    softmax_rows<<<NH * T_NEW, 256>>>(p_scores);

    // 6) attn_out = P @ V (split-K over time, atomic); V rows cache/new split
    gemmB<<<dim3(1, NH, 16), 128>>>(
        p_scores, TFULL, (long)T_NEW * TFULL,
        cache_v, (long)TC * HD, 4, HD,
        out_v, (long)T_NEW * HD, TC,
        TFULL, 256,
        p_attnout, NH * HD, HD);

    // 7) o projection + residual
    gemmA<<<dim3(10, 1, 32), 128>>>(p_attnout, NH * HD, 0, ow, 0, 1, NH * HD,
        nullptr, 0, 0, NH * HD, 128, p_oacc, HIDDEN, 0, 1.f, nullptr, 0, 1);
    add_k<<<(T_NEW * HIDDEN + 255) / 256, 256>>>(x, p_oacc, p_h, T_NEW * HIDDEN);

    // 8) y2 = rmsnorm(h) * ln2
    rmsnorm16<<<T_NEW, 256>>>(p_h, ln2w, p_y2, HIDDEN);

    // 9) gate / up
    gemmA<<<dim3(38, 1, 8), 128>>>(p_y2, HIDDEN, 0, gw, 0, 1, HIDDEN,
        nullptr, 0, 0, HIDDEN, 320, p_gate, INTER, 0, 1.f, nullptr, 0, 1);
    gemmA<<<dim3(38, 1, 8), 128>>>(p_y2, HIDDEN, 0, uw, 0, 1, HIDDEN,
        nullptr, 0, 0, HIDDEN, 320, p_up, INTER, 0, 1.f, nullptr, 0, 1);

    // 10) mid = silu(gate) * up
    silu_mul_k<<<(T_NEW * INTER + 255) / 256, 256>>>(p_gate, p_up, p_mid, T_NEW * INTER);

    // 11) down projection + residual -> out
    gemmA<<<dim3(10, 1, 32), 128>>>(p_mid, INTER, 0, dw, 0, 1, INTER,
        nullptr, 0, 0, INTER, 304, p_dacc, HIDDEN, 0, 1.f, nullptr, 0, 1);
    add_k<<<(T_NEW * HIDDEN + 255) / 256, 256>>>(p_h, p_dacc, out, T_NEW * HIDDEN);
}

// round 4
// speedup vs baseline: 1.7815x; 1.1215x over previous
#include <cuda_runtime.h>
#include <cuda_bf16.h>
#include <math.h>

// ---------------- problem constants ----------------
#define T_NEW 16
#define HIDDEN 2560
#define INTER 9728
#define NH 32
#define NKV 8
#define HD 128
#define TC 4080
#define TFULL 4096
#define RMS_EPS 1e-6f
#define KT 16

typedef unsigned long long ull;

// ---------------- scratch (device globals, no allocs) ----------------
__device__ float g_y[T_NEW * HIDDEN];
__device__ float g_q[T_NEW * NH * HD];
__device__ float g_k[T_NEW * NKV * HD];
__device__ float g_v[T_NEW * NKV * HD];
__device__ float g_scores[NH * T_NEW * TFULL];
__device__ float g_attnout[T_NEW * NH * HD];
__device__ float g_h[T_NEW * HIDDEN];
__device__ float g_y2[T_NEW * HIDDEN];
__device__ float g_gate[T_NEW * INTER];
__device__ float g_up[T_NEW * INTER];
__device__ float g_mid[T_NEW * INTER];

// ---------------- packed f32x2 helpers ----------------
__device__ __forceinline__ void fma2(ull& d, ull a, ull b) {
    asm("fma.rn.f32x2 %0, %1, %2, %0;" : "+l"(d) : "l"(a), "l"(b));
}
__device__ __forceinline__ float2 up2(ull v) {
    float2 f;
    asm("mov.b64 {%0, %1}, %2;" : "=f"(f.x), "=f"(f.y) : "l"(v));
    return f;
}

// ---------------- zero atomic targets + seed h with x ----------------
__global__ void zero_scratch(const float* __restrict__ x) {
    int i = blockIdx.x * 256 + threadIdx.x;
    if (i < T_NEW * INTER) { g_gate[i] = 0.f; g_up[i] = 0.f; }
    if (i < T_NEW * NH * HD) { g_q[i] = 0.f; g_attnout[i] = 0.f; }
    if (i < T_NEW * NKV * HD) { g_k[i] = 0.f; g_v[i] = 0.f; }
    if (i < T_NEW * HIDDEN)  { g_h[i] = x[i]; }
}

// ---------------- rmsnorm per token (optional raw copy to cp) ----------------
__global__ void rmsnorm16(const float* __restrict__ x, const float* __restrict__ w,
                          float* __restrict__ y, float* __restrict__ cp, int D) {
    int t = blockIdx.x;
    const float* row = x + (size_t)t * D;
    float s = 0.f;
    for (int i = threadIdx.x; i < D; i += 256) { float v = row[i]; s += v * v; }
    __shared__ float red[8];
    for (int o = 16; o > 0; o >>= 1) s += __shfl_xor_sync(0xffffffffu, s, o);
    if ((threadIdx.x & 31) == 0) red[threadIdx.x >> 5] = s;
    __syncthreads();
    float tot = 0.f;
#pragma unroll
    for (int i = 0; i < 8; i++) tot += red[i];
    float r = rsqrtf(tot / (float)D + RMS_EPS);
    for (int i = threadIdx.x; i < D; i += 256) {
        float v = row[i];
        y[(size_t)t * D + i] = v * r * w[i];
        if (cp) cp[(size_t)t * D + i] = v;
    }
}

// =============================================================
// gemmM: multi-region skinny GEMM, out[t][nloc] += sum_k A[t][k]*W[n][k]
// Up to 3 weight regions selected by block's global-n tile. Atomic output.
// tile 16t x 256n, KT=16 double-buffered, 128 thr, thread tile 8t x 4n.
// =============================================================
__global__ void __launch_bounds__(128)
gemmM(const float* __restrict__ A, int lda,
      const float* __restrict__ W0, const float* __restrict__ W1,
      const float* __restrict__ W2,
      float* __restrict__ O0, float* __restrict__ O1, float* __restrict__ O2,
      int ldo0, int ldo1, int ldo2,
      int nb1, int nb2,
      int ldw, int K, int klen) {
    __shared__ __align__(16) float ws[2][KT][260];
    __shared__ __align__(16) float2 asp[2][KT][16];

    const int tid = threadIdx.x;
    const int g = blockIdx.x * 256;
    const int kbeg = blockIdx.z * klen;
    int kend = kbeg + klen; if (kend > K) kend = K;
    if (kbeg >= kend) return;

    const float* W; float* O; int ldo, nloc;
    if (g >= nb2)      { W = W2; O = O2; ldo = ldo2; nloc = g - nb2; }
    else if (g >= nb1) { W = W1; O = O1; ldo = ldo1; nloc = g - nb1; }
    else               { W = W0; O = O0; ldo = ldo0; nloc = g; }

    const float* wp0 = W + (long)(nloc + tid) * ldw;
    const float* wp1 = wp0 + (long)128 * ldw;

    const int at = tid >> 3;
    const int ac = (tid & 7) * 2;
    const float* ap = A + (long)at * lda + ac;

    const int tt = tid >> 6;
    const int nn = tid & 63;

    ull acc[8][2];
#pragma unroll
    for (int i = 0; i < 8; i++) { acc[i][0] = 0ULL; acc[i][1] = 0ULL; }

    float4 wr0[4], wr1[4];
    float2 ar;
    const int nb = (kend - kbeg) >> 4;

#pragma unroll
    for (int j = 0; j < 4; j++) {
        wr0[j] = *(const float4*)(wp0 + kbeg + j * 4);
        wr1[j] = *(const float4*)(wp1 + kbeg + j * 4);
    }
    ar = *(const float2*)(ap + kbeg);
#pragma unroll
    for (int j = 0; j < 4; j++) {
        ws[0][j * 4 + 0][tid] = wr0[j].x; ws[0][j * 4 + 1][tid] = wr0[j].y;
        ws[0][j * 4 + 2][tid] = wr0[j].z; ws[0][j * 4 + 3][tid] = wr0[j].w;
        ws[0][j * 4 + 0][tid + 128] = wr1[j].x; ws[0][j * 4 + 1][tid + 128] = wr1[j].y;
        ws[0][j * 4 + 2][tid + 128] = wr1[j].z; ws[0][j * 4 + 3][tid + 128] = wr1[j].w;
    }
    asp[0][ac + 0][at] = make_float2(ar.x, ar.x);
    asp[0][ac + 1][at] = make_float2(ar.y, ar.y);
    __syncthreads();

    for (int it = 0; it < nb; ++it) {
        const int cur = it & 1;
        if (it + 1 < nb) {
            int k0 = kbeg + (it + 1) * KT;
#pragma unroll
            for (int j = 0; j < 4; j++) {
                wr0[j] = *(const float4*)(wp0 + k0 + j * 4);
                wr1[j] = *(const float4*)(wp1 + k0 + j * 4);
            }
            ar = *(const float2*)(ap + k0);
        }
#pragma unroll
        for (int k = 0; k < KT; k++) {
            ulonglong2 w2 = *(const ulonglong2*)&ws[cur][k][nn * 4];
            const ulonglong2* av = (const ulonglong2*)&asp[cur][k][tt * 8];
            ulonglong2 a01 = av[0], a23 = av[1], a45 = av[2], a67 = av[3];
            fma2(acc[0][0], a01.x, w2.x); fma2(acc[0][1], a01.x, w2.y);
            fma2(acc[1][0], a01.y, w2.x); fma2(acc[1][1], a01.y, w2.y);
            fma2(acc[2][0], a23.x, w2.x); fma2(acc[2][1], a23.x, w2.y);
            fma2(acc[3][0], a23.y, w2.x); fma2(acc[3][1], a23.y, w2.y);
            fma2(acc[4][0], a45.x, w2.x); fma2(acc[4][1], a45.x, w2.y);
            fma2(acc[5][0], a45.y, w2.x); fma2(acc[5][1], a45.y, w2.y);
            fma2(acc[6][0], a67.x, w2.x); fma2(acc[6][1], a67.x, w2.y);
            fma2(acc[7][0], a67.y, w2.x); fma2(acc[7][1], a67.y, w2.y);
        }
        if (it + 1 < nb) {
            const int nxt = cur ^ 1;
#pragma unroll
            for (int j = 0; j < 4; j++) {
                ws[nxt][j * 4 + 0][tid] = wr0[j].x; ws[nxt][j * 4 + 1][tid] = wr0[j].y;
                ws[nxt][j * 4 + 2][tid] = wr0[j].z; ws[nxt][j * 4 + 3][tid] = wr0[j].w;
                ws[nxt][j * 4 + 0][tid + 128] = wr1[j].x; ws[nxt][j * 4 + 1][tid + 128] = wr1[j].y;
                ws[nxt][j * 4 + 2][tid + 128] = wr1[j].z; ws[nxt][j * 4 + 3][tid + 128] = wr1[j].w;
            }
            asp[nxt][ac + 0][at] = make_float2(ar.x, ar.x);
            asp[nxt][ac + 1][at] = make_float2(ar.y, ar.y);
        }
        __syncthreads();
    }

#pragma unroll
    for (int i = 0; i < 8; i++) {
        int t = tt * 8 + i;
        int n = nloc + nn * 4;
        float2 v0 = up2(acc[i][0]);
        float2 v1 = up2(acc[i][1]);
        float* dst = O + (long)t * ldo + n;
        atomicAdd(dst + 0, v0.x); atomicAdd(dst + 1, v0.y);
        atomicAdd(dst + 2, v1.x); atomicAdd(dst + 3, v1.y);
    }
}

// =============================================================
// gemmA: scores GEMM with cache/new weight-row split, mask + scale, batched.
// =============================================================
__global__ void __launch_bounds__(128)
gemmA(const float* __restrict__ A, int lda, long sA,
      const float* __restrict__ Wc, long sWc, int wdiv, int ldw,
      const float* __restrict__ Wn, long sWn, int rowSw,
      int K,
      float* __restrict__ O, int ldo, long sO,
      float scale, const float* __restrict__ maskAdd, int maskld) {
    __shared__ __align__(16) float ws[2][KT][260];
    __shared__ __align__(16) float2 asp[2][KT][16];

    const int tid = threadIdx.x;
    const int b = blockIdx.y;
    const int nbase = blockIdx.x * 256;

    const float* Ab = A + (long)b * sA;
    const int r0 = nbase + tid, r1 = r0 + 128;
    const float* wp0 = (r0 >= rowSw)
        ? Wn + (long)(b / wdiv) * sWn + (long)(r0 - rowSw) * ldw
        : Wc + (long)(b / wdiv) * sWc + (long)r0 * ldw;
    const float* wp1 = (r1 >= rowSw)
        ? Wn + (long)(b / wdiv) * sWn + (long)(r1 - rowSw) * ldw
        : Wc + (long)(b / wdiv) * sWc + (long)r1 * ldw;

    const int at = tid >> 3;
    const int ac = (tid & 7) * 2;
    const float* ap = Ab + (long)at * lda + ac;

    const int tt = tid >> 6;
    const int nn = tid & 63;

    ull acc[8][2];
#pragma unroll
    for (int i = 0; i < 8; i++) { acc[i][0] = 0ULL; acc[i][1] = 0ULL; }

    float4 wr0[4], wr1[4];
    float2 ar;
    const int nb = K >> 4;

#pragma unroll
    for (int j = 0; j < 4; j++) {
        wr0[j] = *(const float4*)(wp0 + j * 4);
        wr1[j] = *(const float4*)(wp1 + j * 4);
    }
    ar = *(const float2*)(ap);
#pragma unroll
    for (int j = 0; j < 4; j++) {
        ws[0][j * 4 + 0][tid] = wr0[j].x; ws[0][j * 4 + 1][tid] = wr0[j].y;
        ws[0][j * 4 + 2][tid] = wr0[j].z; ws[0][j * 4 + 3][tid] = wr0[j].w;
        ws[0][j * 4 + 0][tid + 128] = wr1[j].x; ws[0][j * 4 + 1][tid + 128] = wr1[j].y;
        ws[0][j * 4 + 2][tid + 128] = wr1[j].z; ws[0][j * 4 + 3][tid + 128] = wr1[j].w;
    }
    asp[0][ac + 0][at] = make_float2(ar.x, ar.x);
    asp[0][ac + 1][at] = make_float2(ar.y, ar.y);
    __syncthreads();

    for (int it = 0; it < nb; ++it) {
        const int cur = it & 1;
        if (it + 1 < nb) {
            int k0 = (it + 1) * KT;
#pragma unroll
            for (int j = 0; j < 4; j++) {
                wr0[j] = *(const float4*)(wp0 + k0 + j * 4);
                wr1[j] = *(const float4*)(wp1 + k0 + j * 4);
            }
            ar = *(const float2*)(ap + k0);
        }
#pragma unroll
        for (int k = 0; k < KT; k++) {
            ulonglong2 w2 = *(const ulonglong2*)&ws[cur][k][nn * 4];
            const ulonglong2* av = (const ulonglong2*)&asp[cur][k][tt * 8];
            ulonglong2 a01 = av[0], a23 = av[1], a45 = av[2], a67 = av[3];
            fma2(acc[0][0], a01.x, w2.x); fma2(acc[0][1], a01.x, w2.y);
            fma2(acc[1][0], a01.y, w2.x); fma2(acc[1][1], a01.y, w2.y);
            fma2(acc[2][0], a23.x, w2.x); fma2(acc[2][1], a23.x, w2.y);
            fma2(acc[3][0], a23.y, w2.x); fma2(acc[3][1], a23.y, w2.y);
            fma2(acc[4][0], a45.x, w2.x); fma2(acc[4][1], a45.x, w2.y);
            fma2(acc[5][0], a45.y, w2.x); fma2(acc[5][1], a45.y, w2.y);
            fma2(acc[6][0], a67.x, w2.x); fma2(acc[6][1], a67.x, w2.y);
            fma2(acc[7][0], a67.y, w2.x); fma2(acc[7][1], a67.y, w2.y);
        }
        if (it + 1 < nb) {
            const int nxt = cur ^ 1;
#pragma unroll
            for (int j = 0; j < 4; j++) {
                ws[nxt][j * 4 + 0][tid] = wr0[j].x; ws[nxt][j * 4 + 1][tid] = wr0[j].y;
                ws[nxt][j * 4 + 2][tid] = wr0[j].z; ws[nxt][j * 4 + 3][tid] = wr0[j].w;
                ws[nxt][j * 4 + 0][tid + 128] = wr1[j].x; ws[nxt][j * 4 + 1][tid + 128] = wr1[j].y;
                ws[nxt][j * 4 + 2][tid + 128] = wr1[j].z; ws[nxt][j * 4 + 3][tid + 128] = wr1[j].w;
            }
            asp[nxt][ac + 0][at] = make_float2(ar.x, ar.x);
            asp[nxt][ac + 1][at] = make_float2(ar.y, ar.y);
        }
        __syncthreads();
    }

    float* Ob = O + (long)b * sO;
#pragma unroll
    for (int i = 0; i < 8; i++) {
        int t = tt * 8 + i;
        int n = nbase + nn * 4;
        float2 v0 = up2(acc[i][0]);
        float2 v1 = up2(acc[i][1]);
        float4 v = make_float4(v0.x * scale, v0.y * scale, v1.x * scale, v1.y * scale);
        const float* m = maskAdd + (long)t * maskld + n;
        v.x += m[0]; v.y += m[1]; v.z += m[2]; v.w += m[3];
        *(float4*)(Ob + (long)t * ldo + n) = v;
    }
}

// =============================================================
// gemmB: out[t][n] = sum_k A[t][k] * V[k][n], V rows cache/new split. PV GEMM.
// =============================================================
__global__ void __launch_bounds__(128)
gemmB(const float* __restrict__ A, int lda, long sA,
      const float* __restrict__ Wc, long sWc, int wdiv, int ldw,
      const float* __restrict__ Wn, long sWn, int rowSw,
      int K, int klen,
      float* __restrict__ O, int ldo, long sO) {
    __shared__ __align__(16) float ws[2][KT][132];
    __shared__ __align__(16) float2 asp[2][KT][16];

    const int tid = threadIdx.x;
    const int b = blockIdx.y;
    const int kbeg = blockIdx.z * klen;
    int kend = kbeg + klen; if (kend > K) kend = K;
    if (kbeg >= kend) return;

    const float* Ab = A + (long)b * sA;
    const long wco = (long)(b / wdiv) * sWc;
    const long wno = (long)(b / wdiv) * sWn;

    const int kk = tid >> 3;
    const int cc = (tid & 7) * 4;

    const int at = tid >> 3;
    const int ac = (tid & 7) * 2;
    const float* ap = Ab + (long)at * lda + ac;

    const int tt = tid >> 6;
    const int nn = tid & 63;

    ull acc[8];
#pragma unroll
    for (int i = 0; i < 8; i++) acc[i] = 0ULL;

    float4 wr[4];
    float2 ar;
    const int nb = (kend - kbeg) >> 4;

    {
        int r = kbeg + kk;
        const float* wp = (r >= rowSw) ? Wn + wno + (long)(r - rowSw) * ldw
                                       : Wc + wco + (long)r * ldw;
#pragma unroll
        for (int j = 0; j < 4; j++) wr[j] = *(const float4*)(wp + cc + j * 32);
        ar = *(const float2*)(ap + kbeg);
#pragma unroll
        for (int j = 0; j < 4; j++) *(float4*)&ws[0][kk][cc + j * 32] = wr[j];
        asp[0][ac + 0][at] = make_float2(ar.x, ar.x);
        asp[0][ac + 1][at] = make_float2(ar.y, ar.y);
    }
    __syncthreads();

    for (int it = 0; it < nb; ++it) {
        const int cur = it & 1;
        if (it + 1 < nb) {
            int k0 = kbeg + (it + 1) * KT;
            int r = k0 + kk;
            const float* wp = (r >= rowSw) ? Wn + wno + (long)(r - rowSw) * ldw
                                           : Wc + wco + (long)r * ldw;
#pragma unroll
            for (int j = 0; j < 4; j++) wr[j] = *(const float4*)(wp + cc + j * 32);
            ar = *(const float2*)(ap + k0);
        }
#pragma unroll
        for (int k = 0; k < KT; k++) {
            ull wv = *(const ull*)&ws[cur][k][nn * 2];
            const ulonglong2* av = (const ulonglong2*)&asp[cur][k][tt * 8];
            ulonglong2 a01 = av[0], a23 = av[1], a45 = av[2], a67 = av[3];
            fma2(acc[0], a01.x, wv); fma2(acc[1], a01.y, wv);
            fma2(acc[2], a23.x, wv); fma2(acc[3], a23.y, wv);
            fma2(acc[4], a45.x, wv); fma2(acc[5], a45.y, wv);
            fma2(acc[6], a67.x, wv); fma2(acc[7], a67.y, wv);
        }
        if (it + 1 < nb) {
            const int nxt = cur ^ 1;
#pragma unroll
            for (int j = 0; j < 4; j++) *(float4*)&ws[nxt][kk][cc + j * 32] = wr[j];
            asp[nxt][ac + 0][at] = make_float2(ar.x, ar.x);
            asp[nxt][ac + 1][at] = make_float2(ar.y, ar.y);
        }
        __syncthreads();
    }

    float* Ob = O + (long)b * sO;
#pragma unroll
    for (int i = 0; i < 8; i++) {
        int t = tt * 8 + i;
        int n = nn * 2;
        float2 v = up2(acc[i]);
        float* dst = Ob + (long)t * ldo + n;
        atomicAdd(dst + 0, v.x);
        atomicAdd(dst + 1, v.y);
    }
}

// ---------------- per-head rmsnorm + RoPE for q/k, and new_v copy ----------------
__global__ void qk_norm_rope(float* __restrict__ q, float* __restrict__ k,
                             const float* __restrict__ v,
                             const float* __restrict__ qw, const float* __restrict__ kw,
                             const float* __restrict__ cosr, const float* __restrict__ sinr,
                             float* __restrict__ outk, float* __restrict__ outv) {
    int t = blockIdx.x;
    int hh = blockIdx.y;
    int d = threadIdx.x;

    if (hh >= 40) {
        int h = hh - 40;
        outv[(size_t)(h * T_NEW + t) * HD + d] = v[(size_t)t * (NKV * HD) + h * HD + d];
        return;
    }

    __shared__ float sv[HD];
    __shared__ float red[4];
    float* row; const float* w;
    if (hh < 32) { row = q + (size_t)t * (NH * HD) + hh * HD; w = qw; }
    else         { row = k + (size_t)t * (NKV * HD) + (hh - 32) * HD; w = kw; }

    float val = row[d];
    float s = val * val;
    for (int o = 16; o > 0; o >>= 1) s += __shfl_xor_sync(0xffffffffu, s, o);
    if ((d & 31) == 0) red[d >> 5] = s;
    __syncthreads();
    float tot = red[0] + red[1] + red[2] + red[3];
    float r = rsqrtf(tot / 128.f + RMS_EPS);
    float xn = val * r * w[d];
    sv[d] = xn;
    __syncthreads();
    float rot = (d < 64) ? -sv[d + 64] : sv[d - 64];
    float o = xn * cosr[t * HD + d] + rot * sinr[t * HD + d];
    row[d] = o;
    if (hh >= 32) {
        int h = hh - 32;
        outk[(size_t)(h * T_NEW + t) * HD + d] = o;
    }
}

// ---------------- row softmax over TFULL ----------------
__global__ void softmax_rows(float* __restrict__ s) {
    int row = blockIdx.x;
    float* p = s + (size_t)row * TFULL;
    __shared__ float red[8];
    int tid = threadIdx.x;
    float m = -3.4e38f;
    for (int i = tid; i < TFULL; i += 256) m = fmaxf(m, p[i]);
    for (int o = 16; o > 0; o >>= 1) m = fmaxf(m, __shfl_xor_sync(0xffffffffu, m, o));
    if ((tid & 31) == 0) red[tid >> 5] = m;
    __syncthreads();
    float mm = red[0];
#pragma unroll
    for (int i = 1; i < 8; i++) mm = fmaxf(mm, red[i]);
    __syncthreads();
    float sum = 0.f;
    for (int i = tid; i < TFULL; i += 256) {
        float e = expf(p[i] - mm);
        p[i] = e;
        sum += e;
    }
    for (int o = 16; o > 0; o >>= 1) sum += __shfl_xor_sync(0xffffffffu, sum, o);
    if ((tid & 31) == 0) red[tid >> 5] = sum;
    __syncthreads();
    float tot = 0.f;
#pragma unroll
    for (int i = 0; i < 8; i++) tot += red[i];
    float inv = 1.f / tot;
    for (int i = tid; i < TFULL; i += 256) p[i] *= inv;
}

// ---------------- silu * up ----------------
__global__ void silu_mul_k(const float* __restrict__ g, const float* __restrict__ u,
                           float* __restrict__ o, int n) {
    int i = blockIdx.x * 256 + threadIdx.x;
    if (i < n) {
        float x = g[i];
        o[i] = (x / (1.f + expf(-x))) * u[i];
    }
}

static float* sym(const void* s) {
    void* p = nullptr;
    cudaGetSymbolAddress(&p, s);
    return (float*)p;
}

extern "C" void kernel_launch(void* const* d_in, const int* in_sizes, int n_in,
                              void* d_out, int out_size) {
    const float* x       = (const float*)d_in[0];
    const float* cos_q   = (const float*)d_in[1];
    const float* sin_q   = (const float*)d_in[2];
    const float* cache_k = (const float*)d_in[5];
    const float* cache_v = (const float*)d_in[6];
    const float* cmask   = (const float*)d_in[7];
    const float* ln1w    = (const float*)d_in[8];
    const float* ln2w    = (const float*)d_in[9];
    const float* qnw     = (const float*)d_in[10];
    const float* knw     = (const float*)d_in[11];
    const float* qw      = (const float*)d_in[12];
    const float* kw      = (const float*)d_in[13];
    const float* vw      = (const float*)d_in[14];
    const float* ow      = (const float*)d_in[15];
    const float* gw      = (const float*)d_in[16];
    const float* uw      = (const float*)d_in[17];
    const float* dw      = (const float*)d_in[18];
    float* out = (float*)d_out;
    float* out_k = out + T_NEW * HIDDEN;
    float* out_v = out_k + NKV * T_NEW * HD;

    static float *p_y = nullptr, *p_q, *p_k, *p_v, *p_scores, *p_attnout,
                 *p_h, *p_y2, *p_gate, *p_up, *p_mid;
    if (!p_y) {
        p_y = sym(g_y); p_q = sym(g_q); p_k = sym(g_k); p_v = sym(g_v);
        p_scores = sym(g_scores); p_attnout = sym(g_attnout);
        p_h = sym(g_h); p_y2 = sym(g_y2); p_gate = sym(g_gate); p_up = sym(g_up);
        p_mid = sym(g_mid);
    }

    const float scale = 0.08838834764831845f; // 1/sqrt(128)
    const int BIG = 1 << 30;

    // 0) zero atomic targets; seed h = x
    zero_scratch<<<(T_NEW * INTER + 255) / 256, 256>>>(x);

    // 1) y = rmsnorm(x) * ln1
    rmsnorm16<<<T_NEW, 256>>>(x, ln1w, p_y, nullptr, HIDDEN);

    // 2) fused q/k/v projection: regions [0,4096)->q, [4096,5120)->k, [5120,6144)->v
    gemmM<<<dim3(24, 1, 16), 128>>>(p_y, HIDDEN,
        qw, kw, vw, p_q, p_k, p_v,
        NH * HD, NKV * HD, NKV * HD,
        4096, 5120, HIDDEN, HIDDEN, 160);

    // 3) per-head q/k rmsnorm + RoPE; writes new_k/new_v into d_out
    qk_norm_rope<<<dim3(T_NEW, 48), 128>>>(p_q, p_k, p_v, qnw, knw, cos_q, sin_q,
                                           out_k, out_v);

    // 4) scores = (q @ K^T)*scale + mask (K rows: cache / new split)
    gemmA<<<dim3(16, NH, 1), 128>>>(
        p_q, NH * HD, HD,
        cache_k, (long)TC * HD, 4, HD,
        out_k, (long)T_NEW * HD, TC,
        HD,
        p_scores, TFULL, (long)T_NEW * TFULL,
        scale, cmask, TFULL);

    // 5) softmax
    softmax_rows<<<NH * T_NEW, 256>>>(p_scores);

    // 6) attn_out = P @ V (split-K over time, atomic)
    gemmB<<<dim3(1, NH, 16), 128>>>(
        p_scores, TFULL, (long)T_NEW * TFULL,
        cache_v, (long)TC * HD, 4, HD,
        out_v, (long)T_NEW * HD, TC,
        TFULL, 256,
        p_attnout, NH * HD, HD);

    // 7) o projection accumulates directly into h (pre-seeded with x)
    gemmM<<<dim3(10, 1, 32), 128>>>(p_attnout, NH * HD,
        ow, ow, ow, p_h, p_h, p_h,
        HIDDEN, HIDDEN, HIDDEN,
        BIG, BIG, NH * HD, NH * HD, 128);

    // 8) y2 = rmsnorm(h) * ln2; also copy h -> out (residual seed for down-proj)
    rmsnorm16<<<T_NEW, 256>>>(p_h, ln2w, p_y2, out, HIDDEN);

    // 9) fused gate/up: regions [0,9728)->gate, [9728,19456)->up
    gemmM<<<dim3(76, 1, 8), 128>>>(p_y2, HIDDEN,
        gw, uw, uw, p_gate, p_up, p_up,
        INTER, INTER, INTER,
        INTER, BIG, HIDDEN, HIDDEN, 320);

    // 10) mid = silu(gate) * up
    silu_mul_k<<<(T_NEW * INTER + 255) / 256, 256>>>(p_gate, p_up, p_mid, T_NEW * INTER);

    // 11) down projection accumulates directly into out (pre-seeded with h)
    gemmM<<<dim3(10, 1, 32), 128>>>(p_mid, INTER,
        dw, dw, dw, out, out, out,
        HIDDEN, HIDDEN, HIDDEN,
        BIG, BIG, INTER, INTER, 304);
}

// round 9
// speedup vs baseline: 1.8901x; 1.0610x over previous
#include <cuda_runtime.h>
#include <cuda_bf16.h>
#include <math.h>
#include <stdint.h>

// ---------------- problem constants ----------------
#define T_NEW 16
#define HIDDEN 2560
#define INTER 9728
#define NH 32
#define NKV 8
#define HD 128
#define TC 4080
#define TFULL 4096
#define RMS_EPS 1e-6f
#define KT 16

typedef unsigned long long ull;

// ---------------- scratch (device globals, no allocs) ----------------
__device__ float g_y[T_NEW * HIDDEN];
__device__ float g_q[T_NEW * NH * HD];
__device__ float g_k[T_NEW * NKV * HD];
__device__ float g_v[T_NEW * NKV * HD];
__device__ float g_scores[NH * T_NEW * TFULL];
__device__ float g_attnout[T_NEW * NH * HD];
__device__ float g_h[T_NEW * HIDDEN];
__device__ float g_y2[T_NEW * HIDDEN];
__device__ float g_gate[T_NEW * INTER];
__device__ float g_up[T_NEW * INTER];
__device__ float g_mid[T_NEW * INTER];

// ---------------- packed f32x2 helpers (scalar attention path) ----------------
__device__ __forceinline__ void fma2(ull& d, ull a, ull b) {
    asm("fma.rn.f32x2 %0, %1, %2, %0;" : "+l"(d) : "l"(a), "l"(b));
}
__device__ __forceinline__ float2 up2(ull v) {
    float2 f;
    asm("mov.b64 {%0, %1}, %2;" : "=f"(f.x), "=f"(f.y) : "l"(v));
    return f;
}

// ---------------- tf32 mma.sync helpers (portable, sm_80+) ----------------
__device__ __forceinline__ uint32_t tf(float x) {
    uint32_t r;
    asm("cvt.rna.tf32.f32 %0, %1;" : "=r"(r) : "f"(x));
    return r;
}
__device__ __forceinline__ void mma16n8k8(float* c,
                                          uint32_t a0, uint32_t a1, uint32_t a2, uint32_t a3,
                                          uint32_t b0, uint32_t b1) {
    asm volatile(
        "mma.sync.aligned.m16n8k8.row.col.f32.tf32.tf32.f32 "
        "{%0,%1,%2,%3}, {%4,%5,%6,%7}, {%8,%9}, {%0,%1,%2,%3};"
        : "+f"(c[0]), "+f"(c[1]), "+f"(c[2]), "+f"(c[3])
        : "r"(a0), "r"(a1), "r"(a2), "r"(a3), "r"(b0), "r"(b1));
}

// ---------------- zero atomic targets + seed h with x ----------------
__global__ void zero_scratch(const float* __restrict__ x) {
    int i = blockIdx.x * 256 + threadIdx.x;
    if (i < T_NEW * INTER) { g_gate[i] = 0.f; g_up[i] = 0.f; }
    if (i < T_NEW * NH * HD) { g_q[i] = 0.f; g_attnout[i] = 0.f; }
    if (i < T_NEW * NKV * HD) { g_k[i] = 0.f; g_v[i] = 0.f; }
    if (i < T_NEW * HIDDEN)  { g_h[i] = x[i]; }
}

// ---------------- rmsnorm per token (optional raw copy to cp) ----------------
__global__ void rmsnorm16(const float* __restrict__ x, const float* __restrict__ w,
                          float* __restrict__ y, float* __restrict__ cp, int D) {
    int t = blockIdx.x;
    const float* row = x + (size_t)t * D;
    float s = 0.f;
    for (int i = threadIdx.x; i < D; i += 256) { float v = row[i]; s += v * v; }
    __shared__ float red[8];
    for (int o = 16; o > 0; o >>= 1) s += __shfl_xor_sync(0xffffffffu, s, o);
    if ((threadIdx.x & 31) == 0) red[threadIdx.x >> 5] = s;
    __syncthreads();
    float tot = 0.f;
#pragma unroll
    for (int i = 0; i < 8; i++) tot += red[i];
    float r = rsqrtf(tot / (float)D + RMS_EPS);
    for (int i = threadIdx.x; i < D; i += 256) {
        float v = row[i];
        y[(size_t)t * D + i] = v * r * w[i];
        if (cp) cp[(size_t)t * D + i] = v;
    }
}

// =============================================================
// mmaProj: tf32 mma.sync GEMM. out[t][n] += sum_k act[t][k] * W[n][k]
// Block: 256 thr = 8 warps x 32 weight-rows = 256 rows; m = 16 tokens.
// A = activations (m16), B = weight rows (.col => B[k][n] = W[n][k]).
// Up to 3 weight regions (fused QKV / gate+up). Split-K via atomics
// into pre-seeded/zeroed outputs.
// =============================================================
__global__ void __launch_bounds__(256)
mmaProj(const float* __restrict__ act,
        const float* __restrict__ W0, const float* __restrict__ W1,
        const float* __restrict__ W2,
        float* __restrict__ O0, float* __restrict__ O1, float* __restrict__ O2,
        int ldo0, int ldo1, int ldo2, int nb1, int nb2,
        int K, int klen) {
    const int tid = threadIdx.x;
    const int wid = tid >> 5;
    const int lane = tid & 31;
    const int g = blockIdx.x * 256;

    const float* W; float* O; int ldo, nloc;
    if (g >= nb2)      { W = W2; O = O2; ldo = ldo2; nloc = g - nb2; }
    else if (g >= nb1) { W = W1; O = O1; ldo = ldo1; nloc = g - nb1; }
    else               { W = W0; O = O0; ldo = ldo0; nloc = g; }

    const int R = nloc + wid * 32;
    const int kbeg = blockIdx.z * klen;
    const int kq = lane & 3;
    const int rsel = lane >> 2;

    const float* ap0 = act + (long)rsel * K;
    const float* ap1 = act + (long)(rsel + 8) * K;
    const float* wp0 = W + (long)(R + 0  + rsel) * K;
    const float* wp1 = W + (long)(R + 8  + rsel) * K;
    const float* wp2 = W + (long)(R + 16 + rsel) * K;
    const float* wp3 = W + (long)(R + 24 + rsel) * K;

    float c[4][4];
#pragma unroll
    for (int j = 0; j < 4; j++)
#pragma unroll
        for (int i = 0; i < 4; i++) c[j][i] = 0.f;

    for (int k = kbeg; k < kbeg + klen; k += 32) {
#pragma unroll
        for (int s = 0; s < 4; s++) {
            const int kk = k + s * 8 + kq;
            uint32_t a0 = tf(ap0[kk]);
            uint32_t a1 = tf(ap1[kk]);
            uint32_t a2 = tf(ap0[kk + 4]);
            uint32_t a3 = tf(ap1[kk + 4]);
            {
                uint32_t b0 = tf(wp0[kk]), b1 = tf(wp0[kk + 4]);
                mma16n8k8(c[0], a0, a1, a2, a3, b0, b1);
            }
            {
                uint32_t b0 = tf(wp1[kk]), b1 = tf(wp1[kk + 4]);
                mma16n8k8(c[1], a0, a1, a2, a3, b0, b1);
            }
            {
                uint32_t b0 = tf(wp2[kk]), b1 = tf(wp2[kk + 4]);
                mma16n8k8(c[2], a0, a1, a2, a3, b0, b1);
            }
            {
                uint32_t b0 = tf(wp3[kk]), b1 = tf(wp3[kk + 4]);
                mma16n8k8(c[3], a0, a1, a2, a3, b0, b1);
            }
        }
    }

    const int t0 = lane >> 2, t1 = t0 + 8;
    const int ncol = (lane & 3) * 2;
#pragma unroll
    for (int j = 0; j < 4; j++) {
        int n = R + j * 8 + ncol;
        atomicAdd(O + (long)t0 * ldo + n,     c[j][0]);
        atomicAdd(O + (long)t0 * ldo + n + 1, c[j][1]);
        atomicAdd(O + (long)t1 * ldo + n,     c[j][2]);
        atomicAdd(O + (long)t1 * ldo + n + 1, c[j][3]);
    }
}

// =============================================================
// gemmA (fp32 scalar): scores GEMM with cache/new weight-row split + mask.
// =============================================================
__global__ void __launch_bounds__(128)
gemmA(const float* __restrict__ A, int lda, long sA,
      const float* __restrict__ Wc, long sWc, int wdiv, int ldw,
      const float* __restrict__ Wn, long sWn, int rowSw,
      int K,
      float* __restrict__ O, int ldo, long sO,
      float scale, const float* __restrict__ maskAdd, int maskld) {
    __shared__ __align__(16) float ws[2][KT][260];
    __shared__ __align__(16) float2 asp[2][KT][16];

    const int tid = threadIdx.x;
    const int b = blockIdx.y;
    const int nbase = blockIdx.x * 256;

    const float* Ab = A + (long)b * sA;
    const int r0 = nbase + tid, r1 = r0 + 128;
    const float* wp0 = (r0 >= rowSw)
        ? Wn + (long)(b / wdiv) * sWn + (long)(r0 - rowSw) * ldw
        : Wc + (long)(b / wdiv) * sWc + (long)r0 * ldw;
    const float* wp1 = (r1 >= rowSw)
        ? Wn + (long)(b / wdiv) * sWn + (long)(r1 - rowSw) * ldw
        : Wc + (long)(b / wdiv) * sWc + (long)r1 * ldw;

    const int at = tid >> 3;
    const int ac = (tid & 7) * 2;
    const float* ap = Ab + (long)at * lda + ac;

    const int tt = tid >> 6;
    const int nn = tid & 63;

    ull acc[8][2];
#pragma unroll
    for (int i = 0; i < 8; i++) { acc[i][0] = 0ULL; acc[i][1] = 0ULL; }

    float4 wr0[4], wr1[4];
    float2 ar;
    const int nb = K >> 4;

#pragma unroll
    for (int j = 0; j < 4; j++) {
        wr0[j] = *(const float4*)(wp0 + j * 4);
        wr1[j] = *(const float4*)(wp1 + j * 4);
    }
    ar = *(const float2*)(ap);
#pragma unroll
    for (int j = 0; j < 4; j++) {
        ws[0][j * 4 + 0][tid] = wr0[j].x; ws[0][j * 4 + 1][tid] = wr0[j].y;
        ws[0][j * 4 + 2][tid] = wr0[j].z; ws[0][j * 4 + 3][tid] = wr0[j].w;
        ws[0][j * 4 + 0][tid + 128] = wr1[j].x; ws[0][j * 4 + 1][tid + 128] = wr1[j].y;
        ws[0][j * 4 + 2][tid + 128] = wr1[j].z; ws[0][j * 4 + 3][tid + 128] = wr1[j].w;
    }
    asp[0][ac + 0][at] = make_float2(ar.x, ar.x);
    asp[0][ac + 1][at] = make_float2(ar.y, ar.y);
    __syncthreads();

    for (int it = 0; it < nb; ++it) {
        const int cur = it & 1;
        if (it + 1 < nb) {
            int k0 = (it + 1) * KT;
#pragma unroll
            for (int j = 0; j < 4; j++) {
                wr0[j] = *(const float4*)(wp0 + k0 + j * 4);
                wr1[j] = *(const float4*)(wp1 + k0 + j * 4);
            }
            ar = *(const float2*)(ap + k0);
        }
#pragma unroll
        for (int k = 0; k < KT; k++) {
            ulonglong2 w2 = *(const ulonglong2*)&ws[cur][k][nn * 4];
            const ulonglong2* av = (const ulonglong2*)&asp[cur][k][tt * 8];
            ulonglong2 a01 = av[0], a23 = av[1], a45 = av[2], a67 = av[3];
            fma2(acc[0][0], a01.x, w2.x); fma2(acc[0][1], a01.x, w2.y);
            fma2(acc[1][0], a01.y, w2.x); fma2(acc[1][1], a01.y, w2.y);
            fma2(acc[2][0], a23.x, w2.x); fma2(acc[2][1], a23.x, w2.y);
            fma2(acc[3][0], a23.y, w2.x); fma2(acc[3][1], a23.y, w2.y);
            fma2(acc[4][0], a45.x, w2.x); fma2(acc[4][1], a45.x, w2.y);
            fma2(acc[5][0], a45.y, w2.x); fma2(acc[5][1], a45.y, w2.y);
            fma2(acc[6][0], a67.x, w2.x); fma2(acc[6][1], a67.x, w2.y);
            fma2(acc[7][0], a67.y, w2.x); fma2(acc[7][1], a67.y, w2.y);
        }
        if (it + 1 < nb) {
            const int nxt = cur ^ 1;
#pragma unroll
            for (int j = 0; j < 4; j++) {
                ws[nxt][j * 4 + 0][tid] = wr0[j].x; ws[nxt][j * 4 + 1][tid] = wr0[j].y;
                ws[nxt][j * 4 + 2][tid] = wr0[j].z; ws[nxt][j * 4 + 3][tid] = wr0[j].w;
                ws[nxt][j * 4 + 0][tid + 128] = wr1[j].x; ws[nxt][j * 4 + 1][tid + 128] = wr1[j].y;
                ws[nxt][j * 4 + 2][tid + 128] = wr1[j].z; ws[nxt][j * 4 + 3][tid + 128] = wr1[j].w;
            }
            asp[nxt][ac + 0][at] = make_float2(ar.x, ar.x);
            asp[nxt][ac + 1][at] = make_float2(ar.y, ar.y);
        }
        __syncthreads();
    }

    float* Ob = O + (long)b * sO;
#pragma unroll
    for (int i = 0; i < 8; i++) {
        int t = tt * 8 + i;
        int n = nbase + nn * 4;
        float2 v0 = up2(acc[i][0]);
        float2 v1 = up2(acc[i][1]);
        float4 v = make_float4(v0.x * scale, v0.y * scale, v1.x * scale, v1.y * scale);
        const float* m = maskAdd + (long)t * maskld + n;
        v.x += m[0]; v.y += m[1]; v.z += m[2]; v.w += m[3];
        *(float4*)(Ob + (long)t * ldo + n) = v;
    }
}

// =============================================================
// gemmB (fp32 scalar): PV GEMM with cache/new V-row split, split-K atomic.
// =============================================================
__global__ void __launch_bounds__(128)
gemmB(const float* __restrict__ A, int lda, long sA,
      const float* __restrict__ Wc, long sWc, int wdiv, int ldw,
      const float* __restrict__ Wn, long sWn, int rowSw,
      int K, int klen,
      float* __restrict__ O, int ldo, long sO) {
    __shared__ __align__(16) float ws[2][KT][132];
    __shared__ __align__(16) float2 asp[2][KT][16];

    const int tid = threadIdx.x;
    const int b = blockIdx.y;
    const int kbeg = blockIdx.z * klen;
    int kend = kbeg + klen; if (kend > K) kend = K;
    if (kbeg >= kend) return;

    const float* Ab = A + (long)b * sA;
    const long wco = (long)(b / wdiv) * sWc;
    const long wno = (long)(b / wdiv) * sWn;

    const int kk = tid >> 3;
    const int cc = (tid & 7) * 4;

    const int at = tid >> 3;
    const int ac = (tid & 7) * 2;
    const float* ap = Ab + (long)at * lda + ac;

    const int tt = tid >> 6;
    const int nn = tid & 63;

    ull acc[8];
#pragma unroll
    for (int i = 0; i < 8; i++) acc[i] = 0ULL;

    float4 wr[4];
    float2 ar;
    const int nb = (kend - kbeg) >> 4;

    {
        int r = kbeg + kk;
        const float* wp = (r >= rowSw) ? Wn + wno + (long)(r - rowSw) * ldw
                                       : Wc + wco + (long)r * ldw;
#pragma unroll
        for (int j = 0; j < 4; j++) wr[j] = *(const float4*)(wp + cc + j * 32);
        ar = *(const float2*)(ap + kbeg);
#pragma unroll
        for (int j = 0; j < 4; j++) *(float4*)&ws[0][kk][cc + j * 32] = wr[j];
        asp[0][ac + 0][at] = make_float2(ar.x, ar.x);
        asp[0][ac + 1][at] = make_float2(ar.y, ar.y);
    }
    __syncthreads();

    for (int it = 0; it < nb; ++it) {
        const int cur = it & 1;
        if (it + 1 < nb) {
            int k0 = kbeg + (it + 1) * KT;
            int r = k0 + kk;
            const float* wp = (r >= rowSw) ? Wn + wno + (long)(r - rowSw) * ldw
                                           : Wc + wco + (long)r * ldw;
#pragma unroll
            for (int j = 0; j < 4; j++) wr[j] = *(const float4*)(wp + cc + j * 32);
            ar = *(const float2*)(ap + k0);
        }
#pragma unroll
        for (int k = 0; k < KT; k++) {
            ull wv = *(const ull*)&ws[cur][k][nn * 2];
            const ulonglong2* av = (const ulonglong2*)&asp[cur][k][tt * 8];
            ulonglong2 a01 = av[0], a23 = av[1], a45 = av[2], a67 = av[3];
            fma2(acc[0], a01.x, wv); fma2(acc[1], a01.y, wv);
            fma2(acc[2], a23.x, wv); fma2(acc[3], a23.y, wv);
            fma2(acc[4], a45.x, wv); fma2(acc[5], a45.y, wv);
            fma2(acc[6], a67.x, wv); fma2(acc[7], a67.y, wv);
        }
        if (it + 1 < nb) {
            const int nxt = cur ^ 1;
#pragma unroll
            for (int j = 0; j < 4; j++) *(float4*)&ws[nxt][kk][cc + j * 32] = wr[j];
            asp[nxt][ac + 0][at] = make_float2(ar.x, ar.x);
            asp[nxt][ac + 1][at] = make_float2(ar.y, ar.y);
        }
        __syncthreads();
    }

    float* Ob = O + (long)b * sO;
#pragma unroll
    for (int i = 0; i < 8; i++) {
        int t = tt * 8 + i;
        int n = nn * 2;
        float2 v = up2(acc[i]);
        float* dst = Ob + (long)t * ldo + n;
        atomicAdd(dst + 0, v.x);
        atomicAdd(dst + 1, v.y);
    }
}

// ---------------- per-head rmsnorm + RoPE for q/k, and new_v copy ----------------
__global__ void qk_norm_rope(float* __restrict__ q, float* __restrict__ k,
                             const float* __restrict__ v,
                             const float* __restrict__ qw, const float* __restrict__ kw,
                             const float* __restrict__ cosr, const float* __restrict__ sinr,
                             float* __restrict__ outk, float* __restrict__ outv) {
    int t = blockIdx.x;
    int hh = blockIdx.y;
    int d = threadIdx.x;

    if (hh >= 40) {
        int h = hh - 40;
        outv[(size_t)(h * T_NEW + t) * HD + d] = v[(size_t)t * (NKV * HD) + h * HD + d];
        return;
    }

    __shared__ float sv[HD];
    __shared__ float red[4];
    float* row; const float* w;
    if (hh < 32) { row = q + (size_t)t * (NH * HD) + hh * HD; w = qw; }
    else         { row = k + (size_t)t * (NKV * HD) + (hh - 32) * HD; w = kw; }

    float val = row[d];
    float s = val * val;
    for (int o = 16; o > 0; o >>= 1) s += __shfl_xor_sync(0xffffffffu, s, o);
    if ((d & 31) == 0) red[d >> 5] = s;
    __syncthreads();
    float tot = red[0] + red[1] + red[2] + red[3];
    float r = rsqrtf(tot / 128.f + RMS_EPS);
    float xn = val * r * w[d];
    sv[d] = xn;
    __syncthreads();
    float rot = (d < 64) ? -sv[d + 64] : sv[d - 64];
    float o = xn * cosr[t * HD + d] + rot * sinr[t * HD + d];
    row[d] = o;
    if (hh >= 32) {
        int h = hh - 32;
        outk[(size_t)(h * T_NEW + t) * HD + d] = o;
    }
}

// ---------------- row softmax over TFULL ----------------
__global__ void softmax_rows(float* __restrict__ s) {
    int row = blockIdx.x;
    float* p = s + (size_t)row * TFULL;
    __shared__ float red[8];
    int tid = threadIdx.x;
    float m = -3.4e38f;
    for (int i = tid; i < TFULL; i += 256) m = fmaxf(m, p[i]);
    for (int o = 16; o > 0; o >>= 1) m = fmaxf(m, __shfl_xor_sync(0xffffffffu, m, o));
    if ((tid & 31) == 0) red[tid >> 5] = m;
    __syncthreads();
    float mm = red[0];
#pragma unroll
    for (int i = 1; i < 8; i++) mm = fmaxf(mm, red[i]);
    __syncthreads();
    float sum = 0.f;
    for (int i = tid; i < TFULL; i += 256) {
        float e = expf(p[i] - mm);
        p[i] = e;
        sum += e;
    }
    for (int o = 16; o > 0; o >>= 1) sum += __shfl_xor_sync(0xffffffffu, sum, o);
    if ((tid & 31) == 0) red[tid >> 5] = sum;
    __syncthreads();
    float tot = 0.f;
#pragma unroll
    for (int i = 0; i < 8; i++) tot += red[i];
    float inv = 1.f / tot;
    for (int i = tid; i < TFULL; i += 256) p[i] *= inv;
}

// ---------------- silu * up ----------------
__global__ void silu_mul_k(const float* __restrict__ g, const float* __restrict__ u,
                           float* __restrict__ o, int n) {
    int i = blockIdx.x * 256 + threadIdx.x;
    if (i < n) {
        float x = g[i];
        o[i] = (x / (1.f + expf(-x))) * u[i];
    }
}

static float* sym(const void* s) {
    void* p = nullptr;
    cudaGetSymbolAddress(&p, s);
    return (float*)p;
}

extern "C" void kernel_launch(void* const* d_in, const int* in_sizes, int n_in,
                              void* d_out, int out_size) {
    const float* x       = (const float*)d_in[0];
    const float* cos_q   = (const float*)d_in[1];
    const float* sin_q   = (const float*)d_in[2];
    const float* cache_k = (const float*)d_in[5];
    const float* cache_v = (const float*)d_in[6];
    const float* cmask   = (const float*)d_in[7];
    const float* ln1w    = (const float*)d_in[8];
    const float* ln2w    = (const float*)d_in[9];
    const float* qnw     = (const float*)d_in[10];
    const float* knw     = (const float*)d_in[11];
    const float* qw      = (const float*)d_in[12];
    const float* kw      = (const float*)d_in[13];
    const float* vw      = (const float*)d_in[14];
    const float* ow      = (const float*)d_in[15];
    const float* gw      = (const float*)d_in[16];
    const float* uw      = (const float*)d_in[17];
    const float* dw      = (const float*)d_in[18];
    float* out = (float*)d_out;
    float* out_k = out + T_NEW * HIDDEN;
    float* out_v = out_k + NKV * T_NEW * HD;

    static float *p_y = nullptr, *p_q, *p_k, *p_v, *p_scores, *p_attnout,
                 *p_h, *p_y2, *p_gate, *p_up, *p_mid;
    if (!p_y) {
        p_y = sym(g_y); p_q = sym(g_q); p_k = sym(g_k); p_v = sym(g_v);
        p_scores = sym(g_scores); p_attnout = sym(g_attnout);
        p_h = sym(g_h); p_y2 = sym(g_y2); p_gate = sym(g_gate); p_up = sym(g_up);
        p_mid = sym(g_mid);
    }

    const float scale = 0.08838834764831845f; // 1/sqrt(128)
    const int BIG = 1 << 30;

    // 0) zero atomic targets; seed h = x
    zero_scratch<<<(T_NEW * INTER + 255) / 256, 256>>>(x);

    // 1) y = rmsnorm(x) * ln1
    rmsnorm16<<<T_NEW, 256>>>(x, ln1w, p_y, nullptr, HIDDEN);

    // 2) fused QKV projection (tf32 mma): q [0,4096), k [4096,5120), v [5120,6144)
    mmaProj<<<dim3(24, 1, 8), 256>>>(p_y,
        qw, kw, vw, p_q, p_k, p_v,
        NH * HD, NKV * HD, NKV * HD,
        4096, 5120, HIDDEN, 320);

    // 3) per-head q/k rmsnorm + RoPE; writes new_k/new_v into d_out
    qk_norm_rope<<<dim3(T_NEW, 48), 128>>>(p_q, p_k, p_v, qnw, knw, cos_q, sin_q,
                                           out_k, out_v);

    // 4) scores = (q @ K^T)*scale + mask (fp32 scalar; K rows cache/new split)
    gemmA<<<dim3(16, NH, 1), 128>>>(
        p_q, NH * HD, HD,
        cache_k, (long)TC * HD, 4, HD,
        out_k, (long)T_NEW * HD, TC,
        HD,
        p_scores, TFULL, (long)T_NEW * TFULL,
        scale, cmask, TFULL);

    // 5) softmax
    softmax_rows<<<NH * T_NEW, 256>>>(p_scores);

    // 6) attn_out = P @ V (fp32 scalar, split-K over time, atomic)
    gemmB<<<dim3(1, NH, 16), 128>>>(
        p_scores, TFULL, (long)T_NEW * TFULL,
        cache_v, (long)TC * HD, 4, HD,
        out_v, (long)T_NEW * HD, TC,
        TFULL, 256,
        p_attnout, NH * HD, HD);

    // 7) O projection (tf32 mma) accumulates into h (pre-seeded with x)
    mmaProj<<<dim3(10, 1, 16), 256>>>(p_attnout,
        ow, ow, ow, p_h, p_h, p_h,
        HIDDEN, HIDDEN, HIDDEN,
        BIG, BIG, NH * HD, 256);

    // 8) y2 = rmsnorm(h) * ln2; also copy h -> out (residual seed for down-proj)
    rmsnorm16<<<T_NEW, 256>>>(p_h, ln2w, p_y2, out, HIDDEN);

    // 9) fused gate/up (tf32 mma): gate [0,9728), up [9728,19456)
    mmaProj<<<dim3(76, 1, 8), 256>>>(p_y2,
        gw, uw, uw, p_gate, p_up, p_up,
        INTER, INTER, INTER,
        INTER, BIG, HIDDEN, 320);

    // 10) mid = silu(gate) * up
    silu_mul_k<<<(T_NEW * INTER + 255) / 256, 256>>>(p_gate, p_up, p_mid, T_NEW * INTER);

    // 11) down projection (tf32 mma) accumulates into out (pre-seeded with h)
    mmaProj<<<dim3(10, 1, 16), 256>>>(p_mid,
        dw, dw, dw, out, out, out,
        HIDDEN, HIDDEN, HIDDEN,
        BIG, BIG, INTER, 608);
}

// round 10
// speedup vs baseline: 1.9534x; 1.0335x over previous
#include <cuda_runtime.h>
#include <cuda_bf16.h>
#include <math.h>
#include <stdint.h>

// ---------------- problem constants ----------------
#define T_NEW 16
#define HIDDEN 2560
#define INTER 9728
#define NH 32
#define NKV 8
#define HD 128
#define TC 4080
#define TFULL 4096
#define RMS_EPS 1e-6f
#define KT 16

typedef unsigned long long ull;

// ---------------- scratch (device globals, no allocs) ----------------
__device__ float g_y[T_NEW * HIDDEN];
__device__ float g_q[T_NEW * NH * HD];
__device__ float g_k[T_NEW * NKV * HD];
__device__ float g_v[T_NEW * NKV * HD];
__device__ float g_scores[NH * T_NEW * TFULL];
__device__ float g_attnout[T_NEW * NH * HD];
__device__ float g_h[T_NEW * HIDDEN];
__device__ float g_y2[T_NEW * HIDDEN];
__device__ float g_gate[T_NEW * INTER];
__device__ float g_up[T_NEW * INTER];
__device__ float g_mid[T_NEW * INTER];

// ---------------- packed f32x2 helpers (scalar attention path) ----------------
__device__ __forceinline__ void fma2(ull& d, ull a, ull b) {
    asm("fma.rn.f32x2 %0, %1, %2, %0;" : "+l"(d) : "l"(a), "l"(b));
}
__device__ __forceinline__ float2 up2(ull v) {
    float2 f;
    asm("mov.b64 {%0, %1}, %2;" : "=f"(f.x), "=f"(f.y) : "l"(v));
    return f;
}

// ---------------- tf32 mma.sync helpers (portable, sm_80+) ----------------
__device__ __forceinline__ uint32_t tf(float x) {
    uint32_t r;
    asm("cvt.rna.tf32.f32 %0, %1;" : "=r"(r) : "f"(x));
    return r;
}
__device__ __forceinline__ void mma16n8k8(float* c,
                                          uint32_t a0, uint32_t a1, uint32_t a2, uint32_t a3,
                                          uint32_t b0, uint32_t b1) {
    asm volatile(
        "mma.sync.aligned.m16n8k8.row.col.f32.tf32.tf32.f32 "
        "{%0,%1,%2,%3}, {%4,%5,%6,%7}, {%8,%9}, {%0,%1,%2,%3};"
        : "+f"(c[0]), "+f"(c[1]), "+f"(c[2]), "+f"(c[3])
        : "r"(a0), "r"(a1), "r"(a2), "r"(a3), "r"(b0), "r"(b1));
}

// ---------------- zero atomic targets + seed h with x ----------------
__global__ void zero_scratch(const float* __restrict__ x) {
    int i = blockIdx.x * 256 + threadIdx.x;
    if (i < T_NEW * INTER) { g_gate[i] = 0.f; g_up[i] = 0.f; }
    if (i < T_NEW * NH * HD) { g_q[i] = 0.f; g_attnout[i] = 0.f; }
    if (i < T_NEW * NKV * HD) { g_k[i] = 0.f; g_v[i] = 0.f; }
    if (i < T_NEW * HIDDEN)  { g_h[i] = x[i]; }
}

// ---------------- rmsnorm per token (optional raw copy to cp) ----------------
__global__ void rmsnorm16(const float* __restrict__ x, const float* __restrict__ w,
                          float* __restrict__ y, float* __restrict__ cp, int D) {
    int t = blockIdx.x;
    const float* row = x + (size_t)t * D;
    float s = 0.f;
    for (int i = threadIdx.x; i < D; i += 256) { float v = row[i]; s += v * v; }
    __shared__ float red[8];
    for (int o = 16; o > 0; o >>= 1) s += __shfl_xor_sync(0xffffffffu, s, o);
    if ((threadIdx.x & 31) == 0) red[threadIdx.x >> 5] = s;
    __syncthreads();
    float tot = 0.f;
#pragma unroll
    for (int i = 0; i < 8; i++) tot += red[i];
    float r = rsqrtf(tot / (float)D + RMS_EPS);
    for (int i = threadIdx.x; i < D; i += 256) {
        float v = row[i];
        y[(size_t)t * D + i] = v * r * w[i];
        if (cp) cp[(size_t)t * D + i] = v;
    }
}

// =============================================================
// mmaProj v2: smem-staged tf32 mma.sync GEMM.
// out[t][n] += sum_k act[t][k] * W[n][k]
// Block 256 thr: tile = 256 weight rows x 16 tokens, K-chunk 32.
// Coalesced float4 W loads -> tf32 cvt at STS -> conflict-free LDS
// fragments (row pad 36 words) -> 4 HMMA per warp per k8-step.
// Up to 3 weight regions (fused QKV / gate+up); split-K atomics.
// =============================================================
#define PROW 36
__global__ void __launch_bounds__(256)
mmaProj(const float* __restrict__ act,
        const float* __restrict__ W0, const float* __restrict__ W1,
        const float* __restrict__ W2,
        float* __restrict__ O0, float* __restrict__ O1, float* __restrict__ O2,
        int ldo0, int ldo1, int ldo2, int nb1, int nb2,
        int K, int klen) {
    __shared__ uint32_t sw[256][PROW];
    __shared__ uint32_t sa[16][PROW];

    const int tid = threadIdx.x;
    const int wid = tid >> 5;
    const int lane = tid & 31;
    const int g = blockIdx.x * 256;

    const float* W; float* O; int ldo, nloc;
    if (g >= nb2)      { W = W2; O = O2; ldo = ldo2; nloc = g - nb2; }
    else if (g >= nb1) { W = W1; O = O1; ldo = ldo1; nloc = g - nb1; }
    else               { W = W0; O = O0; ldo = ldo0; nloc = g; }

    const int kbeg = blockIdx.z * klen;

    // staging indices: 2048 float4 over 256 rows x 32 cols; 8 per thread
    const int srow = tid >> 3;          // also used for act staging row (tid<128)
    const int scol = (tid & 7) * 4;

    // fragment indices
    const int kq = lane & 3;
    const int rsel = lane >> 2;
    const int rw = wid * 32;            // 32 rows per warp

    float c[4][4];
#pragma unroll
    for (int j = 0; j < 4; j++)
#pragma unroll
        for (int i = 0; i < 4; i++) c[j][i] = 0.f;

    const int nchunks = klen >> 5;
    for (int ch = 0; ch < nchunks; ++ch) {
        const int k0 = kbeg + ch * 32;
        // gather (issued before barrier; overlaps other warps' compute)
        float4 wv[8];
#pragma unroll
        for (int i = 0; i < 8; i++) {
            int f = tid + i * 256;
            int r = f >> 3, cc = (f & 7) * 4;
            wv[i] = *(const float4*)(W + (long)(nloc + r) * K + k0 + cc);
        }
        float4 av = make_float4(0.f, 0.f, 0.f, 0.f);
        if (tid < 128)
            av = *(const float4*)(act + (long)srow * K + k0 + scol);

        __syncthreads();   // previous chunk's LDS complete
#pragma unroll
        for (int i = 0; i < 8; i++) {
            int f = tid + i * 256;
            int r = f >> 3, cc = (f & 7) * 4;
            uint4 t = make_uint4(tf(wv[i].x), tf(wv[i].y), tf(wv[i].z), tf(wv[i].w));
            *(uint4*)&sw[r][cc] = t;
        }
        if (tid < 128) {
            uint4 t = make_uint4(tf(av.x), tf(av.y), tf(av.z), tf(av.w));
            *(uint4*)&sa[srow][scol] = t;
        }
        __syncthreads();

#pragma unroll
        for (int s = 0; s < 4; s++) {
            const int s8 = s * 8;
            uint32_t a0 = sa[rsel][s8 + kq];
            uint32_t a1 = sa[rsel + 8][s8 + kq];
            uint32_t a2 = sa[rsel][s8 + kq + 4];
            uint32_t a3 = sa[rsel + 8][s8 + kq + 4];
#pragma unroll
            for (int j = 0; j < 4; j++) {
                uint32_t b0 = sw[rw + j * 8 + rsel][s8 + kq];
                uint32_t b1 = sw[rw + j * 8 + rsel][s8 + kq + 4];
                mma16n8k8(c[j], a0, a1, a2, a3, b0, b1);
            }
        }
    }

    const int t0 = lane >> 2, t1 = t0 + 8;
    const int ncol = (lane & 3) * 2;
#pragma unroll
    for (int j = 0; j < 4; j++) {
        int n = nloc + rw + j * 8 + ncol;
        atomicAdd(O + (long)t0 * ldo + n,     c[j][0]);
        atomicAdd(O + (long)t0 * ldo + n + 1, c[j][1]);
        atomicAdd(O + (long)t1 * ldo + n,     c[j][2]);
        atomicAdd(O + (long)t1 * ldo + n + 1, c[j][3]);
    }
}

// =============================================================
// gemmA (fp32 scalar): scores GEMM with cache/new weight-row split + mask.
// =============================================================
__global__ void __launch_bounds__(128)
gemmA(const float* __restrict__ A, int lda, long sA,
      const float* __restrict__ Wc, long sWc, int wdiv, int ldw,
      const float* __restrict__ Wn, long sWn, int rowSw,
      int K,
      float* __restrict__ O, int ldo, long sO,
      float scale, const float* __restrict__ maskAdd, int maskld) {
    __shared__ __align__(16) float ws[2][KT][260];
    __shared__ __align__(16) float2 asp[2][KT][16];

    const int tid = threadIdx.x;
    const int b = blockIdx.y;
    const int nbase = blockIdx.x * 256;

    const float* Ab = A + (long)b * sA;
    const int r0 = nbase + tid, r1 = r0 + 128;
    const float* wp0 = (r0 >= rowSw)
        ? Wn + (long)(b / wdiv) * sWn + (long)(r0 - rowSw) * ldw
        : Wc + (long)(b / wdiv) * sWc + (long)r0 * ldw;
    const float* wp1 = (r1 >= rowSw)
        ? Wn + (long)(b / wdiv) * sWn + (long)(r1 - rowSw) * ldw
        : Wc + (long)(b / wdiv) * sWc + (long)r1 * ldw;

    const int at = tid >> 3;
    const int ac = (tid & 7) * 2;
    const float* ap = Ab + (long)at * lda + ac;

    const int tt = tid >> 6;
    const int nn = tid & 63;

    ull acc[8][2];
#pragma unroll
    for (int i = 0; i < 8; i++) { acc[i][0] = 0ULL; acc[i][1] = 0ULL; }

    float4 wr0[4], wr1[4];
    float2 ar;
    const int nb = K >> 4;

#pragma unroll
    for (int j = 0; j < 4; j++) {
        wr0[j] = *(const float4*)(wp0 + j * 4);
        wr1[j] = *(const float4*)(wp1 + j * 4);
    }
    ar = *(const float2*)(ap);
#pragma unroll
    for (int j = 0; j < 4; j++) {
        ws[0][j * 4 + 0][tid] = wr0[j].x; ws[0][j * 4 + 1][tid] = wr0[j].y;
        ws[0][j * 4 + 2][tid] = wr0[j].z; ws[0][j * 4 + 3][tid] = wr0[j].w;
        ws[0][j * 4 + 0][tid + 128] = wr1[j].x; ws[0][j * 4 + 1][tid + 128] = wr1[j].y;
        ws[0][j * 4 + 2][tid + 128] = wr1[j].z; ws[0][j * 4 + 3][tid + 128] = wr1[j].w;
    }
    asp[0][ac + 0][at] = make_float2(ar.x, ar.x);
    asp[0][ac + 1][at] = make_float2(ar.y, ar.y);
    __syncthreads();

    for (int it = 0; it < nb; ++it) {
        const int cur = it & 1;
        if (it + 1 < nb) {
            int k0 = (it + 1) * KT;
#pragma unroll
            for (int j = 0; j < 4; j++) {
                wr0[j] = *(const float4*)(wp0 + k0 + j * 4);
                wr1[j] = *(const float4*)(wp1 + k0 + j * 4);
            }
            ar = *(const float2*)(ap + k0);
        }
#pragma unroll
        for (int k = 0; k < KT; k++) {
            ulonglong2 w2 = *(const ulonglong2*)&ws[cur][k][nn * 4];
            const ulonglong2* av = (const ulonglong2*)&asp[cur][k][tt * 8];
            ulonglong2 a01 = av[0], a23 = av[1], a45 = av[2], a67 = av[3];
            fma2(acc[0][0], a01.x, w2.x); fma2(acc[0][1], a01.x, w2.y);
            fma2(acc[1][0], a01.y, w2.x); fma2(acc[1][1], a01.y, w2.y);
            fma2(acc[2][0], a23.x, w2.x); fma2(acc[2][1], a23.x, w2.y);
            fma2(acc[3][0], a23.y, w2.x); fma2(acc[3][1], a23.y, w2.y);
            fma2(acc[4][0], a45.x, w2.x); fma2(acc[4][1], a45.x, w2.y);
            fma2(acc[5][0], a45.y, w2.x); fma2(acc[5][1], a45.y, w2.y);
            fma2(acc[6][0], a67.x, w2.x); fma2(acc[6][1], a67.x, w2.y);
            fma2(acc[7][0], a67.y, w2.x); fma2(acc[7][1], a67.y, w2.y);
        }
        if (it + 1 < nb) {
            const int nxt = cur ^ 1;
#pragma unroll
            for (int j = 0; j < 4; j++) {
                ws[nxt][j * 4 + 0][tid] = wr0[j].x; ws[nxt][j * 4 + 1][tid] = wr0[j].y;
                ws[nxt][j * 4 + 2][tid] = wr0[j].z; ws[nxt][j * 4 + 3][tid] = wr0[j].w;
                ws[nxt][j * 4 + 0][tid + 128] = wr1[j].x; ws[nxt][j * 4 + 1][tid + 128] = wr1[j].y;
                ws[nxt][j * 4 + 2][tid + 128] = wr1[j].z; ws[nxt][j * 4 + 3][tid + 128] = wr1[j].w;
            }
            asp[nxt][ac + 0][at] = make_float2(ar.x, ar.x);
            asp[nxt][ac + 1][at] = make_float2(ar.y, ar.y);
        }
        __syncthreads();
    }

    float* Ob = O + (long)b * sO;
#pragma unroll
    for (int i = 0; i < 8; i++) {
        int t = tt * 8 + i;
        int n = nbase + nn * 4;
        float2 v0 = up2(acc[i][0]);
        float2 v1 = up2(acc[i][1]);
        float4 v = make_float4(v0.x * scale, v0.y * scale, v1.x * scale, v1.y * scale);
        const float* m = maskAdd + (long)t * maskld + n;
        v.x += m[0]; v.y += m[1]; v.z += m[2]; v.w += m[3];
        *(float4*)(Ob + (long)t * ldo + n) = v;
    }
}

// =============================================================
// gemmB (fp32 scalar): PV GEMM with cache/new V-row split, split-K atomic.
// =============================================================
__global__ void __launch_bounds__(128)
gemmB(const float* __restrict__ A, int lda, long sA,
      const float* __restrict__ Wc, long sWc, int wdiv, int ldw,
      const float* __restrict__ Wn, long sWn, int rowSw,
      int K, int klen,
      float* __restrict__ O, int ldo, long sO) {
    __shared__ __align__(16) float ws[2][KT][132];
    __shared__ __align__(16) float2 asp[2][KT][16];

    const int tid = threadIdx.x;
    const int b = blockIdx.y;
    const int kbeg = blockIdx.z * klen;
    int kend = kbeg + klen; if (kend > K) kend = K;
    if (kbeg >= kend) return;

    const float* Ab = A + (long)b * sA;
    const long wco = (long)(b / wdiv) * sWc;
    const long wno = (long)(b / wdiv) * sWn;

    const int kk = tid >> 3;
    const int cc = (tid & 7) * 4;

    const int at = tid >> 3;
    const int ac = (tid & 7) * 2;
    const float* ap = Ab + (long)at * lda + ac;

    const int tt = tid >> 6;
    const int nn = tid & 63;

    ull acc[8];
#pragma unroll
    for (int i = 0; i < 8; i++) acc[i] = 0ULL;

    float4 wr[4];
    float2 ar;
    const int nb = (kend - kbeg) >> 4;

    {
        int r = kbeg + kk;
        const float* wp = (r >= rowSw) ? Wn + wno + (long)(r - rowSw) * ldw
                                       : Wc + wco + (long)r * ldw;
#pragma unroll
        for (int j = 0; j < 4; j++) wr[j] = *(const float4*)(wp + cc + j * 32);
        ar = *(const float2*)(ap + kbeg);
#pragma unroll
        for (int j = 0; j < 4; j++) *(float4*)&ws[0][kk][cc + j * 32] = wr[j];
        asp[0][ac + 0][at] = make_float2(ar.x, ar.x);
        asp[0][ac + 1][at] = make_float2(ar.y, ar.y);
    }
    __syncthreads();

    for (int it = 0; it < nb; ++it) {
        const int cur = it & 1;
        if (it + 1 < nb) {
            int k0 = kbeg + (it + 1) * KT;
            int r = k0 + kk;
            const float* wp = (r >= rowSw) ? Wn + wno + (long)(r - rowSw) * ldw
                                           : Wc + wco + (long)r * ldw;
#pragma unroll
            for (int j = 0; j < 4; j++) wr[j] = *(const float4*)(wp + cc + j * 32);
            ar = *(const float2*)(ap + k0);
        }
#pragma unroll
        for (int k = 0; k < KT; k++) {
            ull wv = *(const ull*)&ws[cur][k][nn * 2];
            const ulonglong2* av = (const ulonglong2*)&asp[cur][k][tt * 8];
            ulonglong2 a01 = av[0], a23 = av[1], a45 = av[2], a67 = av[3];
            fma2(acc[0], a01.x, wv); fma2(acc[1], a01.y, wv);
            fma2(acc[2], a23.x, wv); fma2(acc[3], a23.y, wv);
            fma2(acc[4], a45.x, wv); fma2(acc[5], a45.y, wv);
            fma2(acc[6], a67.x, wv); fma2(acc[7], a67.y, wv);
        }
        if (it + 1 < nb) {
            const int nxt = cur ^ 1;
#pragma unroll
            for (int j = 0; j < 4; j++) *(float4*)&ws[nxt][kk][cc + j * 32] = wr[j];
            asp[nxt][ac + 0][at] = make_float2(ar.x, ar.x);
            asp[nxt][ac + 1][at] = make_float2(ar.y, ar.y);
        }
        __syncthreads();
    }

    float* Ob = O + (long)b * sO;
#pragma unroll
    for (int i = 0; i < 8; i++) {
        int t = tt * 8 + i;
        int n = nn * 2;
        float2 v = up2(acc[i]);
        float* dst = Ob + (long)t * ldo + n;
        atomicAdd(dst + 0, v.x);
        atomicAdd(dst + 1, v.y);
    }
}

// ---------------- per-head rmsnorm + RoPE for q/k, and new_v copy ----------------
__global__ void qk_norm_rope(float* __restrict__ q, float* __restrict__ k,
                             const float* __restrict__ v,
                             const float* __restrict__ qw, const float* __restrict__ kw,
                             const float* __restrict__ cosr, const float* __restrict__ sinr,
                             float* __restrict__ outk, float* __restrict__ outv) {
    int t = blockIdx.x;
    int hh = blockIdx.y;
    int d = threadIdx.x;

    if (hh >= 40) {
        int h = hh - 40;
        outv[(size_t)(h * T_NEW + t) * HD + d] = v[(size_t)t * (NKV * HD) + h * HD + d];
        return;
    }

    __shared__ float sv[HD];
    __shared__ float red[4];
    float* row; const float* w;
    if (hh < 32) { row = q + (size_t)t * (NH * HD) + hh * HD; w = qw; }
    else         { row = k + (size_t)t * (NKV * HD) + (hh - 32) * HD; w = kw; }

    float val = row[d];
    float s = val * val;
    for (int o = 16; o > 0; o >>= 1) s += __shfl_xor_sync(0xffffffffu, s, o);
    if ((d & 31) == 0) red[d >> 5] = s;
    __syncthreads();
    float tot = red[0] + red[1] + red[2] + red[3];
    float r = rsqrtf(tot / 128.f + RMS_EPS);
    float xn = val * r * w[d];
    sv[d] = xn;
    __syncthreads();
    float rot = (d < 64) ? -sv[d + 64] : sv[d - 64];
    float o = xn * cosr[t * HD + d] + rot * sinr[t * HD + d];
    row[d] = o;
    if (hh >= 32) {
        int h = hh - 32;
        outk[(size_t)(h * T_NEW + t) * HD + d] = o;
    }
}

// ---------------- row softmax over TFULL ----------------
__global__ void softmax_rows(float* __restrict__ s) {
    int row = blockIdx.x;
    float* p = s + (size_t)row * TFULL;
    __shared__ float red[8];
    int tid = threadIdx.x;
    float m = -3.4e38f;
    for (int i = tid; i < TFULL; i += 256) m = fmaxf(m, p[i]);
    for (int o = 16; o > 0; o >>= 1) m = fmaxf(m, __shfl_xor_sync(0xffffffffu, m, o));
    if ((tid & 31) == 0) red[tid >> 5] = m;
    __syncthreads();
    float mm = red[0];
#pragma unroll
    for (int i = 1; i < 8; i++) mm = fmaxf(mm, red[i]);
    __syncthreads();
    float sum = 0.f;
    for (int i = tid; i < TFULL; i += 256) {
        float e = expf(p[i] - mm);
        p[i] = e;
        sum += e;
    }
    for (int o = 16; o > 0; o >>= 1) sum += __shfl_xor_sync(0xffffffffu, sum, o);
    if ((tid & 31) == 0) red[tid >> 5] = sum;
    __syncthreads();
    float tot = 0.f;
#pragma unroll
    for (int i = 0; i < 8; i++) tot += red[i];
    float inv = 1.f / tot;
    for (int i = tid; i < TFULL; i += 256) p[i] *= inv;
}

// ---------------- silu * up ----------------
__global__ void silu_mul_k(const float* __restrict__ g, const float* __restrict__ u,
                           float* __restrict__ o, int n) {
    int i = blockIdx.x * 256 + threadIdx.x;
    if (i < n) {
        float x = g[i];
        o[i] = (x / (1.f + expf(-x))) * u[i];
    }
}

static float* sym(const void* s) {
    void* p = nullptr;
    cudaGetSymbolAddress(&p, s);
    return (float*)p;
}

extern "C" void kernel_launch(void* const* d_in, const int* in_sizes, int n_in,
                              void* d_out, int out_size) {
    const float* x       = (const float*)d_in[0];
    const float* cos_q   = (const float*)d_in[1];
    const float* sin_q   = (const float*)d_in[2];
    const float* cache_k = (const float*)d_in[5];
    const float* cache_v = (const float*)d_in[6];
    const float* cmask   = (const float*)d_in[7];
    const float* ln1w    = (const float*)d_in[8];
    const float* ln2w    = (const float*)d_in[9];
    const float* qnw     = (const float*)d_in[10];
    const float* knw     = (const float*)d_in[11];
    const float* qw      = (const float*)d_in[12];
    const float* kw      = (const float*)d_in[13];
    const float* vw      = (const float*)d_in[14];
    const float* ow      = (const float*)d_in[15];
    const float* gw      = (const float*)d_in[16];
    const float* uw      = (const float*)d_in[17];
    const float* dw      = (const float*)d_in[18];
    float* out = (float*)d_out;
    float* out_k = out + T_NEW * HIDDEN;
    float* out_v = out_k + NKV * T_NEW * HD;

    static float *p_y = nullptr, *p_q, *p_k, *p_v, *p_scores, *p_attnout,
                 *p_h, *p_y2, *p_gate, *p_up, *p_mid;
    if (!p_y) {
        p_y = sym(g_y); p_q = sym(g_q); p_k = sym(g_k); p_v = sym(g_v);
        p_scores = sym(g_scores); p_attnout = sym(g_attnout);
        p_h = sym(g_h); p_y2 = sym(g_y2); p_gate = sym(g_gate); p_up = sym(g_up);
        p_mid = sym(g_mid);
    }

    const float scale = 0.08838834764831845f; // 1/sqrt(128)
    const int BIG = 1 << 30;

    // 0) zero atomic targets; seed h = x
    zero_scratch<<<(T_NEW * INTER + 255) / 256, 256>>>(x);

    // 1) y = rmsnorm(x) * ln1
    rmsnorm16<<<T_NEW, 256>>>(x, ln1w, p_y, nullptr, HIDDEN);

    // 2) fused QKV projection (tf32 mma, 256-row tiles):
    //    q [0,4096), k [4096,5120), v [5120,6144); K=2560, z=16 -> klen 160
    mmaProj<<<dim3(24, 1, 16), 256>>>(p_y,
        qw, kw, vw, p_q, p_k, p_v,
        NH * HD, NKV * HD, NKV * HD,
        4096, 5120, HIDDEN, 160);

    // 3) per-head q/k rmsnorm + RoPE; writes new_k/new_v into d_out
    qk_norm_rope<<<dim3(T_NEW, 48), 128>>>(p_q, p_k, p_v, qnw, knw, cos_q, sin_q,
                                           out_k, out_v);

    // 4) scores = (q @ K^T)*scale + mask (fp32 scalar; K rows cache/new split)
    gemmA<<<dim3(16, NH, 1), 128>>>(
        p_q, NH * HD, HD,
        cache_k, (long)TC * HD, 4, HD,
        out_k, (long)T_NEW * HD, TC,
        HD,
        p_scores, TFULL, (long)T_NEW * TFULL,
        scale, cmask, TFULL);

    // 5) softmax
    softmax_rows<<<NH * T_NEW, 256>>>(p_scores);

    // 6) attn_out = P @ V (fp32 scalar, split-K over time, atomic)
    gemmB<<<dim3(1, NH, 16), 128>>>(
        p_scores, TFULL, (long)T_NEW * TFULL,
        cache_v, (long)TC * HD, 4, HD,
        out_v, (long)T_NEW * HD, TC,
        TFULL, 256,
        p_attnout, NH * HD, HD);

    // 7) O projection (tf32 mma): 2560 rows -> 10 tiles; K=4096, z=32 -> klen 128
    mmaProj<<<dim3(10, 1, 32), 256>>>(p_attnout,
        ow, ow, ow, p_h, p_h, p_h,
        HIDDEN, HIDDEN, HIDDEN,
        BIG, BIG, NH * HD, 128);

    // 8) y2 = rmsnorm(h) * ln2; also copy h -> out (residual seed for down-proj)
    rmsnorm16<<<T_NEW, 256>>>(p_h, ln2w, p_y2, out, HIDDEN);

    // 9) fused gate/up (tf32 mma): 19456 rows -> 76 tiles; K=2560, z=8 -> klen 320
    mmaProj<<<dim3(76, 1, 8), 256>>>(p_y2,
        gw, uw, uw, p_gate, p_up, p_up,
        INTER, INTER, INTER,
        INTER, BIG, HIDDEN, 320);

    // 10) mid = silu(gate) * up
    silu_mul_k<<<(T_NEW * INTER + 255) / 256, 256>>>(p_gate, p_up, p_mid, T_NEW * INTER);

    // 11) down projection (tf32 mma): 2560 rows -> 10 tiles; K=9728, z=38 -> klen 256
    mmaProj<<<dim3(10, 1, 38), 256>>>(p_mid,
        dw, dw, dw, out, out, out,
        HIDDEN, HIDDEN, HIDDEN,
        BIG, BIG, INTER, 256);
}

// round 11
// speedup vs baseline: 3.0531x; 1.5629x over previous
#include <cuda_runtime.h>
#include <cuda_bf16.h>
#include <math.h>
#include <stdint.h>

// ---------------- problem constants ----------------
#define T_NEW 16
#define HIDDEN 2560
#define INTER 9728
#define NH 32
#define NKV 8
#define HD 128
#define TC 4080
#define TFULL 4096
#define RMS_EPS 1e-6f
#define PROW 36
#define VPAD 132

// ---------------- scratch (device globals, no allocs) ----------------
__device__ float g_y[T_NEW * HIDDEN];
__device__ float g_q[T_NEW * NH * HD];
__device__ float g_k[T_NEW * NKV * HD];
__device__ float g_v[T_NEW * NKV * HD];
__device__ float g_scores[NH * T_NEW * TFULL];
__device__ float g_attnout[T_NEW * NH * HD];
__device__ float g_h[T_NEW * HIDDEN];
__device__ float g_y2[T_NEW * HIDDEN];
__device__ float g_gate[T_NEW * INTER];
__device__ float g_up[T_NEW * INTER];

// ---------------- tf32 mma.sync helpers (portable, sm_80+) ----------------
__device__ __forceinline__ uint32_t tf(float x) {
    uint32_t r;
    asm("cvt.rna.tf32.f32 %0, %1;" : "=r"(r) : "f"(x));
    return r;
}
__device__ __forceinline__ void mma16n8k8(float* c,
                                          uint32_t a0, uint32_t a1, uint32_t a2, uint32_t a3,
                                          uint32_t b0, uint32_t b1) {
    asm volatile(
        "mma.sync.aligned.m16n8k8.row.col.f32.tf32.tf32.f32 "
        "{%0,%1,%2,%3}, {%4,%5,%6,%7}, {%8,%9}, {%0,%1,%2,%3};"
        : "+f"(c[0]), "+f"(c[1]), "+f"(c[2]), "+f"(c[3])
        : "r"(a0), "r"(a1), "r"(a2), "r"(a3), "r"(b0), "r"(b1));
}
__device__ __forceinline__ float silu1(float x) {
    return x / (1.f + __expf(-x));
}

// ---------------- prep: rmsnorm(x)->y (blocks 0..15) + zero/seed (rest) ----------------
__global__ void prep(const float* __restrict__ x, const float* __restrict__ w) {
    if (blockIdx.x < 16) {
        int t = blockIdx.x;
        const float* row = x + (size_t)t * HIDDEN;
        float s = 0.f;
        for (int i = threadIdx.x; i < HIDDEN; i += 256) { float v = row[i]; s += v * v; }
        __shared__ float red[8];
        for (int o = 16; o > 0; o >>= 1) s += __shfl_xor_sync(0xffffffffu, s, o);
        if ((threadIdx.x & 31) == 0) red[threadIdx.x >> 5] = s;
        __syncthreads();
        float tot = 0.f;
#pragma unroll
        for (int i = 0; i < 8; i++) tot += red[i];
        float r = rsqrtf(tot / (float)HIDDEN + RMS_EPS);
        for (int i = threadIdx.x; i < HIDDEN; i += 256)
            g_y[(size_t)t * HIDDEN + i] = row[i] * r * w[i];
    } else {
        int i = (blockIdx.x - 16) * 256 + threadIdx.x;
        if (i < T_NEW * INTER) { g_gate[i] = 0.f; g_up[i] = 0.f; }
        if (i < T_NEW * NH * HD) { g_q[i] = 0.f; g_attnout[i] = 0.f; }
        if (i < T_NEW * NKV * HD) { g_k[i] = 0.f; g_v[i] = 0.f; }
        if (i < T_NEW * HIDDEN)  { g_h[i] = x[i]; }
    }
}

// ---------------- rmsnorm per token (optional raw copy to cp) ----------------
__global__ void rmsnorm16(const float* __restrict__ x, const float* __restrict__ w,
                          float* __restrict__ y, float* __restrict__ cp, int D) {
    int t = blockIdx.x;
    const float* row = x + (size_t)t * D;
    float s = 0.f;
    for (int i = threadIdx.x; i < D; i += 256) { float v = row[i]; s += v * v; }
    __shared__ float red[8];
    for (int o = 16; o > 0; o >>= 1) s += __shfl_xor_sync(0xffffffffu, s, o);
    if ((threadIdx.x & 31) == 0) red[threadIdx.x >> 5] = s;
    __syncthreads();
    float tot = 0.f;
#pragma unroll
    for (int i = 0; i < 8; i++) tot += red[i];
    float r = rsqrtf(tot / (float)D + RMS_EPS);
    for (int i = threadIdx.x; i < D; i += 256) {
        float v = row[i];
        y[(size_t)t * D + i] = v * r * w[i];
        if (cp) cp[(size_t)t * D + i] = v;
    }
}

// =============================================================
// mmaProj: smem-staged tf32 mma.sync GEMM.
// out[t][n] += sum_k act[t][k] * W[n][k]; if act2: act := silu(act)*act2.
// Block 256 thr: 256 weight rows x 16 tokens, K-chunk 32.
// =============================================================
__global__ void __launch_bounds__(256)
mmaProj(const float* __restrict__ act, const float* __restrict__ act2,
        const float* __restrict__ W0, const float* __restrict__ W1,
        const float* __restrict__ W2,
        float* __restrict__ O0, float* __restrict__ O1, float* __restrict__ O2,
        int ldo0, int ldo1, int ldo2, int nb1, int nb2,
        int K, int klen) {
    __shared__ uint32_t sw[256][PROW];
    __shared__ uint32_t sa[16][PROW];

    const int tid = threadIdx.x;
    const int wid = tid >> 5;
    const int lane = tid & 31;
    const int g = blockIdx.x * 256;

    const float* W; float* O; int ldo, nloc;
    if (g >= nb2)      { W = W2; O = O2; ldo = ldo2; nloc = g - nb2; }
    else if (g >= nb1) { W = W1; O = O1; ldo = ldo1; nloc = g - nb1; }
    else               { W = W0; O = O0; ldo = ldo0; nloc = g; }

    const int kbeg = blockIdx.z * klen;
    const int srow = tid >> 3;
    const int scol = (tid & 7) * 4;
    const int kq = lane & 3;
    const int rsel = lane >> 2;
    const int rw = wid * 32;

    float c[4][4];
#pragma unroll
    for (int j = 0; j < 4; j++)
#pragma unroll
        for (int i = 0; i < 4; i++) c[j][i] = 0.f;

    const int nchunks = klen >> 5;
    for (int ch = 0; ch < nchunks; ++ch) {
        const int k0 = kbeg + ch * 32;
        float4 wv[8];
#pragma unroll
        for (int i = 0; i < 8; i++) {
            int f = tid + i * 256;
            int r = f >> 3, cc = (f & 7) * 4;
            wv[i] = *(const float4*)(W + (long)(nloc + r) * K + k0 + cc);
        }
        float4 av = make_float4(0.f, 0.f, 0.f, 0.f);
        if (tid < 128) {
            av = *(const float4*)(act + (long)srow * K + k0 + scol);
            if (act2) {
                float4 u = *(const float4*)(act2 + (long)srow * K + k0 + scol);
                av = make_float4(silu1(av.x) * u.x, silu1(av.y) * u.y,
                                 silu1(av.z) * u.z, silu1(av.w) * u.w);
            }
        }
        __syncthreads();
#pragma unroll
        for (int i = 0; i < 8; i++) {
            int f = tid + i * 256;
            int r = f >> 3, cc = (f & 7) * 4;
            uint4 t = make_uint4(tf(wv[i].x), tf(wv[i].y), tf(wv[i].z), tf(wv[i].w));
            *(uint4*)&sw[r][cc] = t;
        }
        if (tid < 128) {
            uint4 t = make_uint4(tf(av.x), tf(av.y), tf(av.z), tf(av.w));
            *(uint4*)&sa[srow][scol] = t;
        }
        __syncthreads();

#pragma unroll
        for (int s = 0; s < 4; s++) {
            const int s8 = s * 8;
            uint32_t a0 = sa[rsel][s8 + kq];
            uint32_t a1 = sa[rsel + 8][s8 + kq];
            uint32_t a2 = sa[rsel][s8 + kq + 4];
            uint32_t a3 = sa[rsel + 8][s8 + kq + 4];
#pragma unroll
            for (int j = 0; j < 4; j++) {
                uint32_t b0 = sw[rw + j * 8 + rsel][s8 + kq];
                uint32_t b1 = sw[rw + j * 8 + rsel][s8 + kq + 4];
                mma16n8k8(c[j], a0, a1, a2, a3, b0, b1);
            }
        }
    }

    const int t0 = lane >> 2, t1 = t0 + 8;
    const int ncol = (lane & 3) * 2;
#pragma unroll
    for (int j = 0; j < 4; j++) {
        int n = nloc + rw + j * 8 + ncol;
        atomicAdd(O + (long)t0 * ldo + n,     c[j][0]);
        atomicAdd(O + (long)t0 * ldo + n + 1, c[j][1]);
        atomicAdd(O + (long)t1 * ldo + n,     c[j][2]);
        atomicAdd(O + (long)t1 * ldo + n + 1, c[j][3]);
    }
}

// =============================================================
// scoresMMA: scores[h][t][n] = (q_h[t] . K_h[n]) * scale + mask[t][n]
// Block 256 thr: 256 key-rows x 16 q-rows, K=128 (4 chunks).
// K rows from cache (r<TC) or new K (r>=TC). Direct store.
// =============================================================
__global__ void __launch_bounds__(256)
scoresMMA(const float* __restrict__ q,
          const float* __restrict__ kc, const float* __restrict__ kn,
          const float* __restrict__ mask,
          float* __restrict__ scores, float scale) {
    __shared__ uint32_t sw[256][PROW];
    __shared__ uint32_t sa[16][PROW];

    const int tid = threadIdx.x;
    const int wid = tid >> 5;
    const int lane = tid & 31;
    const int h = blockIdx.y;
    const int kvh = h >> 2;
    const int nbase = blockIdx.x * 256;

    const int srow = tid >> 3;
    const int scol = (tid & 7) * 4;
    const int kq = lane & 3;
    const int rsel = lane >> 2;
    const int rw = wid * 32;

    const float* qh = q + h * HD;

    float c[4][4];
#pragma unroll
    for (int j = 0; j < 4; j++)
#pragma unroll
        for (int i = 0; i < 4; i++) c[j][i] = 0.f;

#pragma unroll
    for (int ch = 0; ch < 4; ++ch) {
        const int k0 = ch * 32;
        float4 wv[8];
#pragma unroll
        for (int i = 0; i < 8; i++) {
            int f = tid + i * 256;
            int r = f >> 3, cc = (f & 7) * 4;
            int rg = nbase + r;
            const float* src = (rg < TC)
                ? kc + ((long)kvh * TC + rg) * HD
                : kn + ((long)kvh * T_NEW + (rg - TC)) * HD;
            wv[i] = *(const float4*)(src + k0 + cc);
        }
        float4 av = make_float4(0.f, 0.f, 0.f, 0.f);
        if (tid < 128)
            av = *(const float4*)(qh + (long)srow * (NH * HD) + k0 + scol);
        __syncthreads();
#pragma unroll
        for (int i = 0; i < 8; i++) {
            int f = tid + i * 256;
            int r = f >> 3, cc = (f & 7) * 4;
            uint4 t = make_uint4(tf(wv[i].x), tf(wv[i].y), tf(wv[i].z), tf(wv[i].w));
            *(uint4*)&sw[r][cc] = t;
        }
        if (tid < 128) {
            uint4 t = make_uint4(tf(av.x), tf(av.y), tf(av.z), tf(av.w));
            *(uint4*)&sa[srow][scol] = t;
        }
        __syncthreads();

#pragma unroll
        for (int s = 0; s < 4; s++) {
            const int s8 = s * 8;
            uint32_t a0 = sa[rsel][s8 + kq];
            uint32_t a1 = sa[rsel + 8][s8 + kq];
            uint32_t a2 = sa[rsel][s8 + kq + 4];
            uint32_t a3 = sa[rsel + 8][s8 + kq + 4];
#pragma unroll
            for (int j = 0; j < 4; j++) {
                uint32_t b0 = sw[rw + j * 8 + rsel][s8 + kq];
                uint32_t b1 = sw[rw + j * 8 + rsel][s8 + kq + 4];
                mma16n8k8(c[j], a0, a1, a2, a3, b0, b1);
            }
        }
        __syncthreads();
    }

    float* sh = scores + (long)h * T_NEW * TFULL;
    const int t0 = lane >> 2, t1 = t0 + 8;
    const int ncol = (lane & 3) * 2;
#pragma unroll
    for (int j = 0; j < 4; j++) {
        int n = nbase + rw + j * 8 + ncol;
        float2 v0 = make_float2(c[j][0] * scale + mask[t0 * TFULL + n],
                                c[j][1] * scale + mask[t0 * TFULL + n + 1]);
        float2 v1 = make_float2(c[j][2] * scale + mask[t1 * TFULL + n],
                                c[j][3] * scale + mask[t1 * TFULL + n + 1]);
        *(float2*)(sh + (long)t0 * TFULL + n) = v0;
        *(float2*)(sh + (long)t1 * TFULL + n) = v1;
    }
}

// =============================================================
// pvMMA: attn_out[t][h*128+d] += sum_k P[h][t][k] * V_h[k][d]
// Block 128 thr (4 warps x 32 d-cols). Split-K z=16 over v-rows, atomics.
// B fragment read transposed from row-major sv (pad 132 -> conflict-free).
// =============================================================
__global__ void __launch_bounds__(128)
pvMMA(const float* __restrict__ P,
      const float* __restrict__ vc, const float* __restrict__ vn,
      float* __restrict__ outA) {
    __shared__ uint32_t sv[32][VPAD];
    __shared__ uint32_t sa[16][PROW];

    const int tid = threadIdx.x;
    const int wid = tid >> 5;
    const int lane = tid & 31;
    const int h = blockIdx.y;
    const int kvh = h >> 2;
    const int kbeg = blockIdx.z * 256;

    const int kq = lane & 3;
    const int rsel = lane >> 2;
    const int rw = wid * 32;

    const float* Ph = P + (long)h * T_NEW * TFULL;

    float c[4][4];
#pragma unroll
    for (int j = 0; j < 4; j++)
#pragma unroll
        for (int i = 0; i < 4; i++) c[j][i] = 0.f;

#pragma unroll 1
    for (int ch = 0; ch < 8; ++ch) {
        const int kk0 = kbeg + ch * 32;
        float4 wv[8];
#pragma unroll
        for (int i = 0; i < 8; i++) {
            int f = tid + i * 128;
            int vr = f >> 5, d0 = (f & 31) * 4;
            int rg = kk0 + vr;
            const float* src = (rg < TC)
                ? vc + ((long)kvh * TC + rg) * HD
                : vn + ((long)kvh * T_NEW + (rg - TC)) * HD;
            wv[i] = *(const float4*)(src + d0);
        }
        const int pt = tid >> 3, pc = (tid & 7) * 4;
        float4 av = *(const float4*)(Ph + (long)pt * TFULL + kk0 + pc);
        __syncthreads();
#pragma unroll
        for (int i = 0; i < 8; i++) {
            int f = tid + i * 128;
            int vr = f >> 5, d0 = (f & 31) * 4;
            uint4 t = make_uint4(tf(wv[i].x), tf(wv[i].y), tf(wv[i].z), tf(wv[i].w));
            *(uint4*)&sv[vr][d0] = t;
        }
        {
            uint4 t = make_uint4(tf(av.x), tf(av.y), tf(av.z), tf(av.w));
            *(uint4*)&sa[pt][pc] = t;
        }
        __syncthreads();

#pragma unroll
        for (int s = 0; s < 4; s++) {
            const int s8 = s * 8;
            uint32_t a0 = sa[rsel][s8 + kq];
            uint32_t a1 = sa[rsel + 8][s8 + kq];
            uint32_t a2 = sa[rsel][s8 + kq + 4];
            uint32_t a3 = sa[rsel + 8][s8 + kq + 4];
#pragma unroll
            for (int j = 0; j < 4; j++) {
                uint32_t b0 = sv[s8 + kq][rw + j * 8 + rsel];
                uint32_t b1 = sv[s8 + kq + 4][rw + j * 8 + rsel];
                mma16n8k8(c[j], a0, a1, a2, a3, b0, b1);
            }
        }
        __syncthreads();
    }

    const int t0 = lane >> 2, t1 = t0 + 8;
    const int ncol = (lane & 3) * 2;
#pragma unroll
    for (int j = 0; j < 4; j++) {
        int n = rw + j * 8 + ncol;
        float* o0 = outA + (long)t0 * (NH * HD) + h * HD + n;
        float* o1 = outA + (long)t1 * (NH * HD) + h * HD + n;
        atomicAdd(o0,     c[j][0]);
        atomicAdd(o0 + 1, c[j][1]);
        atomicAdd(o1,     c[j][2]);
        atomicAdd(o1 + 1, c[j][3]);
    }
}

// ---------------- per-head rmsnorm + RoPE for q/k, and new_v copy ----------------
__global__ void qk_norm_rope(float* __restrict__ q, float* __restrict__ k,
                             const float* __restrict__ v,
                             const float* __restrict__ qw, const float* __restrict__ kw,
                             const float* __restrict__ cosr, const float* __restrict__ sinr,
                             float* __restrict__ outk, float* __restrict__ outv) {
    int t = blockIdx.x;
    int hh = blockIdx.y;
    int d = threadIdx.x;

    if (hh >= 40) {
        int h = hh - 40;
        outv[(size_t)(h * T_NEW + t) * HD + d] = v[(size_t)t * (NKV * HD) + h * HD + d];
        return;
    }

    __shared__ float sv[HD];
    __shared__ float red[4];
    float* row; const float* w;
    if (hh < 32) { row = q + (size_t)t * (NH * HD) + hh * HD; w = qw; }
    else         { row = k + (size_t)t * (NKV * HD) + (hh - 32) * HD; w = kw; }

    float val = row[d];
    float s = val * val;
    for (int o = 16; o > 0; o >>= 1) s += __shfl_xor_sync(0xffffffffu, s, o);
    if ((d & 31) == 0) red[d >> 5] = s;
    __syncthreads();
    float tot = red[0] + red[1] + red[2] + red[3];
    float r = rsqrtf(tot / 128.f + RMS_EPS);
    float xn = val * r * w[d];
    sv[d] = xn;
    __syncthreads();
    float rot = (d < 64) ? -sv[d + 64] : sv[d - 64];
    float o = xn * cosr[t * HD + d] + rot * sinr[t * HD + d];
    row[d] = o;
    if (hh >= 32) {
        int h = hh - 32;
        outk[(size_t)(h * T_NEW + t) * HD + d] = o;
    }
}

// ---------------- row softmax over TFULL ----------------
__global__ void softmax_rows(float* __restrict__ s) {
    int row = blockIdx.x;
    float* p = s + (size_t)row * TFULL;
    __shared__ float red[8];
    int tid = threadIdx.x;
    float m = -3.4e38f;
    for (int i = tid; i < TFULL; i += 256) m = fmaxf(m, p[i]);
    for (int o = 16; o > 0; o >>= 1) m = fmaxf(m, __shfl_xor_sync(0xffffffffu, m, o));
    if ((tid & 31) == 0) red[tid >> 5] = m;
    __syncthreads();
    float mm = red[0];
#pragma unroll
    for (int i = 1; i < 8; i++) mm = fmaxf(mm, red[i]);
    __syncthreads();
    float sum = 0.f;
    for (int i = tid; i < TFULL; i += 256) {
        float e = expf(p[i] - mm);
        p[i] = e;
        sum += e;
    }
    for (int o = 16; o > 0; o >>= 1) sum += __shfl_xor_sync(0xffffffffu, sum, o);
    if ((tid & 31) == 0) red[tid >> 5] = sum;
    __syncthreads();
    float tot = 0.f;
#pragma unroll
    for (int i = 0; i < 8; i++) tot += red[i];
    float inv = 1.f / tot;
    for (int i = tid; i < TFULL; i += 256) p[i] *= inv;
}

static float* sym(const void* s) {
    void* p = nullptr;
    cudaGetSymbolAddress(&p, s);
    return (float*)p;
}

extern "C" void kernel_launch(void* const* d_in, const int* in_sizes, int n_in,
                              void* d_out, int out_size) {
    const float* x       = (const float*)d_in[0];
    const float* cos_q   = (const float*)d_in[1];
    const float* sin_q   = (const float*)d_in[2];
    const float* cache_k = (const float*)d_in[5];
    const float* cache_v = (const float*)d_in[6];
    const float* cmask   = (const float*)d_in[7];
    const float* ln1w    = (const float*)d_in[8];
    const float* ln2w    = (const float*)d_in[9];
    const float* qnw     = (const float*)d_in[10];
    const float* knw     = (const float*)d_in[11];
    const float* qw      = (const float*)d_in[12];
    const float* kw      = (const float*)d_in[13];
    const float* vw      = (const float*)d_in[14];
    const float* ow      = (const float*)d_in[15];
    const float* gw      = (const float*)d_in[16];
    const float* uw      = (const float*)d_in[17];
    const float* dw      = (const float*)d_in[18];
    float* out = (float*)d_out;
    float* out_k = out + T_NEW * HIDDEN;
    float* out_v = out_k + NKV * T_NEW * HD;

    static float *p_y = nullptr, *p_q, *p_k, *p_v, *p_scores, *p_attnout,
                 *p_h, *p_y2, *p_gate, *p_up;
    if (!p_y) {
        p_y = sym(g_y); p_q = sym(g_q); p_k = sym(g_k); p_v = sym(g_v);
        p_scores = sym(g_scores); p_attnout = sym(g_attnout);
        p_h = sym(g_h); p_y2 = sym(g_y2); p_gate = sym(g_gate); p_up = sym(g_up);
    }

    const float scale = 0.08838834764831845f; // 1/sqrt(128)
    const int BIG = 1 << 30;

    // 1) prep: rmsnorm1 (blocks 0-15) + zero atomic targets / seed h (rest)
    prep<<<16 + (T_NEW * INTER + 255) / 256, 256>>>(x, ln1w);

    // 2) fused QKV projection (tf32 mma): q [0,4096), k [4096,5120), v [5120,6144)
    mmaProj<<<dim3(24, 1, 16), 256>>>(p_y, nullptr,
        qw, kw, vw, p_q, p_k, p_v,
        NH * HD, NKV * HD, NKV * HD,
        4096, 5120, HIDDEN, 160);

    // 3) per-head q/k rmsnorm + RoPE; writes new_k/new_v into d_out
    qk_norm_rope<<<dim3(T_NEW, 48), 128>>>(p_q, p_k, p_v, qnw, knw, cos_q, sin_q,
                                           out_k, out_v);

    // 4) scores (tf32 mma, fused scale+mask)
    scoresMMA<<<dim3(16, NH), 256>>>(p_q, cache_k, out_k, cmask, p_scores, scale);

    // 5) softmax
    softmax_rows<<<NH * T_NEW, 256>>>(p_scores);

    // 6) attn_out = P @ V (tf32 mma, split-K z=16, atomic)
    pvMMA<<<dim3(1, NH, 16), 128>>>(p_scores, cache_v, out_v, p_attnout);

    // 7) O projection accumulates into h (pre-seeded with x)
    mmaProj<<<dim3(10, 1, 32), 256>>>(p_attnout, nullptr,
        ow, ow, ow, p_h, p_h, p_h,
        HIDDEN, HIDDEN, HIDDEN,
        BIG, BIG, NH * HD, 128);

    // 8) y2 = rmsnorm(h) * ln2; also copy h -> out (residual seed for down-proj)
    rmsnorm16<<<T_NEW, 256>>>(p_h, ln2w, p_y2, out, HIDDEN);

    // 9) fused gate/up: gate [0,9728), up [9728,19456)
    mmaProj<<<dim3(76, 1, 8), 256>>>(p_y2, nullptr,
        gw, uw, uw, p_gate, p_up, p_up,
        INTER, INTER, INTER,
        INTER, BIG, HIDDEN, 320);

    // 10) down projection with fused silu(gate)*up activation, accumulates into out
    mmaProj<<<dim3(10, 1, 38), 256>>>(p_gate, p_up,
        dw, dw, dw, out, out, out,
        HIDDEN, HIDDEN, HIDDEN,
        BIG, BIG, INTER, 256);
}

// round 12
// speedup vs baseline: 3.9810x; 1.3039x over previous
#include <cuda_runtime.h>
#include <cuda_bf16.h>
#include <math.h>
#include <stdint.h>

// ---------------- problem constants ----------------
#define T_NEW 16
#define HIDDEN 2560
#define INTER 9728
#define NH 32
#define NKV 8
#define HD 128
#define TC 4080
#define TFULL 4096
#define RMS_EPS 1e-6f
#define PROW 36
#define VPAD 136

// ---------------- scratch (device globals, no allocs) ----------------
__device__ float g_y[T_NEW * HIDDEN];
__device__ float g_q[T_NEW * NH * HD];
__device__ float g_k[T_NEW * NKV * HD];
__device__ float g_v[T_NEW * NKV * HD];
__device__ float g_scores[NH * T_NEW * TFULL];
__device__ float g_attnout[T_NEW * NH * HD];
__device__ float g_h[T_NEW * HIDDEN];
__device__ float g_y2[T_NEW * HIDDEN];
__device__ float g_gate[T_NEW * INTER];
__device__ float g_up[T_NEW * INTER];

// ---------------- tf32 mma.sync helpers (portable, sm_80+) ----------------
__device__ __forceinline__ uint32_t tf(float x) {
    uint32_t r;
    asm("cvt.rna.tf32.f32 %0, %1;" : "=r"(r) : "f"(x));
    return r;
}
__device__ __forceinline__ void mma16n8k8(float* c,
                                          uint32_t a0, uint32_t a1, uint32_t a2, uint32_t a3,
                                          uint32_t b0, uint32_t b1) {
    asm volatile(
        "mma.sync.aligned.m16n8k8.row.col.f32.tf32.tf32.f32 "
        "{%0,%1,%2,%3}, {%4,%5,%6,%7}, {%8,%9}, {%0,%1,%2,%3};"
        : "+f"(c[0]), "+f"(c[1]), "+f"(c[2]), "+f"(c[3])
        : "r"(a0), "r"(a1), "r"(a2), "r"(a3), "r"(b0), "r"(b1));
}
__device__ __forceinline__ float silu1(float x) {
    return x / (1.f + __expf(-x));
}

// ---------------- prep: rmsnorm(x)->y (blocks 0..15) + zero/seed (rest) ----------------
__global__ void prep(const float* __restrict__ x, const float* __restrict__ w) {
    if (blockIdx.x < 16) {
        int t = blockIdx.x;
        const float* row = x + (size_t)t * HIDDEN;
        float s = 0.f;
        for (int i = threadIdx.x; i < HIDDEN; i += 256) { float v = row[i]; s += v * v; }
        __shared__ float red[8];
        for (int o = 16; o > 0; o >>= 1) s += __shfl_xor_sync(0xffffffffu, s, o);
        if ((threadIdx.x & 31) == 0) red[threadIdx.x >> 5] = s;
        __syncthreads();
        float tot = 0.f;
#pragma unroll
        for (int i = 0; i < 8; i++) tot += red[i];
        float r = rsqrtf(tot / (float)HIDDEN + RMS_EPS);
        for (int i = threadIdx.x; i < HIDDEN; i += 256)
            g_y[(size_t)t * HIDDEN + i] = row[i] * r * w[i];
    } else {
        int i = (blockIdx.x - 16) * 256 + threadIdx.x;
        if (i < T_NEW * INTER) { g_gate[i] = 0.f; g_up[i] = 0.f; }
        if (i < T_NEW * NH * HD) { g_q[i] = 0.f; g_attnout[i] = 0.f; }
        if (i < T_NEW * NKV * HD) { g_k[i] = 0.f; g_v[i] = 0.f; }
        if (i < T_NEW * HIDDEN)  { g_h[i] = x[i]; }
    }
}

// ---------------- rmsnorm per token (optional raw copy to cp) ----------------
__global__ void rmsnorm16(const float* __restrict__ x, const float* __restrict__ w,
                          float* __restrict__ y, float* __restrict__ cp, int D) {
    int t = blockIdx.x;
    const float* row = x + (size_t)t * D;
    float s = 0.f;
    for (int i = threadIdx.x; i < D; i += 256) { float v = row[i]; s += v * v; }
    __shared__ float red[8];
    for (int o = 16; o > 0; o >>= 1) s += __shfl_xor_sync(0xffffffffu, s, o);
    if ((threadIdx.x & 31) == 0) red[threadIdx.x >> 5] = s;
    __syncthreads();
    float tot = 0.f;
#pragma unroll
    for (int i = 0; i < 8; i++) tot += red[i];
    float r = rsqrtf(tot / (float)D + RMS_EPS);
    for (int i = threadIdx.x; i < D; i += 256) {
        float v = row[i];
        y[(size_t)t * D + i] = v * r * w[i];
        if (cp) cp[(size_t)t * D + i] = v;
    }
}

// =============================================================
// mmaProj: smem-staged tf32 mma.sync GEMM, software-pipelined.
// out[t][n] += sum_k act[t][k] * W[n][k]; if act2: act := silu(act)*act2.
// Block 256 thr: 256 weight rows x 16 tokens, K-chunk 32.
// Loop: sync -> STS(cur) -> sync -> LDG(next, same regs) -> MMA(cur).
// =============================================================
__global__ void __launch_bounds__(256)
mmaProj(const float* __restrict__ act, const float* __restrict__ act2,
        const float* __restrict__ W0, const float* __restrict__ W1,
        const float* __restrict__ W2,
        float* __restrict__ O0, float* __restrict__ O1, float* __restrict__ O2,
        int ldo0, int ldo1, int ldo2, int nb1, int nb2,
        int K, int klen) {
    __shared__ uint32_t sw[256][PROW];
    __shared__ uint32_t sa[16][PROW];

    const int tid = threadIdx.x;
    const int wid = tid >> 5;
    const int lane = tid & 31;
    const int g = blockIdx.x * 256;

    const float* W; float* O; int ldo, nloc;
    if (g >= nb2)      { W = W2; O = O2; ldo = ldo2; nloc = g - nb2; }
    else if (g >= nb1) { W = W1; O = O1; ldo = ldo1; nloc = g - nb1; }
    else               { W = W0; O = O0; ldo = ldo0; nloc = g; }

    const int kbeg = blockIdx.z * klen;
    const int srow = tid >> 3;
    const int scol = (tid & 7) * 4;
    const int kq = lane & 3;
    const int rsel = lane >> 2;
    const int rw = wid * 32;

    float c[4][4];
#pragma unroll
    for (int j = 0; j < 4; j++)
#pragma unroll
        for (int i = 0; i < 4; i++) c[j][i] = 0.f;

    float4 wv[8];
    float4 av = make_float4(0.f, 0.f, 0.f, 0.f);

    // prologue loads (chunk 0)
#pragma unroll
    for (int i = 0; i < 8; i++) {
        int f = tid + i * 256;
        int r = f >> 3, cc = (f & 7) * 4;
        wv[i] = *(const float4*)(W + (long)(nloc + r) * K + kbeg + cc);
    }
    if (tid < 128) {
        av = *(const float4*)(act + (long)srow * K + kbeg + scol);
        if (act2) {
            float4 u = *(const float4*)(act2 + (long)srow * K + kbeg + scol);
            av = make_float4(silu1(av.x) * u.x, silu1(av.y) * u.y,
                             silu1(av.z) * u.z, silu1(av.w) * u.w);
        }
    }

    const int nchunks = klen >> 5;
    for (int ch = 0; ch < nchunks; ++ch) {
        __syncthreads();   // previous MMA reads complete
#pragma unroll
        for (int i = 0; i < 8; i++) {
            int f = tid + i * 256;
            int r = f >> 3, cc = (f & 7) * 4;
            uint4 t = make_uint4(tf(wv[i].x), tf(wv[i].y), tf(wv[i].z), tf(wv[i].w));
            *(uint4*)&sw[r][cc] = t;
        }
        if (tid < 128) {
            uint4 t = make_uint4(tf(av.x), tf(av.y), tf(av.z), tf(av.w));
            *(uint4*)&sa[srow][scol] = t;
        }
        __syncthreads();

        if (ch + 1 < nchunks) {
            const int k0 = kbeg + (ch + 1) * 32;
#pragma unroll
            for (int i = 0; i < 8; i++) {
                int f = tid + i * 256;
                int r = f >> 3, cc = (f & 7) * 4;
                wv[i] = *(const float4*)(W + (long)(nloc + r) * K + k0 + cc);
            }
            if (tid < 128) {
                av = *(const float4*)(act + (long)srow * K + k0 + scol);
                if (act2) {
                    float4 u = *(const float4*)(act2 + (long)srow * K + k0 + scol);
                    av = make_float4(silu1(av.x) * u.x, silu1(av.y) * u.y,
                                     silu1(av.z) * u.z, silu1(av.w) * u.w);
                }
            }
        }

#pragma unroll
        for (int s = 0; s < 4; s++) {
            const int s8 = s * 8;
            uint32_t a0 = sa[rsel][s8 + kq];
            uint32_t a1 = sa[rsel + 8][s8 + kq];
            uint32_t a2 = sa[rsel][s8 + kq + 4];
            uint32_t a3 = sa[rsel + 8][s8 + kq + 4];
#pragma unroll
            for (int j = 0; j < 4; j++) {
                uint32_t b0 = sw[rw + j * 8 + rsel][s8 + kq];
                uint32_t b1 = sw[rw + j * 8 + rsel][s8 + kq + 4];
                mma16n8k8(c[j], a0, a1, a2, a3, b0, b1);
            }
        }
    }

    const int t0 = lane >> 2, t1 = t0 + 8;
    const int ncol = (lane & 3) * 2;
#pragma unroll
    for (int j = 0; j < 4; j++) {
        int n = nloc + rw + j * 8 + ncol;
        atomicAdd(O + (long)t0 * ldo + n,     c[j][0]);
        atomicAdd(O + (long)t0 * ldo + n + 1, c[j][1]);
        atomicAdd(O + (long)t1 * ldo + n,     c[j][2]);
        atomicAdd(O + (long)t1 * ldo + n + 1, c[j][3]);
    }
}

// =============================================================
// scoresMMA: GQA-batched. Block: 256 key-rows x 64 q-rows (4 heads
// sharing one kv head). Grid (TFULL/256, NKV). K staged once for the
// whole group. scores[h][t][n] = (q.K)*scale + mask. Pipelined.
// =============================================================
__global__ void __launch_bounds__(256)
scoresMMA(const float* __restrict__ q,
          const float* __restrict__ kc, const float* __restrict__ kn,
          const float* __restrict__ mask,
          float* __restrict__ scores, float scale) {
    __shared__ uint32_t sw[256][PROW];
    __shared__ uint32_t sa[64][PROW];

    const int tid = threadIdx.x;
    const int wid = tid >> 5;
    const int lane = tid & 31;
    const int kvh = blockIdx.y;
    const int h0 = kvh * 4;
    const int nbase = blockIdx.x * 256;

    const int kq = lane & 3;
    const int rsel = lane >> 2;
    const int rw = wid * 32;

    float c[4][4][4];   // [head][j][reg]
#pragma unroll
    for (int hh = 0; hh < 4; hh++)
#pragma unroll
        for (int j = 0; j < 4; j++)
#pragma unroll
            for (int i = 0; i < 4; i++) c[hh][j][i] = 0.f;

    float4 wv[8], av[2];

    // prologue (chunk 0)
#pragma unroll
    for (int i = 0; i < 8; i++) {
        int f = tid + i * 256;
        int r = f >> 3, cc = (f & 7) * 4;
        int rg = nbase + r;
        const float* src = (rg < TC)
            ? kc + ((long)kvh * TC + rg) * HD
            : kn + ((long)kvh * T_NEW + (rg - TC)) * HD;
        wv[i] = *(const float4*)(src + cc);
    }
#pragma unroll
    for (int i = 0; i < 2; i++) {
        int f = tid + i * 256;
        int row = f >> 3, cc = (f & 7) * 4;
        int hh = row >> 4, t = row & 15;
        av[i] = *(const float4*)(q + ((long)t * NH + h0 + hh) * HD + cc);
    }

#pragma unroll 1
    for (int ch = 0; ch < 4; ++ch) {
        __syncthreads();
#pragma unroll
        for (int i = 0; i < 8; i++) {
            int f = tid + i * 256;
            int r = f >> 3, cc = (f & 7) * 4;
            uint4 t = make_uint4(tf(wv[i].x), tf(wv[i].y), tf(wv[i].z), tf(wv[i].w));
            *(uint4*)&sw[r][cc] = t;
        }
#pragma unroll
        for (int i = 0; i < 2; i++) {
            int f = tid + i * 256;
            int row = f >> 3, cc = (f & 7) * 4;
            uint4 t = make_uint4(tf(av[i].x), tf(av[i].y), tf(av[i].z), tf(av[i].w));
            *(uint4*)&sa[row][cc] = t;
        }
        __syncthreads();

        if (ch + 1 < 4) {
            const int k0 = (ch + 1) * 32;
#pragma unroll
            for (int i = 0; i < 8; i++) {
                int f = tid + i * 256;
                int r = f >> 3, cc = (f & 7) * 4;
                int rg = nbase + r;
                const float* src = (rg < TC)
                    ? kc + ((long)kvh * TC + rg) * HD
                    : kn + ((long)kvh * T_NEW + (rg - TC)) * HD;
                wv[i] = *(const float4*)(src + k0 + cc);
            }
#pragma unroll
            for (int i = 0; i < 2; i++) {
                int f = tid + i * 256;
                int row = f >> 3, cc = (f & 7) * 4;
                int hh = row >> 4, t = row & 15;
                av[i] = *(const float4*)(q + ((long)t * NH + h0 + hh) * HD + k0 + cc);
            }
        }

#pragma unroll
        for (int s = 0; s < 4; s++) {
            const int s8 = s * 8;
            uint32_t a[4][4];
#pragma unroll
            for (int hh = 0; hh < 4; hh++) {
                a[hh][0] = sa[hh * 16 + rsel][s8 + kq];
                a[hh][1] = sa[hh * 16 + rsel + 8][s8 + kq];
                a[hh][2] = sa[hh * 16 + rsel][s8 + kq + 4];
                a[hh][3] = sa[hh * 16 + rsel + 8][s8 + kq + 4];
            }
#pragma unroll
            for (int j = 0; j < 4; j++) {
                uint32_t b0 = sw[rw + j * 8 + rsel][s8 + kq];
                uint32_t b1 = sw[rw + j * 8 + rsel][s8 + kq + 4];
#pragma unroll
                for (int hh = 0; hh < 4; hh++)
                    mma16n8k8(c[hh][j], a[hh][0], a[hh][1], a[hh][2], a[hh][3], b0, b1);
            }
        }
    }

    const int t0 = lane >> 2, t1 = t0 + 8;
    const int ncol = (lane & 3) * 2;
#pragma unroll
    for (int hh = 0; hh < 4; hh++) {
        float* sh = scores + (long)(h0 + hh) * T_NEW * TFULL;
#pragma unroll
        for (int j = 0; j < 4; j++) {
            int n = nbase + rw + j * 8 + ncol;
            float2 v0 = make_float2(c[hh][j][0] * scale + mask[t0 * TFULL + n],
                                    c[hh][j][1] * scale + mask[t0 * TFULL + n + 1]);
            float2 v1 = make_float2(c[hh][j][2] * scale + mask[t1 * TFULL + n],
                                    c[hh][j][3] * scale + mask[t1 * TFULL + n + 1]);
            *(float2*)(sh + (long)t0 * TFULL + n) = v0;
            *(float2*)(sh + (long)t1 * TFULL + n) = v1;
        }
    }
}

// =============================================================
// pvMMA: GQA-batched. Block 128 thr (4 warps x 32 d-cols), m=64
// (4 heads x 16 t), k-chunk 32 v-rows, split-K z over 4096 rows.
// V staged once per group; atomics into attn_out. Pipelined.
// =============================================================
__global__ void __launch_bounds__(128)
pvMMA(const float* __restrict__ P,
      const float* __restrict__ vc, const float* __restrict__ vn,
      float* __restrict__ outA) {
    __shared__ uint32_t sv[32][VPAD];
    __shared__ uint32_t sa[64][PROW];

    const int tid = threadIdx.x;
    const int wid = tid >> 5;
    const int lane = tid & 31;
    const int kvh = blockIdx.y;
    const int h0 = kvh * 4;
    const int kbeg = blockIdx.z * 256;

    const int kq = lane & 3;
    const int rsel = lane >> 2;
    const int rw = wid * 32;

    float c[4][4][4];
#pragma unroll
    for (int hh = 0; hh < 4; hh++)
#pragma unroll
        for (int j = 0; j < 4; j++)
#pragma unroll
            for (int i = 0; i < 4; i++) c[hh][j][i] = 0.f;

    float4 wv[8], av[4];

    // prologue (chunk 0)
#pragma unroll
    for (int i = 0; i < 8; i++) {
        int f = tid + i * 128;
        int vr = f >> 5, d0 = (f & 31) * 4;
        int rg = kbeg + vr;
        const float* src = (rg < TC)
            ? vc + ((long)kvh * TC + rg) * HD
            : vn + ((long)kvh * T_NEW + (rg - TC)) * HD;
        wv[i] = *(const float4*)(src + d0);
    }
#pragma unroll
    for (int i = 0; i < 4; i++) {
        int f = tid + i * 128;
        int row = f >> 3, cc = (f & 7) * 4;
        int hh = row >> 4, t = row & 15;
        av[i] = *(const float4*)(P + ((long)(h0 + hh) * T_NEW + t) * TFULL + kbeg + cc);
    }

#pragma unroll 1
    for (int ch = 0; ch < 8; ++ch) {
        __syncthreads();
#pragma unroll
        for (int i = 0; i < 8; i++) {
            int f = tid + i * 128;
            int vr = f >> 5, d0 = (f & 31) * 4;
            uint4 t = make_uint4(tf(wv[i].x), tf(wv[i].y), tf(wv[i].z), tf(wv[i].w));
            *(uint4*)&sv[vr][d0] = t;
        }
#pragma unroll
        for (int i = 0; i < 4; i++) {
            int f = tid + i * 128;
            int row = f >> 3, cc = (f & 7) * 4;
            uint4 t = make_uint4(tf(av[i].x), tf(av[i].y), tf(av[i].z), tf(av[i].w));
            *(uint4*)&sa[row][cc] = t;
        }
        __syncthreads();

        if (ch + 1 < 8) {
            const int kk0 = kbeg + (ch + 1) * 32;
#pragma unroll
            for (int i = 0; i < 8; i++) {
                int f = tid + i * 128;
                int vr = f >> 5, d0 = (f & 31) * 4;
                int rg = kk0 + vr;
                const float* src = (rg < TC)
                    ? vc + ((long)kvh * TC + rg) * HD
                    : vn + ((long)kvh * T_NEW + (rg - TC)) * HD;
                wv[i] = *(const float4*)(src + d0);
            }
#pragma unroll
            for (int i = 0; i < 4; i++) {
                int f = tid + i * 128;
                int row = f >> 3, cc = (f & 7) * 4;
                int hh = row >> 4, t = row & 15;
                av[i] = *(const float4*)(P + ((long)(h0 + hh) * T_NEW + t) * TFULL + kk0 + cc);
            }
        }

#pragma unroll
        for (int s = 0; s < 4; s++) {
            const int s8 = s * 8;
            uint32_t a[4][4];
#pragma unroll
            for (int hh = 0; hh < 4; hh++) {
                a[hh][0] = sa[hh * 16 + rsel][s8 + kq];
                a[hh][1] = sa[hh * 16 + rsel + 8][s8 + kq];
                a[hh][2] = sa[hh * 16 + rsel][s8 + kq + 4];
                a[hh][3] = sa[hh * 16 + rsel + 8][s8 + kq + 4];
            }
#pragma unroll
            for (int j = 0; j < 4; j++) {
                uint32_t b0 = sv[s8 + kq][rw + j * 8 + rsel];
                uint32_t b1 = sv[s8 + kq + 4][rw + j * 8 + rsel];
#pragma unroll
                for (int hh = 0; hh < 4; hh++)
                    mma16n8k8(c[hh][j], a[hh][0], a[hh][1], a[hh][2], a[hh][3], b0, b1);
            }
        }
    }

    const int t0 = lane >> 2, t1 = t0 + 8;
    const int ncol = (lane & 3) * 2;
#pragma unroll
    for (int hh = 0; hh < 4; hh++) {
        const long hb = (long)(h0 + hh) * HD;
#pragma unroll
        for (int j = 0; j < 4; j++) {
            int n = rw + j * 8 + ncol;
            float* o0 = outA + (long)t0 * (NH * HD) + hb + n;
            float* o1 = outA + (long)t1 * (NH * HD) + hb + n;
            atomicAdd(o0,     c[hh][j][0]);
            atomicAdd(o0 + 1, c[hh][j][1]);
            atomicAdd(o1,     c[hh][j][2]);
            atomicAdd(o1 + 1, c[hh][j][3]);
        }
    }
}

// ---------------- per-head rmsnorm + RoPE for q/k, and new_v copy ----------------
__global__ void qk_norm_rope(float* __restrict__ q, float* __restrict__ k,
                             const float* __restrict__ v,
                             const float* __restrict__ qw, const float* __restrict__ kw,
                             const float* __restrict__ cosr, const float* __restrict__ sinr,
                             float* __restrict__ outk, float* __restrict__ outv) {
    int t = blockIdx.x;
    int hh = blockIdx.y;
    int d = threadIdx.x;

    if (hh >= 40) {
        int h = hh - 40;
        outv[(size_t)(h * T_NEW + t) * HD + d] = v[(size_t)t * (NKV * HD) + h * HD + d];
        return;
    }

    __shared__ float sv[HD];
    __shared__ float red[4];
    float* row; const float* w;
    if (hh < 32) { row = q + (size_t)t * (NH * HD) + hh * HD; w = qw; }
    else         { row = k + (size_t)t * (NKV * HD) + (hh - 32) * HD; w = kw; }

    float val = row[d];
    float s = val * val;
    for (int o = 16; o > 0; o >>= 1) s += __shfl_xor_sync(0xffffffffu, s, o);
    if ((d & 31) == 0) red[d >> 5] = s;
    __syncthreads();
    float tot = red[0] + red[1] + red[2] + red[3];
    float r = rsqrtf(tot / 128.f + RMS_EPS);
    float xn = val * r * w[d];
    sv[d] = xn;
    __syncthreads();
    float rot = (d < 64) ? -sv[d + 64] : sv[d - 64];
    float o = xn * cosr[t * HD + d] + rot * sinr[t * HD + d];
    row[d] = o;
    if (hh >= 32) {
        int h = hh - 32;
        outk[(size_t)(h * T_NEW + t) * HD + d] = o;
    }
}

// ---------------- row softmax over TFULL ----------------
__global__ void softmax_rows(float* __restrict__ s) {
    int row = blockIdx.x;
    float* p = s + (size_t)row * TFULL;
    __shared__ float red[8];
    int tid = threadIdx.x;
    float m = -3.4e38f;
    for (int i = tid; i < TFULL; i += 256) m = fmaxf(m, p[i]);
    for (int o = 16; o > 0; o >>= 1) m = fmaxf(m, __shfl_xor_sync(0xffffffffu, m, o));
    if ((tid & 31) == 0) red[tid >> 5] = m;
    __syncthreads();
    float mm = red[0];
#pragma unroll
    for (int i = 1; i < 8; i++) mm = fmaxf(mm, red[i]);
    __syncthreads();
    float sum = 0.f;
    for (int i = tid; i < TFULL; i += 256) {
        float e = expf(p[i] - mm);
        p[i] = e;
        sum += e;
    }
    for (int o = 16; o > 0; o >>= 1) sum += __shfl_xor_sync(0xffffffffu, sum, o);
    if ((tid & 31) == 0) red[tid >> 5] = sum;
    __syncthreads();
    float tot = 0.f;
#pragma unroll
    for (int i = 0; i < 8; i++) tot += red[i];
    float inv = 1.f / tot;
    for (int i = tid; i < TFULL; i += 256) p[i] *= inv;
}

static float* sym(const void* s) {
    void* p = nullptr;
    cudaGetSymbolAddress(&p, s);
    return (float*)p;
}

extern "C" void kernel_launch(void* const* d_in, const int* in_sizes, int n_in,
                              void* d_out, int out_size) {
    const float* x       = (const float*)d_in[0];
    const float* cos_q   = (const float*)d_in[1];
    const float* sin_q   = (const float*)d_in[2];
    const float* cache_k = (const float*)d_in[5];
    const float* cache_v = (const float*)d_in[6];
    const float* cmask   = (const float*)d_in[7];
    const float* ln1w    = (const float*)d_in[8];
    const float* ln2w    = (const float*)d_in[9];
    const float* qnw     = (const float*)d_in[10];
    const float* knw     = (const float*)d_in[11];
    const float* qw      = (const float*)d_in[12];
    const float* kw      = (const float*)d_in[13];
    const float* vw      = (const float*)d_in[14];
    const float* ow      = (const float*)d_in[15];
    const float* gw      = (const float*)d_in[16];
    const float* uw      = (const float*)d_in[17];
    const float* dw      = (const float*)d_in[18];
    float* out = (float*)d_out;
    float* out_k = out + T_NEW * HIDDEN;
    float* out_v = out_k + NKV * T_NEW * HD;

    static float *p_y = nullptr, *p_q, *p_k, *p_v, *p_scores, *p_attnout,
                 *p_h, *p_y2, *p_gate, *p_up;
    if (!p_y) {
        p_y = sym(g_y); p_q = sym(g_q); p_k = sym(g_k); p_v = sym(g_v);
        p_scores = sym(g_scores); p_attnout = sym(g_attnout);
        p_h = sym(g_h); p_y2 = sym(g_y2); p_gate = sym(g_gate); p_up = sym(g_up);
    }

    const float scale = 0.08838834764831845f; // 1/sqrt(128)
    const int BIG = 1 << 30;

    // 1) prep: rmsnorm1 (blocks 0-15) + zero atomic targets / seed h (rest)
    prep<<<16 + (T_NEW * INTER + 255) / 256, 256>>>(x, ln1w);

    // 2) fused QKV projection: q [0,4096), k [4096,5120), v [5120,6144)
    mmaProj<<<dim3(24, 1, 16), 256>>>(p_y, nullptr,
        qw, kw, vw, p_q, p_k, p_v,
        NH * HD, NKV * HD, NKV * HD,
        4096, 5120, HIDDEN, 160);

    // 3) per-head q/k rmsnorm + RoPE; writes new_k/new_v into d_out
    qk_norm_rope<<<dim3(T_NEW, 48), 128>>>(p_q, p_k, p_v, qnw, knw, cos_q, sin_q,
                                           out_k, out_v);

    // 4) scores (GQA-batched tf32 mma, fused scale+mask)
    scoresMMA<<<dim3(16, NKV), 256>>>(p_q, cache_k, out_k, cmask, p_scores, scale);

    // 5) softmax
    softmax_rows<<<NH * T_NEW, 256>>>(p_scores);

    // 6) attn_out = P @ V (GQA-batched, split-K z=16, atomic)
    pvMMA<<<dim3(1, NKV, 16), 128>>>(p_scores, cache_v, out_v, p_attnout);

    // 7) O projection accumulates into h (pre-seeded with x)
    mmaProj<<<dim3(10, 1, 32), 256>>>(p_attnout, nullptr,
        ow, ow, ow, p_h, p_h, p_h,
        HIDDEN, HIDDEN, HIDDEN,
        BIG, BIG, NH * HD, 128);

    // 8) y2 = rmsnorm(h) * ln2; also copy h -> out (residual seed for down-proj)
    rmsnorm16<<<T_NEW, 256>>>(p_h, ln2w, p_y2, out, HIDDEN);

    // 9) fused gate/up: gate [0,9728), up [9728,19456)
    mmaProj<<<dim3(76, 1, 8), 256>>>(p_y2, nullptr,
        gw, uw, uw, p_gate, p_up, p_up,
        INTER, INTER, INTER,
        INTER, BIG, HIDDEN, 320);

    // 10) down projection with fused silu(gate)*up activation, accumulates into out
    mmaProj<<<dim3(10, 1, 38), 256>>>(p_gate, p_up,
        dw, dw, dw, out, out, out,
        HIDDEN, HIDDEN, HIDDEN,
        BIG, BIG, INTER, 256);
}

// round 13
// speedup vs baseline: 4.1526x; 1.0431x over previous
#include <cuda_runtime.h>
#include <cuda_bf16.h>
#include <cuda_fp16.h>
#include <math.h>
#include <stdint.h>

// ---------------- problem constants ----------------
#define T_NEW 16
#define HIDDEN 2560
#define INTER 9728
#define NH 32
#define NKV 8
#define HD 128
#define TC 4080
#define TFULL 4096
#define RMS_EPS 1e-6f
#define PROW 20      // half2 words per 32-float k-chunk row (16 + 4 pad)
#define APROW 36     // fp32 pad for pvMMA A
#define VPAD 136

// ---------------- scratch (device globals, no allocs) ----------------
__device__ float g_y[T_NEW * HIDDEN];
__device__ float g_q[T_NEW * NH * HD];
__device__ float g_k[T_NEW * NKV * HD];
__device__ float g_v[T_NEW * NKV * HD];
__device__ float g_scores[NH * T_NEW * TFULL];
__device__ float g_attnout[T_NEW * NH * HD];
__device__ float g_h[T_NEW * HIDDEN];
__device__ float g_y2[T_NEW * HIDDEN];
__device__ float g_gate[T_NEW * INTER];
__device__ float g_up[T_NEW * INTER];

// ---------------- fp16 / tf32 mma helpers ----------------
__device__ __forceinline__ uint32_t h2(float lo, float hi) {
    uint32_t r;
    asm("cvt.rn.f16x2.f32 %0, %1, %2;" : "=r"(r) : "f"(hi), "f"(lo));
    return r;
}
__device__ __forceinline__ void mmaF16(float* c,
                                       uint32_t a0, uint32_t a1, uint32_t a2, uint32_t a3,
                                       uint32_t b0, uint32_t b1) {
    asm volatile(
        "mma.sync.aligned.m16n8k16.row.col.f32.f16.f16.f32 "
        "{%0,%1,%2,%3}, {%4,%5,%6,%7}, {%8,%9}, {%0,%1,%2,%3};"
        : "+f"(c[0]), "+f"(c[1]), "+f"(c[2]), "+f"(c[3])
        : "r"(a0), "r"(a1), "r"(a2), "r"(a3), "r"(b0), "r"(b1));
}
__device__ __forceinline__ uint32_t tf(float x) {
    uint32_t r;
    asm("cvt.rna.tf32.f32 %0, %1;" : "=r"(r) : "f"(x));
    return r;
}
__device__ __forceinline__ void mmaTF32(float* c,
                                        uint32_t a0, uint32_t a1, uint32_t a2, uint32_t a3,
                                        uint32_t b0, uint32_t b1) {
    asm volatile(
        "mma.sync.aligned.m16n8k8.row.col.f32.tf32.tf32.f32 "
        "{%0,%1,%2,%3}, {%4,%5,%6,%7}, {%8,%9}, {%0,%1,%2,%3};"
        : "+f"(c[0]), "+f"(c[1]), "+f"(c[2]), "+f"(c[3])
        : "r"(a0), "r"(a1), "r"(a2), "r"(a3), "r"(b0), "r"(b1));
}
__device__ __forceinline__ float silu1(float x) {
    return x / (1.f + __expf(-x));
}

// ---------------- prep: rmsnorm(x)->y (blocks 0..15) + zero/seed (rest) ----------------
__global__ void prep(const float* __restrict__ x, const float* __restrict__ w) {
    if (blockIdx.x < 16) {
        int t = blockIdx.x;
        const float* row = x + (size_t)t * HIDDEN;
        float s = 0.f;
        for (int i = threadIdx.x; i < HIDDEN; i += 256) { float v = row[i]; s += v * v; }
        __shared__ float red[8];
        for (int o = 16; o > 0; o >>= 1) s += __shfl_xor_sync(0xffffffffu, s, o);
        if ((threadIdx.x & 31) == 0) red[threadIdx.x >> 5] = s;
        __syncthreads();
        float tot = 0.f;
#pragma unroll
        for (int i = 0; i < 8; i++) tot += red[i];
        float r = rsqrtf(tot / (float)HIDDEN + RMS_EPS);
        for (int i = threadIdx.x; i < HIDDEN; i += 256)
            g_y[(size_t)t * HIDDEN + i] = row[i] * r * w[i];
    } else {
        int i = (blockIdx.x - 16) * 256 + threadIdx.x;
        if (i < T_NEW * INTER) { g_gate[i] = 0.f; g_up[i] = 0.f; }
        if (i < T_NEW * NH * HD) { g_q[i] = 0.f; g_attnout[i] = 0.f; }
        if (i < T_NEW * NKV * HD) { g_k[i] = 0.f; g_v[i] = 0.f; }
        if (i < T_NEW * HIDDEN)  { g_h[i] = x[i]; }
    }
}

// ---------------- rmsnorm per token (optional raw copy to cp) ----------------
__global__ void rmsnorm16(const float* __restrict__ x, const float* __restrict__ w,
                          float* __restrict__ y, float* __restrict__ cp, int D) {
    int t = blockIdx.x;
    const float* row = x + (size_t)t * D;
    float s = 0.f;
    for (int i = threadIdx.x; i < D; i += 256) { float v = row[i]; s += v * v; }
    __shared__ float red[8];
    for (int o = 16; o > 0; o >>= 1) s += __shfl_xor_sync(0xffffffffu, s, o);
    if ((threadIdx.x & 31) == 0) red[threadIdx.x >> 5] = s;
    __syncthreads();
    float tot = 0.f;
#pragma unroll
    for (int i = 0; i < 8; i++) tot += red[i];
    float r = rsqrtf(tot / (float)D + RMS_EPS);
    for (int i = threadIdx.x; i < D; i += 256) {
        float v = row[i];
        y[(size_t)t * D + i] = v * r * w[i];
        if (cp) cp[(size_t)t * D + i] = v;
    }
}

// =============================================================
// mmaProj: fp16 smem-staged mma GEMM, software-pipelined.
// out[t][n] += sum_k act[t][k] * W[n][k]; if act2: act := silu(act)*act2.
// Block 256 thr: 256 weight rows x 16 tokens, K-chunk 32 floats.
// =============================================================
__global__ void __launch_bounds__(256)
mmaProj(const float* __restrict__ act, const float* __restrict__ act2,
        const float* __restrict__ W0, const float* __restrict__ W1,
        const float* __restrict__ W2,
        float* __restrict__ O0, float* __restrict__ O1, float* __restrict__ O2,
        int ldo0, int ldo1, int ldo2, int nb1, int nb2,
        int K, int klen) {
    __shared__ uint32_t sw[256][PROW];
    __shared__ uint32_t sa[16][PROW];

    const int tid = threadIdx.x;
    const int wid = tid >> 5;
    const int lane = tid & 31;
    const int g = blockIdx.x * 256;

    const float* W; float* O; int ldo, nloc;
    if (g >= nb2)      { W = W2; O = O2; ldo = ldo2; nloc = g - nb2; }
    else if (g >= nb1) { W = W1; O = O1; ldo = ldo1; nloc = g - nb1; }
    else               { W = W0; O = O0; ldo = ldo0; nloc = g; }

    const int kbeg = blockIdx.z * klen;
    const int kq = lane & 3;
    const int rsel = lane >> 2;
    const int rw = wid * 32;

    // W staging decomposition: u = tid + i*256, r = u>>2, kc = (u&3)*8 floats
    const int wr_[1] = {0}; (void)wr_;
    const int srow = tid >> 3;            // act row (tid<128)
    const int scol = (tid & 7) * 4;       // act float col

    float c[4][4];
#pragma unroll
    for (int j = 0; j < 4; j++)
#pragma unroll
        for (int i = 0; i < 4; i++) c[j][i] = 0.f;

    uint4 wq[4];
    uint32_t aq0 = 0, aq1 = 0;

    // prologue pack (chunk 0)
#pragma unroll
    for (int i = 0; i < 4; i++) {
        int u = tid + i * 256;
        int r = u >> 2, kc = (u & 3) * 8;
        const float* p = W + (long)(nloc + r) * K + kbeg + kc;
        float4 f0 = *(const float4*)p;
        float4 f1 = *(const float4*)(p + 4);
        wq[i] = make_uint4(h2(f0.x, f0.y), h2(f0.z, f0.w),
                           h2(f1.x, f1.y), h2(f1.z, f1.w));
    }
    if (tid < 128) {
        float4 av = *(const float4*)(act + (long)srow * K + kbeg + scol);
        if (act2) {
            float4 u = *(const float4*)(act2 + (long)srow * K + kbeg + scol);
            av = make_float4(silu1(av.x) * u.x, silu1(av.y) * u.y,
                             silu1(av.z) * u.z, silu1(av.w) * u.w);
        }
        aq0 = h2(av.x, av.y); aq1 = h2(av.z, av.w);
    }

    const int nchunks = klen >> 5;
    for (int ch = 0; ch < nchunks; ++ch) {
        __syncthreads();
#pragma unroll
        for (int i = 0; i < 4; i++) {
            int u = tid + i * 256;
            int r = u >> 2, kp = (u & 3) * 4;
            *(uint4*)&sw[r][kp] = wq[i];
        }
        if (tid < 128) {
            sa[srow][(scol >> 1)] = aq0;
            sa[srow][(scol >> 1) + 1] = aq1;
        }
        __syncthreads();

        if (ch + 1 < nchunks) {
            const int k0 = kbeg + (ch + 1) * 32;
#pragma unroll
            for (int i = 0; i < 4; i++) {
                int u = tid + i * 256;
                int r = u >> 2, kc = (u & 3) * 8;
                const float* p = W + (long)(nloc + r) * K + k0 + kc;
                float4 f0 = *(const float4*)p;
                float4 f1 = *(const float4*)(p + 4);
                wq[i] = make_uint4(h2(f0.x, f0.y), h2(f0.z, f0.w),
                                   h2(f1.x, f1.y), h2(f1.z, f1.w));
            }
            if (tid < 128) {
                float4 av = *(const float4*)(act + (long)srow * K + k0 + scol);
                if (act2) {
                    float4 u = *(const float4*)(act2 + (long)srow * K + k0 + scol);
                    av = make_float4(silu1(av.x) * u.x, silu1(av.y) * u.y,
                                     silu1(av.z) * u.z, silu1(av.w) * u.w);
                }
                aq0 = h2(av.x, av.y); aq1 = h2(av.z, av.w);
            }
        }

#pragma unroll
        for (int s = 0; s < 2; s++) {
            const int b8 = s * 8;
            uint32_t a0 = sa[rsel][b8 + kq];
            uint32_t a1 = sa[rsel + 8][b8 + kq];
            uint32_t a2 = sa[rsel][b8 + kq + 4];
            uint32_t a3 = sa[rsel + 8][b8 + kq + 4];
#pragma unroll
            for (int j = 0; j < 4; j++) {
                uint32_t b0 = sw[rw + j * 8 + rsel][b8 + kq];
                uint32_t b1 = sw[rw + j * 8 + rsel][b8 + kq + 4];
                mmaF16(c[j], a0, a1, a2, a3, b0, b1);
            }
        }
    }

    const int t0 = lane >> 2, t1 = t0 + 8;
    const int ncol = (lane & 3) * 2;
#pragma unroll
    for (int j = 0; j < 4; j++) {
        int n = nloc + rw + j * 8 + ncol;
        atomicAdd(O + (long)t0 * ldo + n,     c[j][0]);
        atomicAdd(O + (long)t0 * ldo + n + 1, c[j][1]);
        atomicAdd(O + (long)t1 * ldo + n,     c[j][2]);
        atomicAdd(O + (long)t1 * ldo + n + 1, c[j][3]);
    }
}

// =============================================================
// scoresMMA: GQA-batched fp16. Block: 256 key-rows x 64 q-rows
// (4 heads x 16 tokens sharing a kv head). Pipelined, fused scale+mask.
// =============================================================
__global__ void __launch_bounds__(256)
scoresMMA(const float* __restrict__ q,
          const float* __restrict__ kc_, const float* __restrict__ kn,
          const float* __restrict__ mask,
          float* __restrict__ scores, float scale) {
    __shared__ uint32_t sw[256][PROW];
    __shared__ uint32_t sa[64][PROW];

    const int tid = threadIdx.x;
    const int wid = tid >> 5;
    const int lane = tid & 31;
    const int kvh = blockIdx.y;
    const int h0 = kvh * 4;
    const int nbase = blockIdx.x * 256;

    const int kq = lane & 3;
    const int rsel = lane >> 2;
    const int rw = wid * 32;

    float c[4][4][4];
#pragma unroll
    for (int hh = 0; hh < 4; hh++)
#pragma unroll
        for (int j = 0; j < 4; j++)
#pragma unroll
            for (int i = 0; i < 4; i++) c[hh][j][i] = 0.f;

    uint4 wq[4];
    uint32_t aq[2][2];

    // prologue (chunk 0)
#pragma unroll
    for (int i = 0; i < 4; i++) {
        int u = tid + i * 256;
        int r = u >> 2, kcf = (u & 3) * 8;
        int rg = nbase + r;
        const float* src = (rg < TC)
            ? kc_ + ((long)kvh * TC + rg) * HD
            : kn + ((long)kvh * T_NEW + (rg - TC)) * HD;
        float4 f0 = *(const float4*)(src + kcf);
        float4 f1 = *(const float4*)(src + kcf + 4);
        wq[i] = make_uint4(h2(f0.x, f0.y), h2(f0.z, f0.w),
                           h2(f1.x, f1.y), h2(f1.z, f1.w));
    }
#pragma unroll
    for (int i = 0; i < 2; i++) {
        int u = tid + i * 256;
        int row = u >> 3, kcf = (u & 7) * 4;
        int hh = row >> 4, t = row & 15;
        float4 av = *(const float4*)(q + ((long)t * NH + h0 + hh) * HD + kcf);
        aq[i][0] = h2(av.x, av.y); aq[i][1] = h2(av.z, av.w);
    }

#pragma unroll 1
    for (int ch = 0; ch < 4; ++ch) {
        __syncthreads();
#pragma unroll
        for (int i = 0; i < 4; i++) {
            int u = tid + i * 256;
            int r = u >> 2, kp = (u & 3) * 4;
            *(uint4*)&sw[r][kp] = wq[i];
        }
#pragma unroll
        for (int i = 0; i < 2; i++) {
            int u = tid + i * 256;
            int row = u >> 3, kp = (u & 7) * 2;
            sa[row][kp] = aq[i][0];
            sa[row][kp + 1] = aq[i][1];
        }
        __syncthreads();

        if (ch + 1 < 4) {
            const int k0 = (ch + 1) * 32;
#pragma unroll
            for (int i = 0; i < 4; i++) {
                int u = tid + i * 256;
                int r = u >> 2, kcf = (u & 3) * 8;
                int rg = nbase + r;
                const float* src = (rg < TC)
                    ? kc_ + ((long)kvh * TC + rg) * HD
                    : kn + ((long)kvh * T_NEW + (rg - TC)) * HD;
                float4 f0 = *(const float4*)(src + k0 + kcf);
                float4 f1 = *(const float4*)(src + k0 + kcf + 4);
                wq[i] = make_uint4(h2(f0.x, f0.y), h2(f0.z, f0.w),
                                   h2(f1.x, f1.y), h2(f1.z, f1.w));
            }
#pragma unroll
            for (int i = 0; i < 2; i++) {
                int u = tid + i * 256;
                int row = u >> 3, kcf = (u & 7) * 4;
                int hh = row >> 4, t = row & 15;
                float4 av = *(const float4*)(q + ((long)t * NH + h0 + hh) * HD + k0 + kcf);
                aq[i][0] = h2(av.x, av.y); aq[i][1] = h2(av.z, av.w);
            }
        }

#pragma unroll
        for (int s = 0; s < 2; s++) {
            const int b8 = s * 8;
            uint32_t a[4][4];
#pragma unroll
            for (int hh = 0; hh < 4; hh++) {
                a[hh][0] = sa[hh * 16 + rsel][b8 + kq];
                a[hh][1] = sa[hh * 16 + rsel + 8][b8 + kq];
                a[hh][2] = sa[hh * 16 + rsel][b8 + kq + 4];
                a[hh][3] = sa[hh * 16 + rsel + 8][b8 + kq + 4];
            }
#pragma unroll
            for (int j = 0; j < 4; j++) {
                uint32_t b0 = sw[rw + j * 8 + rsel][b8 + kq];
                uint32_t b1 = sw[rw + j * 8 + rsel][b8 + kq + 4];
#pragma unroll
                for (int hh = 0; hh < 4; hh++)
                    mmaF16(c[hh][j], a[hh][0], a[hh][1], a[hh][2], a[hh][3], b0, b1);
            }
        }
    }

    const int t0 = lane >> 2, t1 = t0 + 8;
    const int ncol = (lane & 3) * 2;
#pragma unroll
    for (int hh = 0; hh < 4; hh++) {
        float* sh = scores + (long)(h0 + hh) * T_NEW * TFULL;
#pragma unroll
        for (int j = 0; j < 4; j++) {
            int n = nbase + rw + j * 8 + ncol;
            float2 v0 = make_float2(c[hh][j][0] * scale + mask[t0 * TFULL + n],
                                    c[hh][j][1] * scale + mask[t0 * TFULL + n + 1]);
            float2 v1 = make_float2(c[hh][j][2] * scale + mask[t1 * TFULL + n],
                                    c[hh][j][3] * scale + mask[t1 * TFULL + n + 1]);
            *(float2*)(sh + (long)t0 * TFULL + n) = v0;
            *(float2*)(sh + (long)t1 * TFULL + n) = v1;
        }
    }
}

// =============================================================
// pvMMA: GQA-batched tf32 (unchanged from R12). Block 128 thr,
// m=64 (4 heads x 16 t), k-chunk 32 v-rows, split-K z, atomics.
// =============================================================
__global__ void __launch_bounds__(128)
pvMMA(const float* __restrict__ P,
      const float* __restrict__ vc, const float* __restrict__ vn,
      float* __restrict__ outA) {
    __shared__ uint32_t sv[32][VPAD];
    __shared__ uint32_t sa[64][APROW];

    const int tid = threadIdx.x;
    const int wid = tid >> 5;
    const int lane = tid & 31;
    const int kvh = blockIdx.y;
    const int h0 = kvh * 4;
    const int kbeg = blockIdx.z * 256;

    const int kq = lane & 3;
    const int rsel = lane >> 2;
    const int rw = wid * 32;

    float c[4][4][4];
#pragma unroll
    for (int hh = 0; hh < 4; hh++)
#pragma unroll
        for (int j = 0; j < 4; j++)
#pragma unroll
            for (int i = 0; i < 4; i++) c[hh][j][i] = 0.f;

    float4 wv[8], av[4];

#pragma unroll
    for (int i = 0; i < 8; i++) {
        int f = tid + i * 128;
        int vr = f >> 5, d0 = (f & 31) * 4;
        int rg = kbeg + vr;
        const float* src = (rg < TC)
            ? vc + ((long)kvh * TC + rg) * HD
            : vn + ((long)kvh * T_NEW + (rg - TC)) * HD;
        wv[i] = *(const float4*)(src + d0);
    }
#pragma unroll
    for (int i = 0; i < 4; i++) {
        int f = tid + i * 128;
        int row = f >> 3, cc = (f & 7) * 4;
        int hh = row >> 4, t = row & 15;
        av[i] = *(const float4*)(P + ((long)(h0 + hh) * T_NEW + t) * TFULL + kbeg + cc);
    }

#pragma unroll 1
    for (int ch = 0; ch < 8; ++ch) {
        __syncthreads();
#pragma unroll
        for (int i = 0; i < 8; i++) {
            int f = tid + i * 128;
            int vr = f >> 5, d0 = (f & 31) * 4;
            uint4 t = make_uint4(tf(wv[i].x), tf(wv[i].y), tf(wv[i].z), tf(wv[i].w));
            *(uint4*)&sv[vr][d0] = t;
        }
#pragma unroll
        for (int i = 0; i < 4; i++) {
            int f = tid + i * 128;
            int row = f >> 3, cc = (f & 7) * 4;
            uint4 t = make_uint4(tf(av[i].x), tf(av[i].y), tf(av[i].z), tf(av[i].w));
            *(uint4*)&sa[row][cc] = t;
        }
        __syncthreads();

        if (ch + 1 < 8) {
            const int kk0 = kbeg + (ch + 1) * 32;
#pragma unroll
            for (int i = 0; i < 8; i++) {
                int f = tid + i * 128;
                int vr = f >> 5, d0 = (f & 31) * 4;
                int rg = kk0 + vr;
                const float* src = (rg < TC)
                    ? vc + ((long)kvh * TC + rg) * HD
                    : vn + ((long)kvh * T_NEW + (rg - TC)) * HD;
                wv[i] = *(const float4*)(src + d0);
            }
#pragma unroll
            for (int i = 0; i < 4; i++) {
                int f = tid + i * 128;
                int row = f >> 3, cc = (f & 7) * 4;
                av[i] = *(const float4*)(P + ((long)(h0 + (row >> 4)) * T_NEW + (row & 15)) * TFULL + kk0 + cc);
            }
        }

#pragma unroll
        for (int s = 0; s < 4; s++) {
            const int s8 = s * 8;
            uint32_t a[4][4];
#pragma unroll
            for (int hh = 0; hh < 4; hh++) {
                a[hh][0] = sa[hh * 16 + rsel][s8 + kq];
                a[hh][1] = sa[hh * 16 + rsel + 8][s8 + kq];
                a[hh][2] = sa[hh * 16 + rsel][s8 + kq + 4];
                a[hh][3] = sa[hh * 16 + rsel + 8][s8 + kq + 4];
            }
#pragma unroll
            for (int j = 0; j < 4; j++) {
                uint32_t b0 = sv[s8 + kq][rw + j * 8 + rsel];
                uint32_t b1 = sv[s8 + kq + 4][rw + j * 8 + rsel];
#pragma unroll
                for (int hh = 0; hh < 4; hh++)
                    mmaTF32(c[hh][j], a[hh][0], a[hh][1], a[hh][2], a[hh][3], b0, b1);
            }
        }
    }

    const int t0 = lane >> 2, t1 = t0 + 8;
    const int ncol = (lane & 3) * 2;
#pragma unroll
    for (int hh = 0; hh < 4; hh++) {
        const long hb = (long)(h0 + hh) * HD;
#pragma unroll
        for (int j = 0; j < 4; j++) {
            int n = rw + j * 8 + ncol;
            float* o0 = outA + (long)t0 * (NH * HD) + hb + n;
            float* o1 = outA + (long)t1 * (NH * HD) + hb + n;
            atomicAdd(o0,     c[hh][j][0]);
            atomicAdd(o0 + 1, c[hh][j][1]);
            atomicAdd(o1,     c[hh][j][2]);
            atomicAdd(o1 + 1, c[hh][j][3]);
        }
    }
}

// ---------------- per-head rmsnorm + RoPE for q/k, and new_v copy ----------------
__global__ void qk_norm_rope(float* __restrict__ q, float* __restrict__ k,
                             const float* __restrict__ v,
                             const float* __restrict__ qw, const float* __restrict__ kw,
                             const float* __restrict__ cosr, const float* __restrict__ sinr,
                             float* __restrict__ outk, float* __restrict__ outv) {
    int t = blockIdx.x;
    int hh = blockIdx.y;
    int d = threadIdx.x;

    if (hh >= 40) {
        int h = hh - 40;
        outv[(size_t)(h * T_NEW + t) * HD + d] = v[(size_t)t * (NKV * HD) + h * HD + d];
        return;
    }

    __shared__ float sv[HD];
    __shared__ float red[4];
    float* row; const float* w;
    if (hh < 32) { row = q + (size_t)t * (NH * HD) + hh * HD; w = qw; }
    else         { row = k + (size_t)t * (NKV * HD) + (hh - 32) * HD; w = kw; }

    float val = row[d];
    float s = val * val;
    for (int o = 16; o > 0; o >>= 1) s += __shfl_xor_sync(0xffffffffu, s, o);
    if ((d & 31) == 0) red[d >> 5] = s;
    __syncthreads();
    float tot = red[0] + red[1] + red[2] + red[3];
    float r = rsqrtf(tot / 128.f + RMS_EPS);
    float xn = val * r * w[d];
    sv[d] = xn;
    __syncthreads();
    float rot = (d < 64) ? -sv[d + 64] : sv[d - 64];
    float o = xn * cosr[t * HD + d] + rot * sinr[t * HD + d];
    row[d] = o;
    if (hh >= 32) {
        int h = hh - 32;
        outk[(size_t)(h * T_NEW + t) * HD + d] = o;
    }
}

// ---------------- row softmax over TFULL ----------------
__global__ void softmax_rows(float* __restrict__ s) {
    int row = blockIdx.x;
    float* p = s + (size_t)row * TFULL;
    __shared__ float red[8];
    int tid = threadIdx.x;
    float m = -3.4e38f;
    for (int i = tid; i < TFULL; i += 256) m = fmaxf(m, p[i]);
    for (int o = 16; o > 0; o >>= 1) m = fmaxf(m, __shfl_xor_sync(0xffffffffu, m, o));
    if ((tid & 31) == 0) red[tid >> 5] = m;
    __syncthreads();
    float mm = red[0];
#pragma unroll
    for (int i = 1; i < 8; i++) mm = fmaxf(mm, red[i]);
    __syncthreads();
    float sum = 0.f;
    for (int i = tid; i < TFULL; i += 256) {
        float e = __expf(p[i] - mm);
        p[i] = e;
        sum += e;
    }
    for (int o = 16; o > 0; o >>= 1) sum += __shfl_xor_sync(0xffffffffu, sum, o);
    if ((tid & 31) == 0) red[tid >> 5] = sum;
    __syncthreads();
    float tot = 0.f;
#pragma unroll
    for (int i = 0; i < 8; i++) tot += red[i];
    float inv = 1.f / tot;
    for (int i = tid; i < TFULL; i += 256) p[i] *= inv;
}

static float* sym(const void* s) {
    void* p = nullptr;
    cudaGetSymbolAddress(&p, s);
    return (float*)p;
}

extern "C" void kernel_launch(void* const* d_in, const int* in_sizes, int n_in,
                              void* d_out, int out_size) {
    const float* x       = (const float*)d_in[0];
    const float* cos_q   = (const float*)d_in[1];
    const float* sin_q   = (const float*)d_in[2];
    const float* cache_k = (const float*)d_in[5];
    const float* cache_v = (const float*)d_in[6];
    const float* cmask   = (const float*)d_in[7];
    const float* ln1w    = (const float*)d_in[8];
    const float* ln2w    = (const float*)d_in[9];
    const float* qnw     = (const float*)d_in[10];
    const float* knw     = (const float*)d_in[11];
    const float* qw      = (const float*)d_in[12];
    const float* kw      = (const float*)d_in[13];
    const float* vw      = (const float*)d_in[14];
    const float* ow      = (const float*)d_in[15];
    const float* gw      = (const float*)d_in[16];
    const float* uw      = (const float*)d_in[17];
    const float* dw      = (const float*)d_in[18];
    float* out = (float*)d_out;
    float* out_k = out + T_NEW * HIDDEN;
    float* out_v = out_k + NKV * T_NEW * HD;

    static float *p_y = nullptr, *p_q, *p_k, *p_v, *p_scores, *p_attnout,
                 *p_h, *p_y2, *p_gate, *p_up;
    if (!p_y) {
        p_y = sym(g_y); p_q = sym(g_q); p_k = sym(g_k); p_v = sym(g_v);
        p_scores = sym(g_scores); p_attnout = sym(g_attnout);
        p_h = sym(g_h); p_y2 = sym(g_y2); p_gate = sym(g_gate); p_up = sym(g_up);
    }

    const float scale = 0.08838834764831845f; // 1/sqrt(128)
    const int BIG = 1 << 30;

    // 1) prep: rmsnorm1 (blocks 0-15) + zero atomic targets / seed h (rest)
    prep<<<16 + (T_NEW * INTER + 255) / 256, 256>>>(x, ln1w);

    // 2) fused QKV projection: q [0,4096), k [4096,5120), v [5120,6144)
    mmaProj<<<dim3(24, 1, 16), 256>>>(p_y, nullptr,
        qw, kw, vw, p_q, p_k, p_v,
        NH * HD, NKV * HD, NKV * HD,
        4096, 5120, HIDDEN, 160);

    // 3) per-head q/k rmsnorm + RoPE; writes new_k/new_v into d_out
    qk_norm_rope<<<dim3(T_NEW, 48), 128>>>(p_q, p_k, p_v, qnw, knw, cos_q, sin_q,
                                           out_k, out_v);

    // 4) scores (GQA-batched fp16 mma, fused scale+mask)
    scoresMMA<<<dim3(16, NKV), 256>>>(p_q, cache_k, out_k, cmask, p_scores, scale);

    // 5) softmax
    softmax_rows<<<NH * T_NEW, 256>>>(p_scores);

    // 6) attn_out = P @ V (GQA-batched tf32, split-K z=16, atomic)
    pvMMA<<<dim3(1, NKV, 16), 128>>>(p_scores, cache_v, out_v, p_attnout);

    // 7) O projection accumulates into h (pre-seeded with x)
    mmaProj<<<dim3(10, 1, 32), 256>>>(p_attnout, nullptr,
        ow, ow, ow, p_h, p_h, p_h,
        HIDDEN, HIDDEN, HIDDEN,
        BIG, BIG, NH * HD, 128);

    // 8) y2 = rmsnorm(h) * ln2; also copy h -> out (residual seed for down-proj)
    rmsnorm16<<<T_NEW, 256>>>(p_h, ln2w, p_y2, out, HIDDEN);

    // 9) fused gate/up: gate [0,9728), up [9728,19456)
    mmaProj<<<dim3(76, 1, 8), 256>>>(p_y2, nullptr,
        gw, uw, uw, p_gate, p_up, p_up,
        INTER, INTER, INTER,
        INTER, BIG, HIDDEN, 320);

    // 10) down projection with fused silu(gate)*up activation, accumulates into out
    mmaProj<<<dim3(10, 1, 38), 256>>>(p_gate, p_up,
        dw, dw, dw, out, out, out,
        HIDDEN, HIDDEN, HIDDEN,
        BIG, BIG, INTER, 256);
}